// round 7
// baseline (speedup 1.0000x reference)
#include <cuda_runtime.h>
#include <cuda_bf16.h>
#include <cstdint>
#include <cstddef>

// Problem constants
#define C_IN   256
#define C_OUT  256
#define KPTS   15
#define NNB    16
#define HH     64
#define WW     2048
#define KP_EXT 1.2f
#define BN_EPS 1e-5f
#define MAXB   8
#define MAXN   40000
#define KD     (KPTS * C_IN)        // 3840

// ---------------- scratch (device globals) ----------------
__device__ int   g_cum[MAXB + 1];
__device__ float g_feats[(size_t)MAXN * C_IN];
__device__ float g_allw[(size_t)MAXN * NNB * KPTS];
__device__ __nv_bfloat16 g_Ahi[(size_t)MAXN * KD];     // 307 MB
__device__ __nv_bfloat16 g_Alo[(size_t)MAXN * KD];     // 307 MB
__device__ __nv_bfloat16 g_Bhi[(size_t)C_OUT * KD];    // 1.9 MB, K-major [d][kc]
__device__ __nv_bfloat16 g_Blo[(size_t)C_OUT * KD];
__device__ float g_psum[256 * C_OUT];
__device__ float g_psq[256 * C_OUT];
__device__ float g_scale[C_OUT];
__device__ float g_bias[C_OUT];

// ---------------- PTX helpers (base sm_103-legal only) ----------------
__device__ __forceinline__ uint32_t smem_u32(const void* p) {
    uint32_t a;
    asm("{ .reg .u64 t; cvta.to.shared.u64 t, %1; cvt.u32.u64 %0, t; }" : "=r"(a) : "l"(p));
    return a;
}

#define CP_ASYNC16(dst_u32, src_ptr) \
    asm volatile("cp.async.cg.shared.global [%0], [%1], 16;" \
                 :: "r"(dst_u32), "l"(src_ptr) : "memory")
#define CP_COMMIT() asm volatile("cp.async.commit_group;" ::: "memory")
#define CP_WAIT2()  asm volatile("cp.async.wait_group 2;" ::: "memory")
#define CP_WAIT1()  asm volatile("cp.async.wait_group 1;" ::: "memory")
#define CP_WAIT0()  asm volatile("cp.async.wait_group 0;" ::: "memory")

__device__ __forceinline__ void ldsm4(uint32_t* r, uint32_t addr) {
    asm volatile("ldmatrix.sync.aligned.m8n8.x4.shared.b16 {%0,%1,%2,%3}, [%4];"
                 : "=r"(r[0]), "=r"(r[1]), "=r"(r[2]), "=r"(r[3]) : "r"(addr));
}

__device__ __forceinline__ void mma16816(float* c, const uint32_t* a,
                                         uint32_t b0, uint32_t b1) {
    asm volatile(
        "mma.sync.aligned.m16n8k16.row.col.f32.bf16.bf16.f32 "
        "{%0,%1,%2,%3}, {%4,%5,%6,%7}, {%8,%9}, {%0,%1,%2,%3};"
        : "+f"(c[0]), "+f"(c[1]), "+f"(c[2]), "+f"(c[3])
        : "r"(a[0]), "r"(a[1]), "r"(a[2]), "r"(a[3]), "r"(b0), "r"(b1));
}

__device__ __forceinline__ int batch_of(int n, int Bn) {
    int b = 0;
#pragma unroll
    for (int i = 1; i < MAXB; i++)
        if (i < Bn && n >= g_cum[i]) b = i;
    return b;
}

// ---------------- launch 1: fused prefix sums + B hi/lo transpose ----------------
__global__ void prep_all_kernel(const int* __restrict__ np, int Bn,
                                const float* __restrict__ kpw) {
    if (blockIdx.x == 0 && threadIdx.x == 0) {
        int c = 0;
        for (int b = 0; b < Bn && b < MAXB; b++) { g_cum[b] = c; c += np[b]; }
        for (int b = Bn; b < MAXB; b++) g_cum[b] = c;
        g_cum[MAXB] = c;
    }
    int i = blockIdx.x * blockDim.x + threadIdx.x;
    if (i >= KD * C_OUT) return;
    int kc = i >> 8;
    int d  = i & 255;
    float v = kpw[i];
    __nv_bfloat16 h = __float2bfloat16(v);
    float rem = v - __bfloat162float(h);
    g_Bhi[(size_t)d * KD + kc] = h;
    g_Blo[(size_t)d * KD + kc] = __float2bfloat16(rem);
}

// ---------------- launch 2: fused grid sample + kernel-point weights ----------------
// blocks [0, N): feats for point bid (256 threads = channels)
// blocks [N, N + ceil(N*NNB/256)): allw, one thread per (point, neighbor)
__global__ void feats_allw_kernel(const float* __restrict__ x,
                                  const float* __restrict__ px,
                                  const float* __restrict__ py,
                                  const float* __restrict__ pxyz,
                                  const int* __restrict__ pknn,
                                  const float* __restrict__ kp,
                                  int N, int Bn) {
    __shared__ float skp[KPTS * 3];
    int bid = blockIdx.x;
    if (bid < N) {
        int n = bid;
        int c = threadIdx.x;
        int b = batch_of(n, Bn);

        float ix = fminf(fmaxf((px[n] + 1.0f) * (WW * 0.5f) - 0.5f, 0.0f), (float)(WW - 1));
        float iy = fminf(fmaxf((py[n] + 1.0f) * (HH * 0.5f) - 0.5f, 0.0f), (float)(HH - 1));
        float x0f = floorf(ix), y0f = floorf(iy);
        float wx = ix - x0f, wy = iy - y0f;
        int x0 = (int)x0f, y0 = (int)y0f;
        int x1 = min(x0 + 1, WW - 1);
        int y1 = min(y0 + 1, HH - 1);

        const float* base = x + ((size_t)b * C_IN + c) * (size_t)(HH * WW);
        float v00 = base[(size_t)y0 * WW + x0];
        float v01 = base[(size_t)y0 * WW + x1];
        float v10 = base[(size_t)y1 * WW + x0];
        float v11 = base[(size_t)y1 * WW + x1];

        float top = v00 + (v01 - v00) * wx;
        float bot = v10 + (v11 - v10) * wx;
        g_feats[(size_t)n * C_IN + c] = top + (bot - top) * wy;
    } else {
        if (threadIdx.x < KPTS * 3) skp[threadIdx.x] = kp[threadIdx.x];
        __syncthreads();

        int t = (bid - N) * 256 + threadIdx.x;
        int n = t / NNB;
        int a = t % NNB;
        if (n >= N) return;
        int b = batch_of(n, Bn);
        int j = pknn[(size_t)n * NNB + a] + g_cum[b];

        float cx = pxyz[(size_t)n * 3 + 0];
        float cy = pxyz[(size_t)n * 3 + 1];
        float cz = pxyz[(size_t)n * 3 + 2];
        float rx = pxyz[(size_t)j * 3 + 0] - cx;
        float ry = pxyz[(size_t)j * 3 + 1] - cy;
        float rz = pxyz[(size_t)j * 3 + 2] - cz;

#pragma unroll
        for (int k = 0; k < KPTS; k++) {
            float dx = rx - skp[k * 3 + 0];
            float dy = ry - skp[k * 3 + 1];
            float dz = rz - skp[k * 3 + 2];
            float dist = sqrtf(dx * dx + dy * dy + dz * dz);
            g_allw[((size_t)n * NNB + a) * KPTS + k] = fmaxf(1.0f - dist * (1.0f / KP_EXT), 0.0f);
        }
    }
}

// ---------------- launch 3: weighted -> bf16 hi/lo split (vectorized) ----------------
// 2 points per block; 128 threads per point; each thread owns channels (2c, 2c+1)
__global__ void __launch_bounds__(256, 4)
weighted_kernel(const int* __restrict__ pknn, int N, int Bn) {
    int half = threadIdx.x >> 7;          // 0 or 1
    int c2   = threadIdx.x & 127;         // channel pair index
    int n = blockIdx.x * 2 + half;
    n = min(n, N - 1);                    // duplicate work if N odd (benign)

    __shared__ float sw[2][NNB * KPTS];
    __shared__ int sidx[2][NNB];

    if (c2 < NNB) {
        int b = batch_of(n, Bn);
        sidx[half][c2] = pknn[(size_t)n * NNB + c2] + g_cum[b];
    }
    for (int i = c2; i < NNB * KPTS; i += 128)
        sw[half][i] = g_allw[(size_t)n * NNB * KPTS + i];
    __syncthreads();

    float2 nx[NNB];
#pragma unroll
    for (int a = 0; a < NNB; a++)
        nx[a] = *(const float2*)(g_feats + (size_t)sidx[half][a] * C_IN + 2 * c2);

    __nv_bfloat162* Ahi2 = (__nv_bfloat162*)g_Ahi;
    __nv_bfloat162* Alo2 = (__nv_bfloat162*)g_Alo;
    size_t rowbase = ((size_t)n * KD) >> 1;

#pragma unroll
    for (int k = 0; k < KPTS; k++) {
        float acc0 = 0.0f, acc1 = 0.0f;
#pragma unroll
        for (int a = 0; a < NNB; a++) {
            float w = sw[half][a * KPTS + k];
            acc0 = fmaf(w, nx[a].x, acc0);
            acc1 = fmaf(w, nx[a].y, acc1);
        }
        __nv_bfloat16 h0 = __float2bfloat16(acc0);
        __nv_bfloat16 h1 = __float2bfloat16(acc1);
        float r0 = acc0 - __bfloat162float(h0);
        float r1 = acc1 - __bfloat162float(h1);
        size_t idx = rowbase + (size_t)k * 128 + c2;
        Ahi2[idx] = __nv_bfloat162(h0, h1);
        Alo2[idx] = __nv_bfloat162(__float2bfloat16(r0), __float2bfloat16(r1));
    }
}

// ---------------- launch 4: HMMA bf16 3-pass GEMM (3-stage cp.async pipeline) ----------------
// C[m, d] = sum_kc A[m,kc] * B[d,kc]
// CTA: 128(M) x 128(N), 8 warps = 2(M) x 4(N), warp tile 64 x 32
#define GM 128
#define GN 128
#define KCHUNK 64
#define NCHUNKS (KD / KCHUNK)           // 60
#define ARR_BYTES 16384                 // one 128x64 bf16 array
#define OFF_AH 0
#define OFF_AL 16384
#define OFF_BH 32768
#define OFF_BL 49152
#define STAGE_BYTES 65536
#define NSTAGE 3
#define GEMM_SMEM (NSTAGE * STAGE_BYTES + 1024)

extern __shared__ char gemm_smem[];

__device__ __forceinline__ void issue_chunk(uint32_t stage_u32, int mBase, int nBase,
                                            int k0, int M, int tid) {
    int r_lo = tid >> 3;        // 0..31
    int i    = tid & 7;         // 16B granule within 128B row
    const __nv_bfloat16* __restrict__ Ah = g_Ahi;
    const __nv_bfloat16* __restrict__ Al = g_Alo;
    const __nv_bfloat16* __restrict__ Bh = g_Bhi;
    const __nv_bfloat16* __restrict__ Bl = g_Blo;
#pragma unroll
    for (int p = 0; p < 16; p++) {
        int quarter = p >> 2;                   // 0:Ah 1:Al 2:Bh 3:Bl
        int row = ((p & 3) * 32 + r_lo) & 127;  // 0..127
        uint32_t off = (uint32_t)(row * 128 + i * 16);
        uint32_t sw = off ^ ((off >> 3) & 0x70);
        uint32_t dst = stage_u32 + quarter * ARR_BYTES + sw;
        const __nv_bfloat16* src;
        if (quarter == 0) {
            int gr = min(mBase + row, M - 1);
            src = Ah + (size_t)gr * KD + k0 + i * 8;
        } else if (quarter == 1) {
            int gr = min(mBase + row, M - 1);
            src = Al + (size_t)gr * KD + k0 + i * 8;
        } else if (quarter == 2) {
            src = Bh + (size_t)(nBase + row) * KD + k0 + i * 8;
        } else {
            src = Bl + (size_t)(nBase + row) * KD + k0 + i * 8;
        }
        CP_ASYNC16(dst, src);
    }
}

__global__ void __launch_bounds__(256, 1) gemm_mma_kernel(float* __restrict__ C, int M) {
    int tid = threadIdx.x;
    int wid = tid >> 5;
    int lane = tid & 31;
    int wm = wid & 1;          // 0..1  (64 rows each)
    int wn = wid >> 1;         // 0..3  (32 cols each)
    int mBase = blockIdx.y * GM;
    int nBase = blockIdx.x * GN;

    uint32_t dyn_u32 = smem_u32(gemm_smem);
    uint32_t base_u32 = (dyn_u32 + 1023u) & ~1023u;

    float acc[4][4][4];
#pragma unroll
    for (int a = 0; a < 4; a++)
#pragma unroll
        for (int b = 0; b < 4; b++)
#pragma unroll
            for (int c = 0; c < 4; c++) acc[a][b][c] = 0.0f;

    // per-lane ldmatrix address components
    int lrow = lane & 15;                 // row within 16-row group
    int csel = (lane >> 4) * 16;          // 16B column half (k0-7 / k8-15)
    int aRow = wm * 64 + lrow;            // A row for mt=0
    int bRow = wn * 32 + lrow;            // B row for 16-n group 0
    uint32_t xa = (uint32_t)((aRow & 7) << 4);
    uint32_t xb = (uint32_t)((bRow & 7) << 4);

    // prologue: fill 2 of 3 stages
    issue_chunk(base_u32 + 0 * STAGE_BYTES, mBase, nBase, 0, M, tid);
    CP_COMMIT();
    issue_chunk(base_u32 + 1 * STAGE_BYTES, mBase, nBase, KCHUNK, M, tid);
    CP_COMMIT();

    int bufsel = 0;
    for (int ch = 0; ch < NCHUNKS; ch++) {
        uint32_t stg = base_u32 + bufsel * STAGE_BYTES;

        if (ch + 2 < NCHUNKS) {
            int nbuf = bufsel + 2; if (nbuf >= NSTAGE) nbuf -= NSTAGE;
            issue_chunk(base_u32 + nbuf * STAGE_BYTES,
                        mBase, nBase, (ch + 2) * KCHUNK, M, tid);
            CP_COMMIT();
            CP_WAIT2();
        } else if (ch + 1 < NCHUNKS) {
            CP_WAIT1();
        } else {
            CP_WAIT0();
        }
        __syncthreads();

        uint32_t aBase = stg + (uint32_t)(aRow * 128);
        uint32_t bBase = stg + (uint32_t)(bRow * 128);

#pragma unroll
        for (int ks = 0; ks < 4; ks++) {
            uint32_t colA = ((uint32_t)(ks * 32 + csel)) ^ xa;
            uint32_t colB = ((uint32_t)(ks * 32 + csel)) ^ xb;

            // load B once per ks (keeps live registers low)
            uint32_t bh[2][4], bl[2][4];
#pragma unroll
            for (int g = 0; g < 2; g++) {
                uint32_t addr = bBase + (uint32_t)(g * 16 * 128) + colB;
                ldsm4(bh[g], addr + OFF_BH);
                ldsm4(bl[g], addr + OFF_BL);
            }
            // stream A tiles through a small register window
#pragma unroll
            for (int mt = 0; mt < 4; mt++) {
                uint32_t addr = aBase + (uint32_t)(mt * 16 * 128) + colA;
                uint32_t ah[4], al[4];
                ldsm4(ah, addr + OFF_AH);
                ldsm4(al, addr + OFF_AL);
#pragma unroll
                for (int nt = 0; nt < 4; nt++) {
                    int g = nt >> 1, h = nt & 1;
                    mma16816(acc[mt][nt], ah, bh[g][h], bh[g][h + 2]);
                    mma16816(acc[mt][nt], ah, bl[g][h], bl[g][h + 2]);
                    mma16816(acc[mt][nt], al, bh[g][h], bh[g][h + 2]);
                }
            }
        }
        __syncthreads();

        bufsel++; if (bufsel >= NSTAGE) bufsel = 0;
    }

    // epilogue: standard m16n8 accumulator mapping
    int rBase = mBase + wm * 64 + (lane >> 2);
    int cBase = nBase + wn * 32 + (lane & 3) * 2;
#pragma unroll
    for (int mt = 0; mt < 4; mt++) {
#pragma unroll
        for (int nt = 0; nt < 4; nt++) {
            int r0 = rBase + mt * 16;
            int cc = cBase + nt * 8;
            if (r0 < M)
                *(float2*)(C + (size_t)r0 * C_OUT + cc) =
                    make_float2(acc[mt][nt][0], acc[mt][nt][1]);
            if (r0 + 8 < M)
                *(float2*)(C + (size_t)(r0 + 8) * C_OUT + cc) =
                    make_float2(acc[mt][nt][2], acc[mt][nt][3]);
        }
    }
}

// ---------------- launch 5/6: BN stats (deterministic two-pass) ----------------
__global__ void colstats_partial(const float* __restrict__ out0, int N) {
    int d = threadIdx.x;
    int blk = blockIdx.x;
    float s = 0.f, ss = 0.f;
    for (int r = blk; r < N; r += gridDim.x) {
        float v = out0[(size_t)r * C_OUT + d];
        s += v;
        ss += v * v;
    }
    g_psum[blk * C_OUT + d] = s;
    g_psq[blk * C_OUT + d]  = ss;
}

__global__ void colstats_final(const float* __restrict__ gamma,
                               const float* __restrict__ beta,
                               int N, int nchunks) {
    int d = threadIdx.x;
    float s = 0.f, ss = 0.f;
    for (int i = 0; i < nchunks; i++) {
        s += g_psum[i * C_OUT + d];
        ss += g_psq[i * C_OUT + d];
    }
    float invN = 1.0f / (float)N;
    float mean = s * invN;
    float var = ss * invN - mean * mean;
    float sc = rsqrtf(var + BN_EPS) * gamma[d];
    g_scale[d] = sc;
    g_bias[d] = beta[d] - mean * sc;
}

// ---------------- launch 7: BN + ReLU ----------------
__global__ void bn_relu_kernel(float* __restrict__ out, size_t total) {
    for (size_t i = (size_t)blockIdx.x * blockDim.x + threadIdx.x; i < total;
         i += (size_t)gridDim.x * blockDim.x) {
        int d = (int)(i & (C_OUT - 1));
        float v = fmaf(out[i], g_scale[d], g_bias[d]);
        out[i] = v > 0.0f ? v : 0.0f;
    }
}

// ---------------- launch ----------------
extern "C" void kernel_launch(void* const* d_in, const int* in_sizes, int n_in,
                              void* d_out, int out_size) {
    const float* x     = (const float*)d_in[0];
    const float* px    = (const float*)d_in[1];
    const float* py    = (const float*)d_in[2];
    const float* pxyz  = (const float*)d_in[3];
    const int*   pknn  = (const int*)d_in[4];
    const int*   np    = (const int*)d_in[5];
    const float* kp    = (const float*)d_in[6];
    const float* kpw   = (const float*)d_in[7];
    const float* gamma = (const float*)d_in[8];
    const float* beta  = (const float*)d_in[9];
    float* out = (float*)d_out;

    int N  = in_sizes[1];
    int Bn = in_sizes[5];

    cudaFuncSetAttribute(gemm_mma_kernel,
                         cudaFuncAttributeMaxDynamicSharedMemorySize, GEMM_SMEM);

    // launch 1: prefix sums + B transpose
    prep_all_kernel<<<(KD * C_OUT + 255) / 256, 256>>>(np, Bn, kpw);

    // launch 2: fused feats + allw
    int allw_blocks = (N * NNB + 255) / 256;
    feats_allw_kernel<<<N + allw_blocks, 256>>>(x, px, py, pxyz, pknn, kp, N, Bn);

    // launch 3: weighted (2 points per block)
    weighted_kernel<<<(N + 1) / 2, 256>>>(pknn, N, Bn);

    // launch 4: GEMM (profiled slot)
    dim3 ggrid(C_OUT / GN, (N + GM - 1) / GM);
    gemm_mma_kernel<<<ggrid, 256, GEMM_SMEM>>>(out, N);

    colstats_partial<<<256, C_OUT>>>(out, N);
    colstats_final<<<1, C_OUT>>>(gamma, beta, N, 256);

    size_t total = (size_t)N * C_OUT;
    bn_relu_kernel<<<2048, 256>>>(out, total);
}

// round 8
// speedup vs baseline: 1.1689x; 1.1689x over previous
#include <cuda_runtime.h>
#include <cuda_bf16.h>
#include <cstdint>
#include <cstddef>

// Problem constants
#define C_IN   256
#define C_OUT  256
#define KPTS   15
#define NNB    16
#define HH     64
#define WW     2048
#define KP_EXT 1.2f
#define BN_EPS 1e-5f
#define MAXB   8
#define MAXN   40000
#define KD     (KPTS * C_IN)        // 3840

// ---------------- scratch (device globals) ----------------
__device__ int   g_cum[MAXB + 1];
__device__ float g_feats[(size_t)MAXN * C_IN];
__device__ float g_allw[(size_t)MAXN * NNB * KPTS];
__device__ __nv_bfloat16 g_Ahi[(size_t)MAXN * KD];     // 307 MB
__device__ __nv_bfloat16 g_Alo[(size_t)MAXN * KD];     // 307 MB
__device__ __nv_bfloat16 g_Bhi[(size_t)C_OUT * KD];    // 1.9 MB, K-major [d][kc]
__device__ __nv_bfloat16 g_Blo[(size_t)C_OUT * KD];
__device__ float g_psum[256 * C_OUT];
__device__ float g_psq[256 * C_OUT];
__device__ float g_scale[C_OUT];
__device__ float g_bias[C_OUT];

// ---------------- PTX helpers (base sm_103-legal only) ----------------
__device__ __forceinline__ uint32_t smem_u32(const void* p) {
    uint32_t a;
    asm("{ .reg .u64 t; cvta.to.shared.u64 t, %1; cvt.u32.u64 %0, t; }" : "=r"(a) : "l"(p));
    return a;
}

#define CP_ASYNC16(dst_u32, src_ptr) \
    asm volatile("cp.async.cg.shared.global [%0], [%1], 16;" \
                 :: "r"(dst_u32), "l"(src_ptr) : "memory")
#define CP_COMMIT() asm volatile("cp.async.commit_group;" ::: "memory")
#define CP_WAIT2()  asm volatile("cp.async.wait_group 2;" ::: "memory")
#define CP_WAIT1()  asm volatile("cp.async.wait_group 1;" ::: "memory")
#define CP_WAIT0()  asm volatile("cp.async.wait_group 0;" ::: "memory")

__device__ __forceinline__ void ldsm4(uint32_t* r, uint32_t addr) {
    asm volatile("ldmatrix.sync.aligned.m8n8.x4.shared.b16 {%0,%1,%2,%3}, [%4];"
                 : "=r"(r[0]), "=r"(r[1]), "=r"(r[2]), "=r"(r[3]) : "r"(addr));
}

__device__ __forceinline__ void mma16816(float* c, const uint32_t* a,
                                         uint32_t b0, uint32_t b1) {
    asm volatile(
        "mma.sync.aligned.m16n8k16.row.col.f32.bf16.bf16.f32 "
        "{%0,%1,%2,%3}, {%4,%5,%6,%7}, {%8,%9}, {%0,%1,%2,%3};"
        : "+f"(c[0]), "+f"(c[1]), "+f"(c[2]), "+f"(c[3])
        : "r"(a[0]), "r"(a[1]), "r"(a[2]), "r"(a[3]), "r"(b0), "r"(b1));
}

__device__ __forceinline__ int batch_of(int n, int Bn) {
    int b = 0;
#pragma unroll
    for (int i = 1; i < MAXB; i++)
        if (i < Bn && n >= g_cum[i]) b = i;
    return b;
}

// ---------------- launch 1: fused prefix sums + B hi/lo transpose ----------------
__global__ void prep_all_kernel(const int* __restrict__ np, int Bn,
                                const float* __restrict__ kpw) {
    if (blockIdx.x == 0 && threadIdx.x == 0) {
        int c = 0;
        for (int b = 0; b < Bn && b < MAXB; b++) { g_cum[b] = c; c += np[b]; }
        for (int b = Bn; b < MAXB; b++) g_cum[b] = c;
        g_cum[MAXB] = c;
    }
    int i = blockIdx.x * blockDim.x + threadIdx.x;
    if (i >= KD * C_OUT) return;
    int kc = i >> 8;
    int d  = i & 255;
    float v = kpw[i];
    __nv_bfloat16 h = __float2bfloat16(v);
    float rem = v - __bfloat162float(h);
    g_Bhi[(size_t)d * KD + kc] = h;
    g_Blo[(size_t)d * KD + kc] = __float2bfloat16(rem);
}

// ---------------- launch 2: fused grid sample + kernel-point weights ----------------
__global__ void feats_allw_kernel(const float* __restrict__ x,
                                  const float* __restrict__ px,
                                  const float* __restrict__ py,
                                  const float* __restrict__ pxyz,
                                  const int* __restrict__ pknn,
                                  const float* __restrict__ kp,
                                  int N, int Bn) {
    __shared__ float skp[KPTS * 3];
    int bid = blockIdx.x;
    if (bid < N) {
        int n = bid;
        int c = threadIdx.x;
        int b = batch_of(n, Bn);

        float ix = fminf(fmaxf((px[n] + 1.0f) * (WW * 0.5f) - 0.5f, 0.0f), (float)(WW - 1));
        float iy = fminf(fmaxf((py[n] + 1.0f) * (HH * 0.5f) - 0.5f, 0.0f), (float)(HH - 1));
        float x0f = floorf(ix), y0f = floorf(iy);
        float wx = ix - x0f, wy = iy - y0f;
        int x0 = (int)x0f, y0 = (int)y0f;
        int x1 = min(x0 + 1, WW - 1);
        int y1 = min(y0 + 1, HH - 1);

        const float* base = x + ((size_t)b * C_IN + c) * (size_t)(HH * WW);
        float v00 = base[(size_t)y0 * WW + x0];
        float v01 = base[(size_t)y0 * WW + x1];
        float v10 = base[(size_t)y1 * WW + x0];
        float v11 = base[(size_t)y1 * WW + x1];

        float top = v00 + (v01 - v00) * wx;
        float bot = v10 + (v11 - v10) * wx;
        g_feats[(size_t)n * C_IN + c] = top + (bot - top) * wy;
    } else {
        if (threadIdx.x < KPTS * 3) skp[threadIdx.x] = kp[threadIdx.x];
        __syncthreads();

        int t = (bid - N) * 256 + threadIdx.x;
        int n = t / NNB;
        int a = t % NNB;
        if (n >= N) return;
        int b = batch_of(n, Bn);
        int j = pknn[(size_t)n * NNB + a] + g_cum[b];

        float cx = pxyz[(size_t)n * 3 + 0];
        float cy = pxyz[(size_t)n * 3 + 1];
        float cz = pxyz[(size_t)n * 3 + 2];
        float rx = pxyz[(size_t)j * 3 + 0] - cx;
        float ry = pxyz[(size_t)j * 3 + 1] - cy;
        float rz = pxyz[(size_t)j * 3 + 2] - cz;

#pragma unroll
        for (int k = 0; k < KPTS; k++) {
            float dx = rx - skp[k * 3 + 0];
            float dy = ry - skp[k * 3 + 1];
            float dz = rz - skp[k * 3 + 2];
            float dist = sqrtf(dx * dx + dy * dy + dz * dz);
            g_allw[((size_t)n * NNB + a) * KPTS + k] = fmaxf(1.0f - dist * (1.0f / KP_EXT), 0.0f);
        }
    }
}

// ---------------- launch 3: weighted -> bf16 hi/lo split (R6-proven version) ----------------
__global__ void __launch_bounds__(256, 3)
weighted_kernel(const int* __restrict__ pknn, int N, int Bn) {
    int n = blockIdx.x;
    int c = threadIdx.x;
    if (n >= N) return;

    __shared__ float sw[NNB * KPTS];
    __shared__ int sidx[NNB];
    if (c < NNB) {
        int b = batch_of(n, Bn);
        sidx[c] = pknn[(size_t)n * NNB + c] + g_cum[b];
    }
    if (c < NNB * KPTS) sw[c] = g_allw[(size_t)n * NNB * KPTS + c];
    __syncthreads();

    float nx[NNB];
#pragma unroll
    for (int a = 0; a < NNB; a++)
        nx[a] = g_feats[(size_t)sidx[a] * C_IN + c];

#pragma unroll
    for (int k = 0; k < KPTS; k++) {
        float acc = 0.0f;
#pragma unroll
        for (int a = 0; a < NNB; a++)
            acc = fmaf(sw[a * KPTS + k], nx[a], acc);
        __nv_bfloat16 h = __float2bfloat16(acc);
        float rem = acc - __bfloat162float(h);
        size_t idx = (size_t)n * KD + k * C_IN + c;
        g_Ahi[idx] = h;
        g_Alo[idx] = __float2bfloat16(rem);
    }
}

// ---------------- launch 4: HMMA bf16 3-pass GEMM, 16 warps, 3-stage pipeline ----------------
// C[m, d] = sum_kc A[m,kc] * B[d,kc]
// CTA: 128(M) x 128(N), 512 threads = 16 warps = 4(M) x 4(N), warp tile 32 x 32
#define GM 128
#define GN 128
#define KCHUNK 64
#define NCHUNKS (KD / KCHUNK)           // 60
#define ARR_BYTES 16384                 // one 128x64 bf16 array
#define OFF_AH 0
#define OFF_AL 16384
#define OFF_BH 32768
#define OFF_BL 49152
#define STAGE_BYTES 65536
#define NSTAGE 3
#define GEMM_SMEM (NSTAGE * STAGE_BYTES + 1024)
#define GEMM_THREADS 512

extern __shared__ char gemm_smem[];

__device__ __forceinline__ void issue_chunk(uint32_t stage_u32, int mBase, int nBase,
                                            int k0, int M, int tid) {
    int r_lo = tid >> 3;        // 0..63
    int i    = tid & 7;         // 16B granule within 128B row
    const __nv_bfloat16* __restrict__ Ah = g_Ahi;
    const __nv_bfloat16* __restrict__ Al = g_Alo;
    const __nv_bfloat16* __restrict__ Bh = g_Bhi;
    const __nv_bfloat16* __restrict__ Bl = g_Blo;
#pragma unroll
    for (int p = 0; p < 8; p++) {
        int quarter = p >> 1;                   // 0:Ah 1:Al 2:Bh 3:Bl
        int row = (p & 1) * 64 + r_lo;          // 0..127
        uint32_t off = (uint32_t)(row * 128 + i * 16);
        uint32_t sw = off ^ ((off >> 3) & 0x70);
        uint32_t dst = stage_u32 + quarter * ARR_BYTES + sw;
        const __nv_bfloat16* src;
        if (quarter == 0) {
            int gr = min(mBase + row, M - 1);
            src = Ah + (size_t)gr * KD + k0 + i * 8;
        } else if (quarter == 1) {
            int gr = min(mBase + row, M - 1);
            src = Al + (size_t)gr * KD + k0 + i * 8;
        } else if (quarter == 2) {
            src = Bh + (size_t)(nBase + row) * KD + k0 + i * 8;
        } else {
            src = Bl + (size_t)(nBase + row) * KD + k0 + i * 8;
        }
        CP_ASYNC16(dst, src);
    }
}

__global__ void __launch_bounds__(GEMM_THREADS, 1) gemm_mma_kernel(float* __restrict__ C, int M) {
    int tid = threadIdx.x;
    int wid = tid >> 5;
    int lane = tid & 31;
    int wm = wid & 3;          // 0..3  (32 rows each)
    int wn = wid >> 2;         // 0..3  (32 cols each)
    int mBase = blockIdx.y * GM;
    int nBase = blockIdx.x * GN;

    uint32_t dyn_u32 = smem_u32(gemm_smem);
    uint32_t base_u32 = (dyn_u32 + 1023u) & ~1023u;

    float acc[2][4][4];
#pragma unroll
    for (int a = 0; a < 2; a++)
#pragma unroll
        for (int b = 0; b < 4; b++)
#pragma unroll
            for (int c = 0; c < 4; c++) acc[a][b][c] = 0.0f;

    // per-lane ldmatrix address components
    int lrow = lane & 15;                 // row within 16-row group
    int csel = (lane >> 4) * 16;          // 16B column half (k0-7 / k8-15)
    int aRow = wm * 32 + lrow;            // A row for mt=0
    int bRow = wn * 32 + lrow;            // B row for 16-n group 0
    uint32_t xa = (uint32_t)((aRow & 7) << 4);
    uint32_t xb = (uint32_t)((bRow & 7) << 4);

    // prologue: fill 2 of 3 stages
    issue_chunk(base_u32 + 0 * STAGE_BYTES, mBase, nBase, 0, M, tid);
    CP_COMMIT();
    issue_chunk(base_u32 + 1 * STAGE_BYTES, mBase, nBase, KCHUNK, M, tid);
    CP_COMMIT();

    int bufsel = 0;
    for (int ch = 0; ch < NCHUNKS; ch++) {
        uint32_t stg = base_u32 + bufsel * STAGE_BYTES;

        if (ch + 2 < NCHUNKS) {
            int nbuf = bufsel + 2; if (nbuf >= NSTAGE) nbuf -= NSTAGE;
            issue_chunk(base_u32 + nbuf * STAGE_BYTES,
                        mBase, nBase, (ch + 2) * KCHUNK, M, tid);
            CP_COMMIT();
            CP_WAIT2();
        } else if (ch + 1 < NCHUNKS) {
            CP_WAIT1();
        } else {
            CP_WAIT0();
        }
        __syncthreads();

        uint32_t aBase = stg + (uint32_t)(aRow * 128);
        uint32_t bBase = stg + (uint32_t)(bRow * 128);

#pragma unroll
        for (int ks = 0; ks < 4; ks++) {
            uint32_t colA = ((uint32_t)(ks * 32 + csel)) ^ xa;
            uint32_t colB = ((uint32_t)(ks * 32 + csel)) ^ xb;

            // B tiles for this warp's 32 columns (2 x 16-col groups)
            uint32_t bh[2][4], bl[2][4];
#pragma unroll
            for (int g = 0; g < 2; g++) {
                uint32_t addr = bBase + (uint32_t)(g * 16 * 128) + colB;
                ldsm4(bh[g], addr + OFF_BH);
                ldsm4(bl[g], addr + OFF_BL);
            }
            // A tiles: 2 x 16-row groups, streamed
#pragma unroll
            for (int mt = 0; mt < 2; mt++) {
                uint32_t addr = aBase + (uint32_t)(mt * 16 * 128) + colA;
                uint32_t ah[4], al[4];
                ldsm4(ah, addr + OFF_AH);
                ldsm4(al, addr + OFF_AL);
#pragma unroll
                for (int nt = 0; nt < 4; nt++) {
                    int g = nt >> 1, h = nt & 1;
                    mma16816(acc[mt][nt], ah, bh[g][h], bh[g][h + 2]);
                    mma16816(acc[mt][nt], ah, bl[g][h], bl[g][h + 2]);
                    mma16816(acc[mt][nt], al, bh[g][h], bh[g][h + 2]);
                }
            }
        }
        __syncthreads();

        bufsel++; if (bufsel >= NSTAGE) bufsel = 0;
    }

    // epilogue: standard m16n8 accumulator mapping
    int rBase = mBase + wm * 32 + (lane >> 2);
    int cBase = nBase + wn * 32 + (lane & 3) * 2;
#pragma unroll
    for (int mt = 0; mt < 2; mt++) {
#pragma unroll
        for (int nt = 0; nt < 4; nt++) {
            int r0 = rBase + mt * 16;
            int cc = cBase + nt * 8;
            if (r0 < M)
                *(float2*)(C + (size_t)r0 * C_OUT + cc) =
                    make_float2(acc[mt][nt][0], acc[mt][nt][1]);
            if (r0 + 8 < M)
                *(float2*)(C + (size_t)(r0 + 8) * C_OUT + cc) =
                    make_float2(acc[mt][nt][2], acc[mt][nt][3]);
        }
    }
}

// ---------------- launch 5/6: BN stats (deterministic two-pass) ----------------
__global__ void colstats_partial(const float* __restrict__ out0, int N) {
    int d = threadIdx.x;
    int blk = blockIdx.x;
    float s = 0.f, ss = 0.f;
    for (int r = blk; r < N; r += gridDim.x) {
        float v = out0[(size_t)r * C_OUT + d];
        s += v;
        ss += v * v;
    }
    g_psum[blk * C_OUT + d] = s;
    g_psq[blk * C_OUT + d]  = ss;
}

__global__ void colstats_final(const float* __restrict__ gamma,
                               const float* __restrict__ beta,
                               int N, int nchunks) {
    int d = threadIdx.x;
    float s = 0.f, ss = 0.f;
    for (int i = 0; i < nchunks; i++) {
        s += g_psum[i * C_OUT + d];
        ss += g_psq[i * C_OUT + d];
    }
    float invN = 1.0f / (float)N;
    float mean = s * invN;
    float var = ss * invN - mean * mean;
    float sc = rsqrtf(var + BN_EPS) * gamma[d];
    g_scale[d] = sc;
    g_bias[d] = beta[d] - mean * sc;
}

// ---------------- launch 7: BN + ReLU ----------------
__global__ void bn_relu_kernel(float* __restrict__ out, size_t total) {
    for (size_t i = (size_t)blockIdx.x * blockDim.x + threadIdx.x; i < total;
         i += (size_t)gridDim.x * blockDim.x) {
        int d = (int)(i & (C_OUT - 1));
        float v = fmaf(out[i], g_scale[d], g_bias[d]);
        out[i] = v > 0.0f ? v : 0.0f;
    }
}

// ---------------- launch ----------------
extern "C" void kernel_launch(void* const* d_in, const int* in_sizes, int n_in,
                              void* d_out, int out_size) {
    const float* x     = (const float*)d_in[0];
    const float* px    = (const float*)d_in[1];
    const float* py    = (const float*)d_in[2];
    const float* pxyz  = (const float*)d_in[3];
    const int*   pknn  = (const int*)d_in[4];
    const int*   np    = (const int*)d_in[5];
    const float* kp    = (const float*)d_in[6];
    const float* kpw   = (const float*)d_in[7];
    const float* gamma = (const float*)d_in[8];
    const float* beta  = (const float*)d_in[9];
    float* out = (float*)d_out;

    int N  = in_sizes[1];
    int Bn = in_sizes[5];

    cudaFuncSetAttribute(gemm_mma_kernel,
                         cudaFuncAttributeMaxDynamicSharedMemorySize, GEMM_SMEM);

    // launch 1: prefix sums + B transpose
    prep_all_kernel<<<(KD * C_OUT + 255) / 256, 256>>>(np, Bn, kpw);

    // launch 2: fused feats + allw
    int allw_blocks = (N * NNB + 255) / 256;
    feats_allw_kernel<<<N + allw_blocks, 256>>>(x, px, py, pxyz, pknn, kp, N, Bn);

    // launch 3: weighted (R6-proven config)
    weighted_kernel<<<N, 256>>>(pknn, N, Bn);

    // launch 4: GEMM (profiled slot)
    dim3 ggrid(C_OUT / GN, (N + GM - 1) / GM);
    gemm_mma_kernel<<<ggrid, GEMM_THREADS, GEMM_SMEM>>>(out, N);

    colstats_partial<<<256, C_OUT>>>(out, N);
    colstats_final<<<1, C_OUT>>>(gamma, beta, N, 256);

    size_t total = (size_t)N * C_OUT;
    bn_relu_kernel<<<2048, 256>>>(out, total);
}

// round 9
// speedup vs baseline: 1.2058x; 1.0315x over previous
#include <cuda_runtime.h>
#include <cuda_bf16.h>
#include <cstdint>
#include <cstddef>

// Problem constants
#define C_IN   256
#define C_OUT  256
#define KPTS   15
#define NNB    16
#define HH     64
#define WW     2048
#define KP_EXT 1.2f
#define BN_EPS 1e-5f
#define MAXB   8
#define MAXN   40000
#define KD     (KPTS * C_IN)        // 3840

// ---------------- scratch (device globals) ----------------
__device__ int   g_cum[MAXB + 1];
__device__ float g_feats[(size_t)MAXN * C_IN];
__device__ float g_allw[(size_t)MAXN * NNB * KPTS];
__device__ __nv_bfloat16 g_Ahi[(size_t)MAXN * KD];     // 307 MB
__device__ __nv_bfloat16 g_Alo[(size_t)MAXN * KD];     // 307 MB
__device__ __nv_bfloat16 g_Bhi[(size_t)C_OUT * KD];    // 1.9 MB, K-major [d][kc]
__device__ __nv_bfloat16 g_Blo[(size_t)C_OUT * KD];
__device__ float g_psum[256 * C_OUT];
__device__ float g_psq[256 * C_OUT];
__device__ float g_scale[C_OUT];
__device__ float g_bias[C_OUT];

// ---------------- PTX helpers (base sm_103-legal only) ----------------
__device__ __forceinline__ uint32_t smem_u32(const void* p) {
    uint32_t a;
    asm("{ .reg .u64 t; cvta.to.shared.u64 t, %1; cvt.u32.u64 %0, t; }" : "=r"(a) : "l"(p));
    return a;
}

#define CP_ASYNC16(dst_u32, src_ptr) \
    asm volatile("cp.async.cg.shared.global [%0], [%1], 16;" \
                 :: "r"(dst_u32), "l"(src_ptr) : "memory")
#define CP_COMMIT() asm volatile("cp.async.commit_group;" ::: "memory")
#define CP_WAIT1()  asm volatile("cp.async.wait_group 1;" ::: "memory")
#define CP_WAIT0()  asm volatile("cp.async.wait_group 0;" ::: "memory")

__device__ __forceinline__ void ldsm4(uint32_t* r, uint32_t addr) {
    asm volatile("ldmatrix.sync.aligned.m8n8.x4.shared.b16 {%0,%1,%2,%3}, [%4];"
                 : "=r"(r[0]), "=r"(r[1]), "=r"(r[2]), "=r"(r[3]) : "r"(addr));
}

__device__ __forceinline__ void mma16816(float* c, const uint32_t* a,
                                         uint32_t b0, uint32_t b1) {
    asm volatile(
        "mma.sync.aligned.m16n8k16.row.col.f32.bf16.bf16.f32 "
        "{%0,%1,%2,%3}, {%4,%5,%6,%7}, {%8,%9}, {%0,%1,%2,%3};"
        : "+f"(c[0]), "+f"(c[1]), "+f"(c[2]), "+f"(c[3])
        : "r"(a[0]), "r"(a[1]), "r"(a[2]), "r"(a[3]), "r"(b0), "r"(b1));
}

__device__ __forceinline__ int batch_of(int n, int Bn) {
    int b = 0;
#pragma unroll
    for (int i = 1; i < MAXB; i++)
        if (i < Bn && n >= g_cum[i]) b = i;
    return b;
}

// ---------------- launch 1: fused prefix sums + B hi/lo transpose ----------------
__global__ void prep_all_kernel(const int* __restrict__ np, int Bn,
                                const float* __restrict__ kpw) {
    if (blockIdx.x == 0 && threadIdx.x == 0) {
        int c = 0;
        for (int b = 0; b < Bn && b < MAXB; b++) { g_cum[b] = c; c += np[b]; }
        for (int b = Bn; b < MAXB; b++) g_cum[b] = c;
        g_cum[MAXB] = c;
    }
    int i = blockIdx.x * blockDim.x + threadIdx.x;
    if (i >= KD * C_OUT) return;
    int kc = i >> 8;
    int d  = i & 255;
    float v = kpw[i];
    __nv_bfloat16 h = __float2bfloat16(v);
    float rem = v - __bfloat162float(h);
    g_Bhi[(size_t)d * KD + kc] = h;
    g_Blo[(size_t)d * KD + kc] = __float2bfloat16(rem);
}

// ---------------- launch 2: fused grid sample + kernel-point weights ----------------
__global__ void feats_allw_kernel(const float* __restrict__ x,
                                  const float* __restrict__ px,
                                  const float* __restrict__ py,
                                  const float* __restrict__ pxyz,
                                  const int* __restrict__ pknn,
                                  const float* __restrict__ kp,
                                  int N, int Bn) {
    __shared__ float skp[KPTS * 3];
    int bid = blockIdx.x;
    if (bid < N) {
        int n = bid;
        int c = threadIdx.x;
        int b = batch_of(n, Bn);

        float ix = fminf(fmaxf((px[n] + 1.0f) * (WW * 0.5f) - 0.5f, 0.0f), (float)(WW - 1));
        float iy = fminf(fmaxf((py[n] + 1.0f) * (HH * 0.5f) - 0.5f, 0.0f), (float)(HH - 1));
        float x0f = floorf(ix), y0f = floorf(iy);
        float wx = ix - x0f, wy = iy - y0f;
        int x0 = (int)x0f, y0 = (int)y0f;
        int x1 = min(x0 + 1, WW - 1);
        int y1 = min(y0 + 1, HH - 1);

        const float* base = x + ((size_t)b * C_IN + c) * (size_t)(HH * WW);
        float v00 = base[(size_t)y0 * WW + x0];
        float v01 = base[(size_t)y0 * WW + x1];
        float v10 = base[(size_t)y1 * WW + x0];
        float v11 = base[(size_t)y1 * WW + x1];

        float top = v00 + (v01 - v00) * wx;
        float bot = v10 + (v11 - v10) * wx;
        g_feats[(size_t)n * C_IN + c] = top + (bot - top) * wy;
    } else {
        if (threadIdx.x < KPTS * 3) skp[threadIdx.x] = kp[threadIdx.x];
        __syncthreads();

        int t = (bid - N) * 256 + threadIdx.x;
        int n = t / NNB;
        int a = t % NNB;
        if (n >= N) return;
        int b = batch_of(n, Bn);
        int j = pknn[(size_t)n * NNB + a] + g_cum[b];

        float cx = pxyz[(size_t)n * 3 + 0];
        float cy = pxyz[(size_t)n * 3 + 1];
        float cz = pxyz[(size_t)n * 3 + 2];
        float rx = pxyz[(size_t)j * 3 + 0] - cx;
        float ry = pxyz[(size_t)j * 3 + 1] - cy;
        float rz = pxyz[(size_t)j * 3 + 2] - cz;

#pragma unroll
        for (int k = 0; k < KPTS; k++) {
            float dx = rx - skp[k * 3 + 0];
            float dy = ry - skp[k * 3 + 1];
            float dz = rz - skp[k * 3 + 2];
            float dist = sqrtf(dx * dx + dy * dy + dz * dz);
            g_allw[((size_t)n * NNB + a) * KPTS + k] = fmaxf(1.0f - dist * (1.0f / KP_EXT), 0.0f);
        }
    }
}

// ---------------- launch 3: weighted -> bf16 hi/lo (float2, 128 thr/point) ----------------
// one block per point, 128 threads, each owns channels (2t, 2t+1)
__global__ void __launch_bounds__(128)
weighted_kernel(const int* __restrict__ pknn, int N, int Bn) {
    int n = blockIdx.x;
    int c2 = threadIdx.x;          // 0..127
    if (n >= N) return;

    __shared__ float sw[NNB * KPTS];
    __shared__ int sidx[NNB];
    if (c2 < NNB) {
        int b = batch_of(n, Bn);
        sidx[c2] = pknn[(size_t)n * NNB + c2] + g_cum[b];
    }
    for (int i = c2; i < NNB * KPTS; i += 128)
        sw[i] = g_allw[(size_t)n * NNB * KPTS + i];
    __syncthreads();

    float2 nx[NNB];
#pragma unroll
    for (int a = 0; a < NNB; a++)
        nx[a] = *(const float2*)(g_feats + (size_t)sidx[a] * C_IN + 2 * c2);

    __nv_bfloat162* Ahi2 = (__nv_bfloat162*)g_Ahi;
    __nv_bfloat162* Alo2 = (__nv_bfloat162*)g_Alo;
    size_t rowbase = ((size_t)n * KD) >> 1;

#pragma unroll
    for (int k = 0; k < KPTS; k++) {
        float acc0 = 0.0f, acc1 = 0.0f;
#pragma unroll
        for (int a = 0; a < NNB; a++) {
            float w = sw[a * KPTS + k];
            acc0 = fmaf(w, nx[a].x, acc0);
            acc1 = fmaf(w, nx[a].y, acc1);
        }
        __nv_bfloat16 h0 = __float2bfloat16(acc0);
        __nv_bfloat16 h1 = __float2bfloat16(acc1);
        float r0 = acc0 - __bfloat162float(h0);
        float r1 = acc1 - __bfloat162float(h1);
        size_t idx = rowbase + (size_t)k * 128 + c2;
        Ahi2[idx] = __nv_bfloat162(h0, h1);
        Alo2[idx] = __nv_bfloat162(__float2bfloat16(r0), __float2bfloat16(r1));
    }
}

// ---------------- launch 4: HMMA bf16 3-pass GEMM, multistage pipeline ----------------
// C[m, d] = sum_kc A[m,kc] * B[d,kc]
// CTA: 128(M) x 128(N), 512 threads = 16 warps = 4(M) x 4(N), warp tile 32 x 32
// Mainloop: 1 sync/chunk; cp.async issue AFTER sync overlaps MMA (cutlass multistage)
#define GM 128
#define GN 128
#define KCHUNK 64
#define NCHUNKS (KD / KCHUNK)           // 60
#define ARR_BYTES 16384                 // one 128x64 bf16 array
#define OFF_AH 0
#define OFF_AL 16384
#define OFF_BH 32768
#define OFF_BL 49152
#define STAGE_BYTES 65536
#define NSTAGE 3
#define GEMM_SMEM (NSTAGE * STAGE_BYTES + 1024)
#define GEMM_THREADS 512

extern __shared__ char gemm_smem[];

__device__ __forceinline__ void issue_chunk(uint32_t stage_u32, int mBase, int nBase,
                                            int k0, int M, int tid) {
    int r_lo = tid >> 3;        // 0..63
    int i    = tid & 7;         // 16B granule within 128B row
    const __nv_bfloat16* __restrict__ Ah = g_Ahi;
    const __nv_bfloat16* __restrict__ Al = g_Alo;
    const __nv_bfloat16* __restrict__ Bh = g_Bhi;
    const __nv_bfloat16* __restrict__ Bl = g_Blo;
#pragma unroll
    for (int p = 0; p < 8; p++) {
        int quarter = p >> 1;                   // 0:Ah 1:Al 2:Bh 3:Bl
        int row = (p & 1) * 64 + r_lo;          // 0..127
        uint32_t off = (uint32_t)(row * 128 + i * 16);
        uint32_t sw = off ^ ((off >> 3) & 0x70);
        uint32_t dst = stage_u32 + quarter * ARR_BYTES + sw;
        const __nv_bfloat16* src;
        if (quarter == 0) {
            int gr = min(mBase + row, M - 1);
            src = Ah + (size_t)gr * KD + k0 + i * 8;
        } else if (quarter == 1) {
            int gr = min(mBase + row, M - 1);
            src = Al + (size_t)gr * KD + k0 + i * 8;
        } else if (quarter == 2) {
            src = Bh + (size_t)(nBase + row) * KD + k0 + i * 8;
        } else {
            src = Bl + (size_t)(nBase + row) * KD + k0 + i * 8;
        }
        CP_ASYNC16(dst, src);
    }
}

__global__ void __launch_bounds__(GEMM_THREADS, 1) gemm_mma_kernel(float* __restrict__ C, int M) {
    int tid = threadIdx.x;
    int wid = tid >> 5;
    int lane = tid & 31;
    int wm = wid & 3;          // 0..3  (32 rows each)
    int wn = wid >> 2;         // 0..3  (32 cols each)
    int mBase = blockIdx.y * GM;
    int nBase = blockIdx.x * GN;

    uint32_t dyn_u32 = smem_u32(gemm_smem);
    uint32_t base_u32 = (dyn_u32 + 1023u) & ~1023u;

    float acc[2][4][4];
#pragma unroll
    for (int a = 0; a < 2; a++)
#pragma unroll
        for (int b = 0; b < 4; b++)
#pragma unroll
            for (int c = 0; c < 4; c++) acc[a][b][c] = 0.0f;

    // per-lane ldmatrix address components
    int lrow = lane & 15;                 // row within 16-row group
    int csel = (lane >> 4) * 16;          // 16B column half (k0-7 / k8-15)
    int aRow = wm * 32 + lrow;            // A row for mt=0
    int bRow = wn * 32 + lrow;            // B row for 16-n group 0
    uint32_t xa = (uint32_t)((aRow & 7) << 4);
    uint32_t xb = (uint32_t)((bRow & 7) << 4);

    // prologue: fill 2 of 3 stages
    issue_chunk(base_u32 + 0 * STAGE_BYTES, mBase, nBase, 0, M, tid);
    CP_COMMIT();
    issue_chunk(base_u32 + 1 * STAGE_BYTES, mBase, nBase, KCHUNK, M, tid);
    CP_COMMIT();

    int bufsel = 0;
    for (int ch = 0; ch < NCHUNKS; ch++) {
        uint32_t stg = base_u32 + bufsel * STAGE_BYTES;

        // retire the oldest in-flight copy (chunk ch), then one CTA-wide sync.
        if (ch == NCHUNKS - 1) { CP_WAIT0(); } else { CP_WAIT1(); }
        __syncthreads();

        // issue copy for chunk ch+2 AFTER the sync: its destination buffer
        // (ch+2)%3 == (ch-1)%3 was fully consumed before this barrier, and the
        // copy overlaps the MMA work below.
        if (ch + 2 < NCHUNKS) {
            int nbuf = bufsel + 2; if (nbuf >= NSTAGE) nbuf -= NSTAGE;
            issue_chunk(base_u32 + nbuf * STAGE_BYTES,
                        mBase, nBase, (ch + 2) * KCHUNK, M, tid);
            CP_COMMIT();
        }

        uint32_t aBase = stg + (uint32_t)(aRow * 128);
        uint32_t bBase = stg + (uint32_t)(bRow * 128);

#pragma unroll
        for (int ks = 0; ks < 4; ks++) {
            uint32_t colA = ((uint32_t)(ks * 32 + csel)) ^ xa;
            uint32_t colB = ((uint32_t)(ks * 32 + csel)) ^ xb;

            uint32_t bh[2][4], bl[2][4];
#pragma unroll
            for (int g = 0; g < 2; g++) {
                uint32_t addr = bBase + (uint32_t)(g * 16 * 128) + colB;
                ldsm4(bh[g], addr + OFF_BH);
                ldsm4(bl[g], addr + OFF_BL);
            }
#pragma unroll
            for (int mt = 0; mt < 2; mt++) {
                uint32_t addr = aBase + (uint32_t)(mt * 16 * 128) + colA;
                uint32_t ah[4], al[4];
                ldsm4(ah, addr + OFF_AH);
                ldsm4(al, addr + OFF_AL);
#pragma unroll
                for (int nt = 0; nt < 4; nt++) {
                    int g = nt >> 1, h = nt & 1;
                    mma16816(acc[mt][nt], ah, bh[g][h], bh[g][h + 2]);
                    mma16816(acc[mt][nt], ah, bl[g][h], bl[g][h + 2]);
                    mma16816(acc[mt][nt], al, bh[g][h], bh[g][h + 2]);
                }
            }
        }

        bufsel++; if (bufsel >= NSTAGE) bufsel = 0;
    }

    // epilogue: standard m16n8 accumulator mapping
    int rBase = mBase + wm * 32 + (lane >> 2);
    int cBase = nBase + wn * 32 + (lane & 3) * 2;
#pragma unroll
    for (int mt = 0; mt < 2; mt++) {
#pragma unroll
        for (int nt = 0; nt < 4; nt++) {
            int r0 = rBase + mt * 16;
            int cc = cBase + nt * 8;
            if (r0 < M)
                *(float2*)(C + (size_t)r0 * C_OUT + cc) =
                    make_float2(acc[mt][nt][0], acc[mt][nt][1]);
            if (r0 + 8 < M)
                *(float2*)(C + (size_t)(r0 + 8) * C_OUT + cc) =
                    make_float2(acc[mt][nt][2], acc[mt][nt][3]);
        }
    }
}

// ---------------- launch 5/6: BN stats (deterministic two-pass) ----------------
__global__ void colstats_partial(const float* __restrict__ out0, int N) {
    int d = threadIdx.x;
    int blk = blockIdx.x;
    float s = 0.f, ss = 0.f;
    for (int r = blk; r < N; r += gridDim.x) {
        float v = out0[(size_t)r * C_OUT + d];
        s += v;
        ss += v * v;
    }
    g_psum[blk * C_OUT + d] = s;
    g_psq[blk * C_OUT + d]  = ss;
}

__global__ void colstats_final(const float* __restrict__ gamma,
                               const float* __restrict__ beta,
                               int N, int nchunks) {
    int d = threadIdx.x;
    float s = 0.f, ss = 0.f;
    for (int i = 0; i < nchunks; i++) {
        s += g_psum[i * C_OUT + d];
        ss += g_psq[i * C_OUT + d];
    }
    float invN = 1.0f / (float)N;
    float mean = s * invN;
    float var = ss * invN - mean * mean;
    float sc = rsqrtf(var + BN_EPS) * gamma[d];
    g_scale[d] = sc;
    g_bias[d] = beta[d] - mean * sc;
}

// ---------------- launch 7: BN + ReLU ----------------
__global__ void bn_relu_kernel(float* __restrict__ out, size_t total) {
    for (size_t i = (size_t)blockIdx.x * blockDim.x + threadIdx.x; i < total;
         i += (size_t)gridDim.x * blockDim.x) {
        int d = (int)(i & (C_OUT - 1));
        float v = fmaf(out[i], g_scale[d], g_bias[d]);
        out[i] = v > 0.0f ? v : 0.0f;
    }
}

// ---------------- launch ----------------
extern "C" void kernel_launch(void* const* d_in, const int* in_sizes, int n_in,
                              void* d_out, int out_size) {
    const float* x     = (const float*)d_in[0];
    const float* px    = (const float*)d_in[1];
    const float* py    = (const float*)d_in[2];
    const float* pxyz  = (const float*)d_in[3];
    const int*   pknn  = (const int*)d_in[4];
    const int*   np    = (const int*)d_in[5];
    const float* kp    = (const float*)d_in[6];
    const float* kpw   = (const float*)d_in[7];
    const float* gamma = (const float*)d_in[8];
    const float* beta  = (const float*)d_in[9];
    float* out = (float*)d_out;

    int N  = in_sizes[1];
    int Bn = in_sizes[5];

    cudaFuncSetAttribute(gemm_mma_kernel,
                         cudaFuncAttributeMaxDynamicSharedMemorySize, GEMM_SMEM);

    // launch 1: prefix sums + B transpose
    prep_all_kernel<<<(KD * C_OUT + 255) / 256, 256>>>(np, Bn, kpw);

    // launch 2: fused feats + allw
    int allw_blocks = (N * NNB + 255) / 256;
    feats_allw_kernel<<<N + allw_blocks, 256>>>(x, px, py, pxyz, pknn, kp, N, Bn);

    // launch 3: weighted (float2, 128 threads per point)
    weighted_kernel<<<N, 128>>>(pknn, N, Bn);

    // launch 4: GEMM (profiled slot)
    dim3 ggrid(C_OUT / GN, (N + GM - 1) / GM);
    gemm_mma_kernel<<<ggrid, GEMM_THREADS, GEMM_SMEM>>>(out, N);

    colstats_partial<<<256, C_OUT>>>(out, N);
    colstats_final<<<1, C_OUT>>>(gamma, beta, N, 256);

    size_t total = (size_t)N * C_OUT;
    bn_relu_kernel<<<2048, 256>>>(out, total);
}

// round 10
// speedup vs baseline: 1.2936x; 1.0728x over previous
#include <cuda_runtime.h>
#include <cuda_bf16.h>
#include <cstdint>
#include <cstddef>

// Problem constants
#define C_IN   256
#define C_OUT  256
#define KPTS   15
#define NNB    16
#define HH     64
#define WW     2048
#define KP_EXT 1.2f
#define BN_EPS 1e-5f
#define MAXB   8
#define MAXN   40000
#define KD     (KPTS * C_IN)        // 3840

// ---------------- scratch (device globals) ----------------
__device__ int   g_cum[MAXB + 1];
__device__ float g_feats[(size_t)MAXN * C_IN];
__device__ float g_allw[(size_t)MAXN * NNB * KPTS];
__device__ __nv_bfloat16 g_Ahi[(size_t)MAXN * KD];     // 307 MB
__device__ __nv_bfloat16 g_Alo[(size_t)MAXN * KD];     // 307 MB
__device__ __nv_bfloat16 g_Bhi[(size_t)C_OUT * KD];    // 1.9 MB, K-major [d][kc]
__device__ __nv_bfloat16 g_Blo[(size_t)C_OUT * KD];
__device__ float g_psum[256 * C_OUT];
__device__ float g_psq[256 * C_OUT];
__device__ float g_scale[C_OUT];
__device__ float g_bias[C_OUT];

// ---------------- PTX helpers (base sm_103-legal only) ----------------
__device__ __forceinline__ uint32_t smem_u32(const void* p) {
    uint32_t a;
    asm("{ .reg .u64 t; cvta.to.shared.u64 t, %1; cvt.u32.u64 %0, t; }" : "=r"(a) : "l"(p));
    return a;
}

#define CP_ASYNC16(dst_u32, src_ptr) \
    asm volatile("cp.async.cg.shared.global [%0], [%1], 16;" \
                 :: "r"(dst_u32), "l"(src_ptr) : "memory")
#define CP_COMMIT() asm volatile("cp.async.commit_group;" ::: "memory")
#define CP_WAIT1()  asm volatile("cp.async.wait_group 1;" ::: "memory")
#define CP_WAIT0()  asm volatile("cp.async.wait_group 0;" ::: "memory")

__device__ __forceinline__ void ldsm4(uint32_t* r, uint32_t addr) {
    asm volatile("ldmatrix.sync.aligned.m8n8.x4.shared.b16 {%0,%1,%2,%3}, [%4];"
                 : "=r"(r[0]), "=r"(r[1]), "=r"(r[2]), "=r"(r[3]) : "r"(addr));
}

__device__ __forceinline__ void mma16816(float* c, const uint32_t* a,
                                         uint32_t b0, uint32_t b1) {
    asm volatile(
        "mma.sync.aligned.m16n8k16.row.col.f32.bf16.bf16.f32 "
        "{%0,%1,%2,%3}, {%4,%5,%6,%7}, {%8,%9}, {%0,%1,%2,%3};"
        : "+f"(c[0]), "+f"(c[1]), "+f"(c[2]), "+f"(c[3])
        : "r"(a[0]), "r"(a[1]), "r"(a[2]), "r"(a[3]), "r"(b0), "r"(b1));
}

__device__ __forceinline__ int batch_of(int n, int Bn) {
    int b = 0;
#pragma unroll
    for (int i = 1; i < MAXB; i++)
        if (i < Bn && n >= g_cum[i]) b = i;
    return b;
}

// ---------------- launch 1: fused prefix sums + B hi/lo transpose ----------------
__global__ void prep_all_kernel(const int* __restrict__ np, int Bn,
                                const float* __restrict__ kpw) {
    if (blockIdx.x == 0 && threadIdx.x == 0) {
        int c = 0;
        for (int b = 0; b < Bn && b < MAXB; b++) { g_cum[b] = c; c += np[b]; }
        for (int b = Bn; b < MAXB; b++) g_cum[b] = c;
        g_cum[MAXB] = c;
    }
    int i = blockIdx.x * blockDim.x + threadIdx.x;
    if (i >= KD * C_OUT) return;
    int kc = i >> 8;
    int d  = i & 255;
    float v = kpw[i];
    __nv_bfloat16 h = __float2bfloat16(v);
    float rem = v - __bfloat162float(h);
    g_Bhi[(size_t)d * KD + kc] = h;
    g_Blo[(size_t)d * KD + kc] = __float2bfloat16(rem);
}

// ---------------- launch 2: fused grid sample + kernel-point weights ----------------
__global__ void feats_allw_kernel(const float* __restrict__ x,
                                  const float* __restrict__ px,
                                  const float* __restrict__ py,
                                  const float* __restrict__ pxyz,
                                  const int* __restrict__ pknn,
                                  const float* __restrict__ kp,
                                  int N, int Bn) {
    __shared__ float skp[KPTS * 3];
    int bid = blockIdx.x;
    if (bid < N) {
        int n = bid;
        int c = threadIdx.x;
        int b = batch_of(n, Bn);

        float ix = fminf(fmaxf((px[n] + 1.0f) * (WW * 0.5f) - 0.5f, 0.0f), (float)(WW - 1));
        float iy = fminf(fmaxf((py[n] + 1.0f) * (HH * 0.5f) - 0.5f, 0.0f), (float)(HH - 1));
        float x0f = floorf(ix), y0f = floorf(iy);
        float wx = ix - x0f, wy = iy - y0f;
        int x0 = (int)x0f, y0 = (int)y0f;
        int x1 = min(x0 + 1, WW - 1);
        int y1 = min(y0 + 1, HH - 1);

        const float* base = x + ((size_t)b * C_IN + c) * (size_t)(HH * WW);
        float v00 = base[(size_t)y0 * WW + x0];
        float v01 = base[(size_t)y0 * WW + x1];
        float v10 = base[(size_t)y1 * WW + x0];
        float v11 = base[(size_t)y1 * WW + x1];

        float top = v00 + (v01 - v00) * wx;
        float bot = v10 + (v11 - v10) * wx;
        g_feats[(size_t)n * C_IN + c] = top + (bot - top) * wy;
    } else {
        if (threadIdx.x < KPTS * 3) skp[threadIdx.x] = kp[threadIdx.x];
        __syncthreads();

        int t = (bid - N) * 256 + threadIdx.x;
        int n = t / NNB;
        int a = t % NNB;
        if (n >= N) return;
        int b = batch_of(n, Bn);
        int j = pknn[(size_t)n * NNB + a] + g_cum[b];

        float cx = pxyz[(size_t)n * 3 + 0];
        float cy = pxyz[(size_t)n * 3 + 1];
        float cz = pxyz[(size_t)n * 3 + 2];
        float rx = pxyz[(size_t)j * 3 + 0] - cx;
        float ry = pxyz[(size_t)j * 3 + 1] - cy;
        float rz = pxyz[(size_t)j * 3 + 2] - cz;

#pragma unroll
        for (int k = 0; k < KPTS; k++) {
            float dx = rx - skp[k * 3 + 0];
            float dy = ry - skp[k * 3 + 1];
            float dz = rz - skp[k * 3 + 2];
            float dist = sqrtf(dx * dx + dy * dy + dz * dz);
            g_allw[((size_t)n * NNB + a) * KPTS + k] = fmaxf(1.0f - dist * (1.0f / KP_EXT), 0.0f);
        }
    }
}

// ---------------- launch 3: weighted -> bf16 hi/lo (float2, 128 thr/point) ----------------
__global__ void __launch_bounds__(128)
weighted_kernel(const int* __restrict__ pknn, int N, int Bn) {
    int n = blockIdx.x;
    int c2 = threadIdx.x;          // 0..127
    if (n >= N) return;

    __shared__ float sw[NNB * KPTS];
    __shared__ int sidx[NNB];
    if (c2 < NNB) {
        int b = batch_of(n, Bn);
        sidx[c2] = pknn[(size_t)n * NNB + c2] + g_cum[b];
    }
    for (int i = c2; i < NNB * KPTS; i += 128)
        sw[i] = g_allw[(size_t)n * NNB * KPTS + i];
    __syncthreads();

    float2 nx[NNB];
#pragma unroll
    for (int a = 0; a < NNB; a++)
        nx[a] = *(const float2*)(g_feats + (size_t)sidx[a] * C_IN + 2 * c2);

    __nv_bfloat162* Ahi2 = (__nv_bfloat162*)g_Ahi;
    __nv_bfloat162* Alo2 = (__nv_bfloat162*)g_Alo;
    size_t rowbase = ((size_t)n * KD) >> 1;

#pragma unroll
    for (int k = 0; k < KPTS; k++) {
        float acc0 = 0.0f, acc1 = 0.0f;
#pragma unroll
        for (int a = 0; a < NNB; a++) {
            float w = sw[a * KPTS + k];
            acc0 = fmaf(w, nx[a].x, acc0);
            acc1 = fmaf(w, nx[a].y, acc1);
        }
        __nv_bfloat16 h0 = __float2bfloat16(acc0);
        __nv_bfloat16 h1 = __float2bfloat16(acc1);
        float r0 = acc0 - __bfloat162float(h0);
        float r1 = acc1 - __bfloat162float(h1);
        size_t idx = rowbase + (size_t)k * 128 + c2;
        Ahi2[idx] = __nv_bfloat162(h0, h1);
        Alo2[idx] = __nv_bfloat162(__float2bfloat16(r0), __float2bfloat16(r1));
    }
}

// ---------------- launch 4: HMMA bf16 3-pass GEMM, 2 CTAs/SM ----------------
// C[m, d] = sum_kc A[m,kc] * B[d,kc]
// CTA: 128(M) x 64(N), 256 threads = 8 warps = 4(M) x 2(N), warp tile 32 x 32
// 2-stage double buffer (48 KB/stage, 96 KB total) -> 2 CTAs resident per SM;
// cross-CTA overlap hides barrier + pipeline-fill stalls.
#define GM 128
#define GN 64
#define KCHUNK 64
#define NCHUNKS (KD / KCHUNK)           // 60
#define OFF_AH 0                        // 128 rows x 128B = 16 KB
#define OFF_AL 16384
#define OFF_BH 32768                    // 64 rows x 128B = 8 KB
#define OFF_BL 40960
#define STAGE_BYTES 49152               // 48 KB
#define NSTAGE 2
#define GEMM_SMEM (NSTAGE * STAGE_BYTES + 1024)
#define GEMM_THREADS 256

extern __shared__ char gemm_smem[];

__device__ __forceinline__ void issue_chunk(uint32_t stage_u32, int mBase, int nBase,
                                            int k0, int M, int tid) {
    int r_lo = tid >> 3;        // 0..31
    int i    = tid & 7;         // 16B granule within 128B row
    const __nv_bfloat16* __restrict__ Ah = g_Ahi;
    const __nv_bfloat16* __restrict__ Al = g_Alo;
    const __nv_bfloat16* __restrict__ Bh = g_Bhi;
    const __nv_bfloat16* __restrict__ Bl = g_Blo;
    // 3072 granules = 256 threads x 12
#pragma unroll
    for (int p = 0; p < 12; p++) {
        uint32_t dst;
        const __nv_bfloat16* src;
        if (p < 4) {                       // Ah rows 0..127
            int row = p * 32 + r_lo;
            uint32_t off = (uint32_t)(row * 128 + i * 16);
            uint32_t sw = off ^ ((off >> 3) & 0x70);
            int gr = min(mBase + row, M - 1);
            dst = stage_u32 + OFF_AH + sw;
            src = Ah + (size_t)gr * KD + k0 + i * 8;
        } else if (p < 8) {                // Al
            int row = (p - 4) * 32 + r_lo;
            uint32_t off = (uint32_t)(row * 128 + i * 16);
            uint32_t sw = off ^ ((off >> 3) & 0x70);
            int gr = min(mBase + row, M - 1);
            dst = stage_u32 + OFF_AL + sw;
            src = Al + (size_t)gr * KD + k0 + i * 8;
        } else if (p < 10) {               // Bh rows 0..63
            int row = (p - 8) * 32 + r_lo;
            uint32_t off = (uint32_t)(row * 128 + i * 16);
            uint32_t sw = off ^ ((off >> 3) & 0x70);
            dst = stage_u32 + OFF_BH + sw;
            src = Bh + (size_t)(nBase + row) * KD + k0 + i * 8;
        } else {                           // Bl
            int row = (p - 10) * 32 + r_lo;
            uint32_t off = (uint32_t)(row * 128 + i * 16);
            uint32_t sw = off ^ ((off >> 3) & 0x70);
            dst = stage_u32 + OFF_BL + sw;
            src = Bl + (size_t)(nBase + row) * KD + k0 + i * 8;
        }
        CP_ASYNC16(dst, src);
    }
}

__global__ void __launch_bounds__(GEMM_THREADS, 2) gemm_mma_kernel(float* __restrict__ C, int M) {
    int tid = threadIdx.x;
    int wid = tid >> 5;
    int lane = tid & 31;
    int wm = wid & 3;          // 0..3  (32 rows each)
    int wn = wid >> 2;         // 0..1  (32 cols each)
    int mBase = blockIdx.y * GM;
    int nBase = blockIdx.x * GN;

    uint32_t dyn_u32 = smem_u32(gemm_smem);
    uint32_t base_u32 = (dyn_u32 + 1023u) & ~1023u;

    float acc[2][4][4];
#pragma unroll
    for (int a = 0; a < 2; a++)
#pragma unroll
        for (int b = 0; b < 4; b++)
#pragma unroll
            for (int c = 0; c < 4; c++) acc[a][b][c] = 0.0f;

    // per-lane ldmatrix address components
    int lrow = lane & 15;                 // row within 16-row group
    int csel = (lane >> 4) * 16;          // 16B column half (k0-7 / k8-15)
    int aRow = wm * 32 + lrow;            // A row for mt=0
    int bRow = wn * 32 + lrow;            // B row for 16-n group 0
    uint32_t xa = (uint32_t)((aRow & 7) << 4);
    uint32_t xb = (uint32_t)((bRow & 7) << 4);

    // prologue
    issue_chunk(base_u32, mBase, nBase, 0, M, tid);
    CP_COMMIT();

    for (int ch = 0; ch < NCHUNKS; ch++) {
        int buf = ch & 1;
        uint32_t stg = base_u32 + buf * STAGE_BYTES;

        if (ch + 1 < NCHUNKS) {
            // buffer buf^1 was consumed in iter ch-1 (protected by trailing sync)
            issue_chunk(base_u32 + (buf ^ 1) * STAGE_BYTES,
                        mBase, nBase, (ch + 1) * KCHUNK, M, tid);
            CP_COMMIT();
            CP_WAIT1();       // chunk ch complete; ch+1 may be in flight
        } else {
            CP_WAIT0();
        }
        __syncthreads();

        uint32_t aBase = stg + (uint32_t)(aRow * 128);
        uint32_t bBase = stg + (uint32_t)(bRow * 128);

#pragma unroll
        for (int ks = 0; ks < 4; ks++) {
            uint32_t colA = ((uint32_t)(ks * 32 + csel)) ^ xa;
            uint32_t colB = ((uint32_t)(ks * 32 + csel)) ^ xb;

            uint32_t bh[2][4], bl[2][4];
#pragma unroll
            for (int g = 0; g < 2; g++) {
                uint32_t addr = bBase + (uint32_t)(g * 16 * 128) + colB;
                ldsm4(bh[g], addr + OFF_BH);
                ldsm4(bl[g], addr + OFF_BL);
            }
#pragma unroll
            for (int mt = 0; mt < 2; mt++) {
                uint32_t addr = aBase + (uint32_t)(mt * 16 * 128) + colA;
                uint32_t ah[4], al[4];
                ldsm4(ah, addr + OFF_AH);
                ldsm4(al, addr + OFF_AL);
#pragma unroll
                for (int nt = 0; nt < 4; nt++) {
                    int g = nt >> 1, h = nt & 1;
                    mma16816(acc[mt][nt], ah, bh[g][h], bh[g][h + 2]);
                    mma16816(acc[mt][nt], ah, bl[g][h], bl[g][h + 2]);
                    mma16816(acc[mt][nt], al, bh[g][h], bh[g][h + 2]);
                }
            }
        }
        __syncthreads();   // buffer ch free before iter ch+1 overwrites it
    }

    // epilogue: standard m16n8 accumulator mapping
    int rBase = mBase + wm * 32 + (lane >> 2);
    int cBase = nBase + wn * 32 + (lane & 3) * 2;
#pragma unroll
    for (int mt = 0; mt < 2; mt++) {
#pragma unroll
        for (int nt = 0; nt < 4; nt++) {
            int r0 = rBase + mt * 16;
            int cc = cBase + nt * 8;
            if (r0 < M)
                *(float2*)(C + (size_t)r0 * C_OUT + cc) =
                    make_float2(acc[mt][nt][0], acc[mt][nt][1]);
            if (r0 + 8 < M)
                *(float2*)(C + (size_t)(r0 + 8) * C_OUT + cc) =
                    make_float2(acc[mt][nt][2], acc[mt][nt][3]);
        }
    }
}

// ---------------- launch 5/6: BN stats (deterministic two-pass) ----------------
__global__ void colstats_partial(const float* __restrict__ out0, int N) {
    int d = threadIdx.x;
    int blk = blockIdx.x;
    float s = 0.f, ss = 0.f;
    for (int r = blk; r < N; r += gridDim.x) {
        float v = out0[(size_t)r * C_OUT + d];
        s += v;
        ss += v * v;
    }
    g_psum[blk * C_OUT + d] = s;
    g_psq[blk * C_OUT + d]  = ss;
}

__global__ void colstats_final(const float* __restrict__ gamma,
                               const float* __restrict__ beta,
                               int N, int nchunks) {
    int d = threadIdx.x;
    float s = 0.f, ss = 0.f;
    for (int i = 0; i < nchunks; i++) {
        s += g_psum[i * C_OUT + d];
        ss += g_psq[i * C_OUT + d];
    }
    float invN = 1.0f / (float)N;
    float mean = s * invN;
    float var = ss * invN - mean * mean;
    float sc = rsqrtf(var + BN_EPS) * gamma[d];
    g_scale[d] = sc;
    g_bias[d] = beta[d] - mean * sc;
}

// ---------------- launch 7: BN + ReLU ----------------
__global__ void bn_relu_kernel(float* __restrict__ out, size_t total) {
    for (size_t i = (size_t)blockIdx.x * blockDim.x + threadIdx.x; i < total;
         i += (size_t)gridDim.x * blockDim.x) {
        int d = (int)(i & (C_OUT - 1));
        float v = fmaf(out[i], g_scale[d], g_bias[d]);
        out[i] = v > 0.0f ? v : 0.0f;
    }
}

// ---------------- launch ----------------
extern "C" void kernel_launch(void* const* d_in, const int* in_sizes, int n_in,
                              void* d_out, int out_size) {
    const float* x     = (const float*)d_in[0];
    const float* px    = (const float*)d_in[1];
    const float* py    = (const float*)d_in[2];
    const float* pxyz  = (const float*)d_in[3];
    const int*   pknn  = (const int*)d_in[4];
    const int*   np    = (const int*)d_in[5];
    const float* kp    = (const float*)d_in[6];
    const float* kpw   = (const float*)d_in[7];
    const float* gamma = (const float*)d_in[8];
    const float* beta  = (const float*)d_in[9];
    float* out = (float*)d_out;

    int N  = in_sizes[1];
    int Bn = in_sizes[5];

    cudaFuncSetAttribute(gemm_mma_kernel,
                         cudaFuncAttributeMaxDynamicSharedMemorySize, GEMM_SMEM);

    // launch 1: prefix sums + B transpose
    prep_all_kernel<<<(KD * C_OUT + 255) / 256, 256>>>(np, Bn, kpw);

    // launch 2: fused feats + allw
    int allw_blocks = (N * NNB + 255) / 256;
    feats_allw_kernel<<<N + allw_blocks, 256>>>(x, px, py, pxyz, pknn, kp, N, Bn);

    // launch 3: weighted (float2, 128 threads per point)
    weighted_kernel<<<N, 128>>>(pknn, N, Bn);

    // launch 4: GEMM (profiled slot) — 2 CTAs/SM
    dim3 ggrid(C_OUT / GN, (N + GM - 1) / GM);
    gemm_mma_kernel<<<ggrid, GEMM_THREADS, GEMM_SMEM>>>(out, N);

    colstats_partial<<<256, C_OUT>>>(out, N);
    colstats_final<<<1, C_OUT>>>(gamma, beta, N, 256);

    size_t total = (size_t)N * C_OUT;
    bn_relu_kernel<<<2048, 256>>>(out, total);
}

// round 11
// speedup vs baseline: 1.3063x; 1.0098x over previous
#include <cuda_runtime.h>
#include <cuda_bf16.h>
#include <cstdint>
#include <cstddef>

// Problem constants
#define C_IN   256
#define C_OUT  256
#define KPTS   15
#define NNB    16
#define HH     64
#define WW     2048
#define KP_EXT 1.2f
#define BN_EPS 1e-5f
#define MAXB   8
#define MAXN   40000
#define KD     (KPTS * C_IN)        // 3840
#define MAXMT  320                  // max M-tiles (40000/128 = 313)

// ---------------- scratch (device globals) ----------------
__device__ int   g_cum[MAXB + 1];
__device__ float g_feats[(size_t)MAXN * C_IN];
__device__ float g_allw[(size_t)MAXN * NNB * KPTS];
__device__ __nv_bfloat16 g_Ahi[(size_t)MAXN * KD];     // 307 MB
__device__ __nv_bfloat16 g_Alo[(size_t)MAXN * KD];     // 307 MB
__device__ __nv_bfloat16 g_Bhi[(size_t)C_OUT * KD];    // 1.9 MB, K-major [d][kc]
__device__ __nv_bfloat16 g_Blo[(size_t)C_OUT * KD];
__device__ float g_psum[MAXMT * C_OUT];
__device__ float g_psq[MAXMT * C_OUT];
__device__ float g_scale[C_OUT];
__device__ float g_bias[C_OUT];

// ---------------- PTX helpers (base sm_103-legal only) ----------------
__device__ __forceinline__ uint32_t smem_u32(const void* p) {
    uint32_t a;
    asm("{ .reg .u64 t; cvta.to.shared.u64 t, %1; cvt.u32.u64 %0, t; }" : "=r"(a) : "l"(p));
    return a;
}

#define CP_ASYNC16(dst_u32, src_ptr) \
    asm volatile("cp.async.cg.shared.global [%0], [%1], 16;" \
                 :: "r"(dst_u32), "l"(src_ptr) : "memory")
#define CP_COMMIT() asm volatile("cp.async.commit_group;" ::: "memory")
#define CP_WAIT0()  asm volatile("cp.async.wait_group 0;" ::: "memory")

__device__ __forceinline__ void ldsm4(uint32_t* r, uint32_t addr) {
    asm volatile("ldmatrix.sync.aligned.m8n8.x4.shared.b16 {%0,%1,%2,%3}, [%4];"
                 : "=r"(r[0]), "=r"(r[1]), "=r"(r[2]), "=r"(r[3]) : "r"(addr));
}

__device__ __forceinline__ void mma16816(float* c, const uint32_t* a,
                                         uint32_t b0, uint32_t b1) {
    asm volatile(
        "mma.sync.aligned.m16n8k16.row.col.f32.bf16.bf16.f32 "
        "{%0,%1,%2,%3}, {%4,%5,%6,%7}, {%8,%9}, {%0,%1,%2,%3};"
        : "+f"(c[0]), "+f"(c[1]), "+f"(c[2]), "+f"(c[3])
        : "r"(a[0]), "r"(a[1]), "r"(a[2]), "r"(a[3]), "r"(b0), "r"(b1));
}

__device__ __forceinline__ int batch_of(int n, int Bn) {
    int b = 0;
#pragma unroll
    for (int i = 1; i < MAXB; i++)
        if (i < Bn && n >= g_cum[i]) b = i;
    return b;
}

// ---------------- launch 1: fused prefix sums + B hi/lo transpose ----------------
__global__ void prep_all_kernel(const int* __restrict__ np, int Bn,
                                const float* __restrict__ kpw) {
    if (blockIdx.x == 0 && threadIdx.x == 0) {
        int c = 0;
        for (int b = 0; b < Bn && b < MAXB; b++) { g_cum[b] = c; c += np[b]; }
        for (int b = Bn; b < MAXB; b++) g_cum[b] = c;
        g_cum[MAXB] = c;
    }
    int i = blockIdx.x * blockDim.x + threadIdx.x;
    if (i >= KD * C_OUT) return;
    int kc = i >> 8;
    int d  = i & 255;
    float v = kpw[i];
    __nv_bfloat16 h = __float2bfloat16(v);
    float rem = v - __bfloat162float(h);
    g_Bhi[(size_t)d * KD + kc] = h;
    g_Blo[(size_t)d * KD + kc] = __float2bfloat16(rem);
}

// ---------------- launch 2: fused grid sample + kernel-point weights ----------------
__global__ void feats_allw_kernel(const float* __restrict__ x,
                                  const float* __restrict__ px,
                                  const float* __restrict__ py,
                                  const float* __restrict__ pxyz,
                                  const int* __restrict__ pknn,
                                  const float* __restrict__ kp,
                                  int N, int Bn) {
    __shared__ float skp[KPTS * 3];
    int bid = blockIdx.x;
    if (bid < N) {
        int n = bid;
        int c = threadIdx.x;
        int b = batch_of(n, Bn);

        float ix = fminf(fmaxf((px[n] + 1.0f) * (WW * 0.5f) - 0.5f, 0.0f), (float)(WW - 1));
        float iy = fminf(fmaxf((py[n] + 1.0f) * (HH * 0.5f) - 0.5f, 0.0f), (float)(HH - 1));
        float x0f = floorf(ix), y0f = floorf(iy);
        float wx = ix - x0f, wy = iy - y0f;
        int x0 = (int)x0f, y0 = (int)y0f;
        int x1 = min(x0 + 1, WW - 1);
        int y1 = min(y0 + 1, HH - 1);

        const float* base = x + ((size_t)b * C_IN + c) * (size_t)(HH * WW);
        float v00 = base[(size_t)y0 * WW + x0];
        float v01 = base[(size_t)y0 * WW + x1];
        float v10 = base[(size_t)y1 * WW + x0];
        float v11 = base[(size_t)y1 * WW + x1];

        float top = v00 + (v01 - v00) * wx;
        float bot = v10 + (v11 - v10) * wx;
        g_feats[(size_t)n * C_IN + c] = top + (bot - top) * wy;
    } else {
        if (threadIdx.x < KPTS * 3) skp[threadIdx.x] = kp[threadIdx.x];
        __syncthreads();

        int t = (bid - N) * 256 + threadIdx.x;
        int n = t / NNB;
        int a = t % NNB;
        if (n >= N) return;
        int b = batch_of(n, Bn);
        int j = pknn[(size_t)n * NNB + a] + g_cum[b];

        float cx = pxyz[(size_t)n * 3 + 0];
        float cy = pxyz[(size_t)n * 3 + 1];
        float cz = pxyz[(size_t)n * 3 + 2];
        float rx = pxyz[(size_t)j * 3 + 0] - cx;
        float ry = pxyz[(size_t)j * 3 + 1] - cy;
        float rz = pxyz[(size_t)j * 3 + 2] - cz;

#pragma unroll
        for (int k = 0; k < KPTS; k++) {
            float dx = rx - skp[k * 3 + 0];
            float dy = ry - skp[k * 3 + 1];
            float dz = rz - skp[k * 3 + 2];
            float dist = sqrtf(dx * dx + dy * dy + dz * dz);
            g_allw[((size_t)n * NNB + a) * KPTS + k] = fmaxf(1.0f - dist * (1.0f / KP_EXT), 0.0f);
        }
    }
}

// ---------------- launch 3: weighted -> bf16 hi/lo (float2, 128 thr/point) ----------------
__global__ void __launch_bounds__(128)
weighted_kernel(const int* __restrict__ pknn, int N, int Bn) {
    int n = blockIdx.x;
    int c2 = threadIdx.x;          // 0..127
    if (n >= N) return;

    __shared__ float sw[NNB * KPTS];
    __shared__ int sidx[NNB];
    if (c2 < NNB) {
        int b = batch_of(n, Bn);
        sidx[c2] = pknn[(size_t)n * NNB + c2] + g_cum[b];
    }
    for (int i = c2; i < NNB * KPTS; i += 128)
        sw[i] = g_allw[(size_t)n * NNB * KPTS + i];
    __syncthreads();

    float2 nx[NNB];
#pragma unroll
    for (int a = 0; a < NNB; a++)
        nx[a] = *(const float2*)(g_feats + (size_t)sidx[a] * C_IN + 2 * c2);

    __nv_bfloat162* Ahi2 = (__nv_bfloat162*)g_Ahi;
    __nv_bfloat162* Alo2 = (__nv_bfloat162*)g_Alo;
    size_t rowbase = ((size_t)n * KD) >> 1;

#pragma unroll
    for (int k = 0; k < KPTS; k++) {
        float acc0 = 0.0f, acc1 = 0.0f;
#pragma unroll
        for (int a = 0; a < NNB; a++) {
            float w = sw[a * KPTS + k];
            acc0 = fmaf(w, nx[a].x, acc0);
            acc1 = fmaf(w, nx[a].y, acc1);
        }
        __nv_bfloat16 h0 = __float2bfloat16(acc0);
        __nv_bfloat16 h1 = __float2bfloat16(acc1);
        float r0 = acc0 - __bfloat162float(h0);
        float r1 = acc1 - __bfloat162float(h1);
        size_t idx = rowbase + (size_t)k * 128 + c2;
        Ahi2[idx] = __nv_bfloat162(h0, h1);
        Alo2[idx] = __nv_bfloat162(__float2bfloat16(r0), __float2bfloat16(r1));
    }
}

// ---------------- launch 4: HMMA bf16 3-pass GEMM, 2 CTAs/SM, 1 sync/chunk ----------------
// C[m, d] = sum_kc A[m,kc] * B[d,kc]
// CTA: 128(M) x 64(N), 256 threads = 8 warps = 4(M) x 2(N), warp tile 32 x 32
// Single-sync multistage: {wait0; sync; issue(ch+1 -> buf^1); compute(ch, buf)}
// Epilogue also reduces this CTA's output tile into BN partial sums (fused colstats).
#define GM 128
#define GN 64
#define KCHUNK 64
#define NCHUNKS (KD / KCHUNK)           // 60
#define OFF_AH 0                        // 128 rows x 128B = 16 KB
#define OFF_AL 16384
#define OFF_BH 32768                    // 64 rows x 128B = 8 KB
#define OFF_BL 40960
#define STAGE_BYTES 49152               // 48 KB
#define NSTAGE 2
#define GEMM_SMEM (NSTAGE * STAGE_BYTES + 1024)
#define GEMM_THREADS 256

extern __shared__ char gemm_smem[];

__device__ __forceinline__ void issue_chunk(uint32_t stage_u32, int mBase, int nBase,
                                            int k0, int M, int tid) {
    int r_lo = tid >> 3;        // 0..31
    int i    = tid & 7;         // 16B granule within 128B row
    const __nv_bfloat16* __restrict__ Ah = g_Ahi;
    const __nv_bfloat16* __restrict__ Al = g_Alo;
    const __nv_bfloat16* __restrict__ Bh = g_Bhi;
    const __nv_bfloat16* __restrict__ Bl = g_Blo;
#pragma unroll
    for (int p = 0; p < 12; p++) {
        uint32_t dst;
        const __nv_bfloat16* src;
        if (p < 4) {                       // Ah rows 0..127
            int row = p * 32 + r_lo;
            uint32_t off = (uint32_t)(row * 128 + i * 16);
            uint32_t sw = off ^ ((off >> 3) & 0x70);
            int gr = min(mBase + row, M - 1);
            dst = stage_u32 + OFF_AH + sw;
            src = Ah + (size_t)gr * KD + k0 + i * 8;
        } else if (p < 8) {                // Al
            int row = (p - 4) * 32 + r_lo;
            uint32_t off = (uint32_t)(row * 128 + i * 16);
            uint32_t sw = off ^ ((off >> 3) & 0x70);
            int gr = min(mBase + row, M - 1);
            dst = stage_u32 + OFF_AL + sw;
            src = Al + (size_t)gr * KD + k0 + i * 8;
        } else if (p < 10) {               // Bh rows 0..63
            int row = (p - 8) * 32 + r_lo;
            uint32_t off = (uint32_t)(row * 128 + i * 16);
            uint32_t sw = off ^ ((off >> 3) & 0x70);
            dst = stage_u32 + OFF_BH + sw;
            src = Bh + (size_t)(nBase + row) * KD + k0 + i * 8;
        } else {                           // Bl
            int row = (p - 10) * 32 + r_lo;
            uint32_t off = (uint32_t)(row * 128 + i * 16);
            uint32_t sw = off ^ ((off >> 3) & 0x70);
            dst = stage_u32 + OFF_BL + sw;
            src = Bl + (size_t)(nBase + row) * KD + k0 + i * 8;
        }
        CP_ASYNC16(dst, src);
    }
}

__global__ void __launch_bounds__(GEMM_THREADS, 2) gemm_mma_kernel(float* __restrict__ C, int M) {
    int tid = threadIdx.x;
    int wid = tid >> 5;
    int lane = tid & 31;
    int wm = wid & 3;          // 0..3  (32 rows each)
    int wn = wid >> 2;         // 0..1  (32 cols each)
    int mBase = blockIdx.y * GM;
    int nBase = blockIdx.x * GN;

    uint32_t dyn_u32 = smem_u32(gemm_smem);
    uint32_t base_u32 = (dyn_u32 + 1023u) & ~1023u;

    float acc[2][4][4];
#pragma unroll
    for (int a = 0; a < 2; a++)
#pragma unroll
        for (int b = 0; b < 4; b++)
#pragma unroll
            for (int c = 0; c < 4; c++) acc[a][b][c] = 0.0f;

    int lrow = lane & 15;
    int csel = (lane >> 4) * 16;
    int aRow = wm * 32 + lrow;
    int bRow = wn * 32 + lrow;
    uint32_t xa = (uint32_t)((aRow & 7) << 4);
    uint32_t xb = (uint32_t)((bRow & 7) << 4);

    // prologue
    issue_chunk(base_u32, mBase, nBase, 0, M, tid);
    CP_COMMIT();

    for (int ch = 0; ch < NCHUNKS; ch++) {
        int buf = ch & 1;
        uint32_t stg = base_u32 + buf * STAGE_BYTES;

        CP_WAIT0();            // copy of chunk ch complete
        __syncthreads();       // everyone done reading buf^1 (iter ch-1)

        if (ch + 1 < NCHUNKS) {
            issue_chunk(base_u32 + (buf ^ 1) * STAGE_BYTES,
                        mBase, nBase, (ch + 1) * KCHUNK, M, tid);
            CP_COMMIT();       // overlaps the compute below
        }

        uint32_t aBase = stg + (uint32_t)(aRow * 128);
        uint32_t bBase = stg + (uint32_t)(bRow * 128);

#pragma unroll
        for (int ks = 0; ks < 4; ks++) {
            uint32_t colA = ((uint32_t)(ks * 32 + csel)) ^ xa;
            uint32_t colB = ((uint32_t)(ks * 32 + csel)) ^ xb;

            uint32_t bh[2][4], bl[2][4];
#pragma unroll
            for (int g = 0; g < 2; g++) {
                uint32_t addr = bBase + (uint32_t)(g * 16 * 128) + colB;
                ldsm4(bh[g], addr + OFF_BH);
                ldsm4(bl[g], addr + OFF_BL);
            }
#pragma unroll
            for (int mt = 0; mt < 2; mt++) {
                uint32_t addr = aBase + (uint32_t)(mt * 16 * 128) + colA;
                uint32_t ah[4], al[4];
                ldsm4(ah, addr + OFF_AH);
                ldsm4(al, addr + OFF_AL);
#pragma unroll
                for (int nt = 0; nt < 4; nt++) {
                    int g = nt >> 1, h = nt & 1;
                    mma16816(acc[mt][nt], ah, bh[g][h], bh[g][h + 2]);
                    mma16816(acc[mt][nt], ah, bl[g][h], bl[g][h + 2]);
                    mma16816(acc[mt][nt], al, bh[g][h], bh[g][h + 2]);
                }
            }
        }
    }

    // ---- store C tile (m16n8 accumulator mapping) ----
    int rBase = mBase + wm * 32 + (lane >> 2);
    int cBase = nBase + wn * 32 + (lane & 3) * 2;
#pragma unroll
    for (int mt = 0; mt < 2; mt++) {
#pragma unroll
        for (int nt = 0; nt < 4; nt++) {
            int r0 = rBase + mt * 16;
            int cc = cBase + nt * 8;
            if (r0 < M)
                *(float2*)(C + (size_t)r0 * C_OUT + cc) =
                    make_float2(acc[mt][nt][0], acc[mt][nt][1]);
            if (r0 + 8 < M)
                *(float2*)(C + (size_t)(r0 + 8) * C_OUT + cc) =
                    make_float2(acc[mt][nt][2], acc[mt][nt][3]);
        }
    }

    // ---- fused BN partial stats: per-CTA column sum / sumsq over valid rows ----
    __syncthreads();                       // pipeline smem no longer needed
    float* sred = (float*)gemm_smem;       // [4 wm][64 cols] sums, then sqs (512 floats)

#pragma unroll
    for (int nt = 0; nt < 4; nt++) {
        float s0 = 0.f, s1 = 0.f, q0 = 0.f, q1 = 0.f;
#pragma unroll
        for (int mt = 0; mt < 2; mt++) {
            int ra = rBase + mt * 16;
            int rb = ra + 8;
            if (ra < M) {
                float v0 = acc[mt][nt][0], v1 = acc[mt][nt][1];
                s0 += v0; s1 += v1; q0 += v0 * v0; q1 += v1 * v1;
            }
            if (rb < M) {
                float v2 = acc[mt][nt][2], v3 = acc[mt][nt][3];
                s0 += v2; s1 += v3; q0 += v2 * v2; q1 += v3 * v3;
            }
        }
        // reduce across the 8 row-groups (lanes with same lane&3)
#pragma unroll
        for (int off = 16; off >= 4; off >>= 1) {
            s0 += __shfl_down_sync(0xffffffffu, s0, off);
            s1 += __shfl_down_sync(0xffffffffu, s1, off);
            q0 += __shfl_down_sync(0xffffffffu, q0, off);
            q1 += __shfl_down_sync(0xffffffffu, q1, off);
        }
        if (lane < 4) {
            int colL = wn * 32 + nt * 8 + lane * 2;   // 0..63
            sred[wm * 64 + colL]       = s0;
            sred[wm * 64 + colL + 1]   = s1;
            sred[256 + wm * 64 + colL]     = q0;
            sred[256 + wm * 64 + colL + 1] = q1;
        }
    }
    __syncthreads();

    if (tid < 64) {
        float s = sred[tid] + sred[64 + tid] + sred[128 + tid] + sred[192 + tid];
        g_psum[(size_t)blockIdx.y * C_OUT + blockIdx.x * GN + tid] = s;
    } else if (tid < 128) {
        int t = tid - 64;
        float s = sred[256 + t] + sred[320 + t] + sred[384 + t] + sred[448 + t];
        g_psq[(size_t)blockIdx.y * C_OUT + blockIdx.x * GN + t] = s;
    }
}

// ---------------- launch 5: finalize BN stats ----------------
__global__ void colstats_final(const float* __restrict__ gamma,
                               const float* __restrict__ beta,
                               int N, int nMtiles) {
    int d = threadIdx.x;
    float s = 0.f, ss = 0.f;
    for (int i = 0; i < nMtiles; i++) {
        s += g_psum[(size_t)i * C_OUT + d];
        ss += g_psq[(size_t)i * C_OUT + d];
    }
    float invN = 1.0f / (float)N;
    float mean = s * invN;
    float var = ss * invN - mean * mean;
    float sc = rsqrtf(var + BN_EPS) * gamma[d];
    g_scale[d] = sc;
    g_bias[d] = beta[d] - mean * sc;
}

// ---------------- launch 6: BN + ReLU ----------------
__global__ void bn_relu_kernel(float* __restrict__ out, size_t total) {
    for (size_t i = (size_t)blockIdx.x * blockDim.x + threadIdx.x; i < total;
         i += (size_t)gridDim.x * blockDim.x) {
        int d = (int)(i & (C_OUT - 1));
        float v = fmaf(out[i], g_scale[d], g_bias[d]);
        out[i] = v > 0.0f ? v : 0.0f;
    }
}

// ---------------- launch ----------------
extern "C" void kernel_launch(void* const* d_in, const int* in_sizes, int n_in,
                              void* d_out, int out_size) {
    const float* x     = (const float*)d_in[0];
    const float* px    = (const float*)d_in[1];
    const float* py    = (const float*)d_in[2];
    const float* pxyz  = (const float*)d_in[3];
    const int*   pknn  = (const int*)d_in[4];
    const int*   np    = (const int*)d_in[5];
    const float* kp    = (const float*)d_in[6];
    const float* kpw   = (const float*)d_in[7];
    const float* gamma = (const float*)d_in[8];
    const float* beta  = (const float*)d_in[9];
    float* out = (float*)d_out;

    int N  = in_sizes[1];
    int Bn = in_sizes[5];

    cudaFuncSetAttribute(gemm_mma_kernel,
                         cudaFuncAttributeMaxDynamicSharedMemorySize, GEMM_SMEM);

    // launch 1: prefix sums + B transpose
    prep_all_kernel<<<(KD * C_OUT + 255) / 256, 256>>>(np, Bn, kpw);

    // launch 2: fused feats + allw
    int allw_blocks = (N * NNB + 255) / 256;
    feats_allw_kernel<<<N + allw_blocks, 256>>>(x, px, py, pxyz, pknn, kp, N, Bn);

    // launch 3: weighted (float2, 128 threads per point)
    weighted_kernel<<<N, 128>>>(pknn, N, Bn);

    // launch 4: GEMM + fused BN partial stats (profiled slot)
    int nMtiles = (N + GM - 1) / GM;
    dim3 ggrid(C_OUT / GN, nMtiles);
    gemm_mma_kernel<<<ggrid, GEMM_THREADS, GEMM_SMEM>>>(out, N);

    // launch 5: finalize stats
    colstats_final<<<1, C_OUT>>>(gamma, beta, N, nMtiles);

    // launch 6: BN + ReLU
    size_t total = (size_t)N * C_OUT;
    bn_relu_kernel<<<2048, 256>>>(out, total);
}

// round 12
// speedup vs baseline: 1.7284x; 1.3231x over previous
#include <cuda_runtime.h>
#include <cuda_fp16.h>
#include <cstdint>
#include <cstddef>

// Problem constants
#define C_IN   256
#define C_OUT  256
#define KPTS   15
#define NNB    16
#define HH     64
#define WW     2048
#define KP_EXT 1.2f
#define BN_EPS 1e-5f
#define MAXB   8
#define MAXN   40000
#define KD     (KPTS * C_IN)        // 3840
#define MAXMT  320                  // max M-tiles (40000/128 = 313)

// ---------------- scratch (device globals) ----------------
__device__ int   g_cum[MAXB + 1];
__device__ float g_feats[(size_t)MAXN * C_IN];
__device__ float g_allw[(size_t)MAXN * NNB * KPTS];
__device__ __half g_Ahi[(size_t)MAXN * KD];     // 307 MB (fp16 hi)
__device__ __half g_Alo[(size_t)MAXN * KD];     // 307 MB (fp16 residual)
__device__ __half g_Bhi[(size_t)C_OUT * KD];    // 1.9 MB, K-major [d][kc], fp16
__device__ float g_psum[MAXMT * C_OUT];
__device__ float g_psq[MAXMT * C_OUT];
__device__ float g_scale[C_OUT];
__device__ float g_bias[C_OUT];

// ---------------- PTX helpers (base sm_103-legal only) ----------------
__device__ __forceinline__ uint32_t smem_u32(const void* p) {
    uint32_t a;
    asm("{ .reg .u64 t; cvta.to.shared.u64 t, %1; cvt.u32.u64 %0, t; }" : "=r"(a) : "l"(p));
    return a;
}

#define CP_ASYNC16(dst_u32, src_ptr) \
    asm volatile("cp.async.cg.shared.global [%0], [%1], 16;" \
                 :: "r"(dst_u32), "l"(src_ptr) : "memory")
#define CP_COMMIT() asm volatile("cp.async.commit_group;" ::: "memory")
#define CP_WAIT1()  asm volatile("cp.async.wait_group 1;" ::: "memory")
#define CP_WAIT0()  asm volatile("cp.async.wait_group 0;" ::: "memory")

__device__ __forceinline__ void ldsm4(uint32_t* r, uint32_t addr) {
    asm volatile("ldmatrix.sync.aligned.m8n8.x4.shared.b16 {%0,%1,%2,%3}, [%4];"
                 : "=r"(r[0]), "=r"(r[1]), "=r"(r[2]), "=r"(r[3]) : "r"(addr));
}

__device__ __forceinline__ void mma16816(float* c, const uint32_t* a,
                                         uint32_t b0, uint32_t b1) {
    asm volatile(
        "mma.sync.aligned.m16n8k16.row.col.f32.f16.f16.f32 "
        "{%0,%1,%2,%3}, {%4,%5,%6,%7}, {%8,%9}, {%0,%1,%2,%3};"
        : "+f"(c[0]), "+f"(c[1]), "+f"(c[2]), "+f"(c[3])
        : "r"(a[0]), "r"(a[1]), "r"(a[2]), "r"(a[3]), "r"(b0), "r"(b1));
}

__device__ __forceinline__ int batch_of(int n, int Bn) {
    int b = 0;
#pragma unroll
    for (int i = 1; i < MAXB; i++)
        if (i < Bn && n >= g_cum[i]) b = i;
    return b;
}

// ---------------- launch 1: fused prefix sums + B fp16 transpose ----------------
__global__ void prep_all_kernel(const int* __restrict__ np, int Bn,
                                const float* __restrict__ kpw) {
    if (blockIdx.x == 0 && threadIdx.x == 0) {
        int c = 0;
        for (int b = 0; b < Bn && b < MAXB; b++) { g_cum[b] = c; c += np[b]; }
        for (int b = Bn; b < MAXB; b++) g_cum[b] = c;
        g_cum[MAXB] = c;
    }
    int i = blockIdx.x * blockDim.x + threadIdx.x;
    if (i >= KD * C_OUT) return;
    int kc = i >> 8;
    int d  = i & 255;
    g_Bhi[(size_t)d * KD + kc] = __float2half_rn(kpw[i]);
}

// ---------------- launch 2: fused grid sample + kernel-point weights ----------------
__global__ void feats_allw_kernel(const float* __restrict__ x,
                                  const float* __restrict__ px,
                                  const float* __restrict__ py,
                                  const float* __restrict__ pxyz,
                                  const int* __restrict__ pknn,
                                  const float* __restrict__ kp,
                                  int N, int Bn) {
    __shared__ float skp[KPTS * 3];
    int bid = blockIdx.x;
    if (bid < N) {
        int n = bid;
        int c = threadIdx.x;
        int b = batch_of(n, Bn);

        float ix = fminf(fmaxf((px[n] + 1.0f) * (WW * 0.5f) - 0.5f, 0.0f), (float)(WW - 1));
        float iy = fminf(fmaxf((py[n] + 1.0f) * (HH * 0.5f) - 0.5f, 0.0f), (float)(HH - 1));
        float x0f = floorf(ix), y0f = floorf(iy);
        float wx = ix - x0f, wy = iy - y0f;
        int x0 = (int)x0f, y0 = (int)y0f;
        int x1 = min(x0 + 1, WW - 1);
        int y1 = min(y0 + 1, HH - 1);

        const float* base = x + ((size_t)b * C_IN + c) * (size_t)(HH * WW);
        float v00 = base[(size_t)y0 * WW + x0];
        float v01 = base[(size_t)y0 * WW + x1];
        float v10 = base[(size_t)y1 * WW + x0];
        float v11 = base[(size_t)y1 * WW + x1];

        float top = v00 + (v01 - v00) * wx;
        float bot = v10 + (v11 - v10) * wx;
        g_feats[(size_t)n * C_IN + c] = top + (bot - top) * wy;
    } else {
        if (threadIdx.x < KPTS * 3) skp[threadIdx.x] = kp[threadIdx.x];
        __syncthreads();

        int t = (bid - N) * 256 + threadIdx.x;
        int n = t / NNB;
        int a = t % NNB;
        if (n >= N) return;
        int b = batch_of(n, Bn);
        int j = pknn[(size_t)n * NNB + a] + g_cum[b];

        float cx = pxyz[(size_t)n * 3 + 0];
        float cy = pxyz[(size_t)n * 3 + 1];
        float cz = pxyz[(size_t)n * 3 + 2];
        float rx = pxyz[(size_t)j * 3 + 0] - cx;
        float ry = pxyz[(size_t)j * 3 + 1] - cy;
        float rz = pxyz[(size_t)j * 3 + 2] - cz;

#pragma unroll
        for (int k = 0; k < KPTS; k++) {
            float dx = rx - skp[k * 3 + 0];
            float dy = ry - skp[k * 3 + 1];
            float dz = rz - skp[k * 3 + 2];
            float dist = sqrtf(dx * dx + dy * dy + dz * dz);
            g_allw[((size_t)n * NNB + a) * KPTS + k] = fmaxf(1.0f - dist * (1.0f / KP_EXT), 0.0f);
        }
    }
}

// ---------------- launch 3: weighted -> fp16 hi/lo (float2, 128 thr/point) ----------------
__global__ void __launch_bounds__(128)
weighted_kernel(const int* __restrict__ pknn, int N, int Bn) {
    int n = blockIdx.x;
    int c2 = threadIdx.x;          // 0..127
    if (n >= N) return;

    __shared__ float sw[NNB * KPTS];
    __shared__ int sidx[NNB];
    if (c2 < NNB) {
        int b = batch_of(n, Bn);
        sidx[c2] = pknn[(size_t)n * NNB + c2] + g_cum[b];
    }
    for (int i = c2; i < NNB * KPTS; i += 128)
        sw[i] = g_allw[(size_t)n * NNB * KPTS + i];
    __syncthreads();

    float2 nx[NNB];
#pragma unroll
    for (int a = 0; a < NNB; a++)
        nx[a] = *(const float2*)(g_feats + (size_t)sidx[a] * C_IN + 2 * c2);

    __half2* Ahi2 = (__half2*)g_Ahi;
    __half2* Alo2 = (__half2*)g_Alo;
    size_t rowbase = ((size_t)n * KD) >> 1;

#pragma unroll
    for (int k = 0; k < KPTS; k++) {
        float acc0 = 0.0f, acc1 = 0.0f;
#pragma unroll
        for (int a = 0; a < NNB; a++) {
            float w = sw[a * KPTS + k];
            acc0 = fmaf(w, nx[a].x, acc0);
            acc1 = fmaf(w, nx[a].y, acc1);
        }
        __half h0 = __float2half_rn(acc0);
        __half h1 = __float2half_rn(acc1);
        float r0 = acc0 - __half2float(h0);
        float r1 = acc1 - __half2float(h1);
        size_t idx = rowbase + (size_t)k * 128 + c2;
        Ahi2[idx] = __halves2half2(h0, h1);
        Alo2[idx] = __halves2half2(__float2half_rn(r0), __float2half_rn(r1));
    }
}

// ---------------- launch 4: HMMA fp16 2-pass GEMM, 2 CTAs/SM ----------------
// C[m, d] = sum_kc (Ah+Al)[m,kc] * B[d,kc],  B single fp16 (11-bit mantissa)
// CTA: 128(M) x 64(N), 256 threads = 8 warps = 4(M) x 2(N), warp tile 32 x 32
// 2-stage double buffer (40 KB/stage) -> 2 CTAs/SM; R10-proven 2-sync mainloop.
#define GM 128
#define GN 64
#define KCHUNK 64
#define NCHUNKS (KD / KCHUNK)           // 60
#define OFF_AH 0                        // 128 rows x 128B = 16 KB
#define OFF_AL 16384
#define OFF_BH 32768                    // 64 rows x 128B = 8 KB
#define STAGE_BYTES 40960               // 40 KB
#define NSTAGE 2
#define GEMM_SMEM (NSTAGE * STAGE_BYTES + 1024)
#define GEMM_THREADS 256

extern __shared__ char gemm_smem[];

__device__ __forceinline__ void issue_chunk(uint32_t stage_u32, int mBase, int nBase,
                                            int k0, int M, int tid) {
    int r_lo = tid >> 3;        // 0..31
    int i    = tid & 7;         // 16B granule within 128B row
    const __half* __restrict__ Ah = g_Ahi;
    const __half* __restrict__ Al = g_Alo;
    const __half* __restrict__ Bh = g_Bhi;
#pragma unroll
    for (int p = 0; p < 10; p++) {
        uint32_t dst;
        const __half* src;
        if (p < 4) {                       // Ah rows 0..127
            int row = p * 32 + r_lo;
            uint32_t off = (uint32_t)(row * 128 + i * 16);
            uint32_t sw = off ^ ((off >> 3) & 0x70);
            int gr = min(mBase + row, M - 1);
            dst = stage_u32 + OFF_AH + sw;
            src = Ah + (size_t)gr * KD + k0 + i * 8;
        } else if (p < 8) {                // Al
            int row = (p - 4) * 32 + r_lo;
            uint32_t off = (uint32_t)(row * 128 + i * 16);
            uint32_t sw = off ^ ((off >> 3) & 0x70);
            int gr = min(mBase + row, M - 1);
            dst = stage_u32 + OFF_AL + sw;
            src = Al + (size_t)gr * KD + k0 + i * 8;
        } else {                           // Bh rows 0..63
            int row = (p - 8) * 32 + r_lo;
            uint32_t off = (uint32_t)(row * 128 + i * 16);
            uint32_t sw = off ^ ((off >> 3) & 0x70);
            dst = stage_u32 + OFF_BH + sw;
            src = Bh + (size_t)(nBase + row) * KD + k0 + i * 8;
        }
        CP_ASYNC16(dst, src);
    }
}

__global__ void __launch_bounds__(GEMM_THREADS, 2) gemm_mma_kernel(float* __restrict__ C, int M) {
    int tid = threadIdx.x;
    int wid = tid >> 5;
    int lane = tid & 31;
    int wm = wid & 3;          // 0..3  (32 rows each)
    int wn = wid >> 2;         // 0..1  (32 cols each)
    int mBase = blockIdx.y * GM;
    int nBase = blockIdx.x * GN;

    uint32_t dyn_u32 = smem_u32(gemm_smem);
    uint32_t base_u32 = (dyn_u32 + 1023u) & ~1023u;

    float acc[2][4][4];
#pragma unroll
    for (int a = 0; a < 2; a++)
#pragma unroll
        for (int b = 0; b < 4; b++)
#pragma unroll
            for (int c = 0; c < 4; c++) acc[a][b][c] = 0.0f;

    int lrow = lane & 15;
    int csel = (lane >> 4) * 16;
    int aRow = wm * 32 + lrow;
    int bRow = wn * 32 + lrow;
    uint32_t xa = (uint32_t)((aRow & 7) << 4);
    uint32_t xb = (uint32_t)((bRow & 7) << 4);

    // prologue
    issue_chunk(base_u32, mBase, nBase, 0, M, tid);
    CP_COMMIT();

    for (int ch = 0; ch < NCHUNKS; ch++) {
        int buf = ch & 1;
        uint32_t stg = base_u32 + buf * STAGE_BYTES;

        if (ch + 1 < NCHUNKS) {
            issue_chunk(base_u32 + (buf ^ 1) * STAGE_BYTES,
                        mBase, nBase, (ch + 1) * KCHUNK, M, tid);
            CP_COMMIT();
            CP_WAIT1();       // chunk ch complete; ch+1 may be in flight
        } else {
            CP_WAIT0();
        }
        __syncthreads();

        uint32_t aBase = stg + (uint32_t)(aRow * 128);
        uint32_t bBase = stg + (uint32_t)(bRow * 128);

#pragma unroll
        for (int ks = 0; ks < 4; ks++) {
            uint32_t colA = ((uint32_t)(ks * 32 + csel)) ^ xa;
            uint32_t colB = ((uint32_t)(ks * 32 + csel)) ^ xb;

            uint32_t bh[2][4];
#pragma unroll
            for (int g = 0; g < 2; g++) {
                uint32_t addr = bBase + (uint32_t)(g * 16 * 128) + colB;
                ldsm4(bh[g], addr + OFF_BH);
            }
#pragma unroll
            for (int mt = 0; mt < 2; mt++) {
                uint32_t addr = aBase + (uint32_t)(mt * 16 * 128) + colA;
                uint32_t ah[4], al[4];
                ldsm4(ah, addr + OFF_AH);
                ldsm4(al, addr + OFF_AL);
#pragma unroll
                for (int nt = 0; nt < 4; nt++) {
                    int g = nt >> 1, h = nt & 1;
                    mma16816(acc[mt][nt], ah, bh[g][h], bh[g][h + 2]);
                    mma16816(acc[mt][nt], al, bh[g][h], bh[g][h + 2]);
                }
            }
        }
        __syncthreads();   // buffer free before next overwrite
    }

    // ---- store C tile (m16n8 accumulator mapping) ----
    int rBase = mBase + wm * 32 + (lane >> 2);
    int cBase = nBase + wn * 32 + (lane & 3) * 2;
#pragma unroll
    for (int mt = 0; mt < 2; mt++) {
#pragma unroll
        for (int nt = 0; nt < 4; nt++) {
            int r0 = rBase + mt * 16;
            int cc = cBase + nt * 8;
            if (r0 < M)
                *(float2*)(C + (size_t)r0 * C_OUT + cc) =
                    make_float2(acc[mt][nt][0], acc[mt][nt][1]);
            if (r0 + 8 < M)
                *(float2*)(C + (size_t)(r0 + 8) * C_OUT + cc) =
                    make_float2(acc[mt][nt][2], acc[mt][nt][3]);
        }
    }

    // ---- fused BN partial stats: per-CTA column sum / sumsq over valid rows ----
    __syncthreads();                       // pipeline smem no longer needed
    float* sred = (float*)gemm_smem;       // [4 wm][64 cols] sums, then sqs (512 floats)

#pragma unroll
    for (int nt = 0; nt < 4; nt++) {
        float s0 = 0.f, s1 = 0.f, q0 = 0.f, q1 = 0.f;
#pragma unroll
        for (int mt = 0; mt < 2; mt++) {
            int ra = rBase + mt * 16;
            int rb = ra + 8;
            if (ra < M) {
                float v0 = acc[mt][nt][0], v1 = acc[mt][nt][1];
                s0 += v0; s1 += v1; q0 += v0 * v0; q1 += v1 * v1;
            }
            if (rb < M) {
                float v2 = acc[mt][nt][2], v3 = acc[mt][nt][3];
                s0 += v2; s1 += v3; q0 += v2 * v2; q1 += v3 * v3;
            }
        }
#pragma unroll
        for (int off = 16; off >= 4; off >>= 1) {
            s0 += __shfl_down_sync(0xffffffffu, s0, off);
            s1 += __shfl_down_sync(0xffffffffu, s1, off);
            q0 += __shfl_down_sync(0xffffffffu, q0, off);
            q1 += __shfl_down_sync(0xffffffffu, q1, off);
        }
        if (lane < 4) {
            int colL = wn * 32 + nt * 8 + lane * 2;   // 0..63
            sred[wm * 64 + colL]       = s0;
            sred[wm * 64 + colL + 1]   = s1;
            sred[256 + wm * 64 + colL]     = q0;
            sred[256 + wm * 64 + colL + 1] = q1;
        }
    }
    __syncthreads();

    if (tid < 64) {
        float s = sred[tid] + sred[64 + tid] + sred[128 + tid] + sred[192 + tid];
        g_psum[(size_t)blockIdx.y * C_OUT + blockIdx.x * GN + tid] = s;
    } else if (tid < 128) {
        int t = tid - 64;
        float s = sred[256 + t] + sred[320 + t] + sred[384 + t] + sred[448 + t];
        g_psq[(size_t)blockIdx.y * C_OUT + blockIdx.x * GN + t] = s;
    }
}

// ---------------- launch 5: finalize BN stats ----------------
__global__ void colstats_final(const float* __restrict__ gamma,
                               const float* __restrict__ beta,
                               int N, int nMtiles) {
    int d = threadIdx.x;
    float s = 0.f, ss = 0.f;
    for (int i = 0; i < nMtiles; i++) {
        s += g_psum[(size_t)i * C_OUT + d];
        ss += g_psq[(size_t)i * C_OUT + d];
    }
    float invN = 1.0f / (float)N;
    float mean = s * invN;
    float var = ss * invN - mean * mean;
    float sc = rsqrtf(var + BN_EPS) * gamma[d];
    g_scale[d] = sc;
    g_bias[d] = beta[d] - mean * sc;
}

// ---------------- launch 6: BN + ReLU ----------------
__global__ void bn_relu_kernel(float* __restrict__ out, size_t total) {
    for (size_t i = (size_t)blockIdx.x * blockDim.x + threadIdx.x; i < total;
         i += (size_t)gridDim.x * blockDim.x) {
        int d = (int)(i & (C_OUT - 1));
        float v = fmaf(out[i], g_scale[d], g_bias[d]);
        out[i] = v > 0.0f ? v : 0.0f;
    }
}

// ---------------- launch ----------------
extern "C" void kernel_launch(void* const* d_in, const int* in_sizes, int n_in,
                              void* d_out, int out_size) {
    const float* x     = (const float*)d_in[0];
    const float* px    = (const float*)d_in[1];
    const float* py    = (const float*)d_in[2];
    const float* pxyz  = (const float*)d_in[3];
    const int*   pknn  = (const int*)d_in[4];
    const int*   np    = (const int*)d_in[5];
    const float* kp    = (const float*)d_in[6];
    const float* kpw   = (const float*)d_in[7];
    const float* gamma = (const float*)d_in[8];
    const float* beta  = (const float*)d_in[9];
    float* out = (float*)d_out;

    int N  = in_sizes[1];
    int Bn = in_sizes[5];

    cudaFuncSetAttribute(gemm_mma_kernel,
                         cudaFuncAttributeMaxDynamicSharedMemorySize, GEMM_SMEM);

    // launch 1: prefix sums + B fp16 transpose
    prep_all_kernel<<<(KD * C_OUT + 255) / 256, 256>>>(np, Bn, kpw);

    // launch 2: fused feats + allw
    int allw_blocks = (N * NNB + 255) / 256;
    feats_allw_kernel<<<N + allw_blocks, 256>>>(x, px, py, pxyz, pknn, kp, N, Bn);

    // launch 3: weighted (float2, 128 threads per point)
    weighted_kernel<<<N, 128>>>(pknn, N, Bn);

    // launch 4: GEMM + fused BN partial stats (profiled slot)
    int nMtiles = (N + GM - 1) / GM;
    dim3 ggrid(C_OUT / GN, nMtiles);
    gemm_mma_kernel<<<ggrid, GEMM_THREADS, GEMM_SMEM>>>(out, N);

    // launch 5: finalize stats
    colstats_final<<<1, C_OUT>>>(gamma, beta, N, nMtiles);

    // launch 6: BN + ReLU
    size_t total = (size_t)N * C_OUT;
    bn_relu_kernel<<<2048, 256>>>(out, total);
}

// round 13
// speedup vs baseline: 1.9995x; 1.1569x over previous
#include <cuda_runtime.h>
#include <cuda_fp16.h>
#include <cstdint>
#include <cstddef>

// Problem constants
#define C_IN   256
#define C_OUT  256
#define KPTS   15
#define NNB    16
#define HH     64
#define WW     2048
#define KP_EXT 1.2f
#define BN_EPS 1e-5f
#define MAXB   8
#define MAXN   40000
#define KD     (KPTS * C_IN)        // 3840
#define MAXMT  320                  // max M-tiles (40000/128 = 313)

// ---------------- scratch (device globals) ----------------
__device__ int   g_cum[MAXB + 1];
__device__ float g_feats[(size_t)MAXN * C_IN];
__device__ float g_allw[(size_t)MAXN * NNB * KPTS];
__device__ __half g_Ah[(size_t)MAXN * KD];      // 307 MB (fp16 A)
__device__ __half g_Bh[(size_t)C_OUT * KD];     // 1.9 MB, K-major [d][kc], fp16
__device__ float g_psum[MAXMT * C_OUT];
__device__ float g_psq[MAXMT * C_OUT];
__device__ float g_scale[C_OUT];
__device__ float g_bias[C_OUT];

// ---------------- PTX helpers (base sm_103-legal only) ----------------
__device__ __forceinline__ uint32_t smem_u32(const void* p) {
    uint32_t a;
    asm("{ .reg .u64 t; cvta.to.shared.u64 t, %1; cvt.u32.u64 %0, t; }" : "=r"(a) : "l"(p));
    return a;
}

#define CP_ASYNC16(dst_u32, src_ptr) \
    asm volatile("cp.async.cg.shared.global [%0], [%1], 16;" \
                 :: "r"(dst_u32), "l"(src_ptr) : "memory")
#define CP_COMMIT() asm volatile("cp.async.commit_group;" ::: "memory")
#define CP_WAIT1()  asm volatile("cp.async.wait_group 1;" ::: "memory")
#define CP_WAIT0()  asm volatile("cp.async.wait_group 0;" ::: "memory")

__device__ __forceinline__ void ldsm4(uint32_t* r, uint32_t addr) {
    asm volatile("ldmatrix.sync.aligned.m8n8.x4.shared.b16 {%0,%1,%2,%3}, [%4];"
                 : "=r"(r[0]), "=r"(r[1]), "=r"(r[2]), "=r"(r[3]) : "r"(addr));
}

__device__ __forceinline__ void mma16816(float* c, const uint32_t* a,
                                         uint32_t b0, uint32_t b1) {
    asm volatile(
        "mma.sync.aligned.m16n8k16.row.col.f32.f16.f16.f32 "
        "{%0,%1,%2,%3}, {%4,%5,%6,%7}, {%8,%9}, {%0,%1,%2,%3};"
        : "+f"(c[0]), "+f"(c[1]), "+f"(c[2]), "+f"(c[3])
        : "r"(a[0]), "r"(a[1]), "r"(a[2]), "r"(a[3]), "r"(b0), "r"(b1));
}

__device__ __forceinline__ int batch_of(int n, int Bn) {
    int b = 0;
#pragma unroll
    for (int i = 1; i < MAXB; i++)
        if (i < Bn && n >= g_cum[i]) b = i;
    return b;
}

// ---------------- launch 1: fused prefix sums + B fp16 transpose ----------------
__global__ void prep_all_kernel(const int* __restrict__ np, int Bn,
                                const float* __restrict__ kpw) {
    if (blockIdx.x == 0 && threadIdx.x == 0) {
        int c = 0;
        for (int b = 0; b < Bn && b < MAXB; b++) { g_cum[b] = c; c += np[b]; }
        for (int b = Bn; b < MAXB; b++) g_cum[b] = c;
        g_cum[MAXB] = c;
    }
    int i = blockIdx.x * blockDim.x + threadIdx.x;
    if (i >= KD * C_OUT) return;
    int kc = i >> 8;
    int d  = i & 255;
    g_Bh[(size_t)d * KD + kc] = __float2half_rn(kpw[i]);
}

// ---------------- launch 2: fused grid sample + kernel-point weights ----------------
__global__ void feats_allw_kernel(const float* __restrict__ x,
                                  const float* __restrict__ px,
                                  const float* __restrict__ py,
                                  const float* __restrict__ pxyz,
                                  const int* __restrict__ pknn,
                                  const float* __restrict__ kp,
                                  int N, int Bn) {
    __shared__ float skp[KPTS * 3];
    int bid = blockIdx.x;
    if (bid < N) {
        int n = bid;
        int c = threadIdx.x;
        int b = batch_of(n, Bn);

        float ix = fminf(fmaxf((px[n] + 1.0f) * (WW * 0.5f) - 0.5f, 0.0f), (float)(WW - 1));
        float iy = fminf(fmaxf((py[n] + 1.0f) * (HH * 0.5f) - 0.5f, 0.0f), (float)(HH - 1));
        float x0f = floorf(ix), y0f = floorf(iy);
        float wx = ix - x0f, wy = iy - y0f;
        int x0 = (int)x0f, y0 = (int)y0f;
        int x1 = min(x0 + 1, WW - 1);
        int y1 = min(y0 + 1, HH - 1);

        const float* base = x + ((size_t)b * C_IN + c) * (size_t)(HH * WW);
        float v00 = base[(size_t)y0 * WW + x0];
        float v01 = base[(size_t)y0 * WW + x1];
        float v10 = base[(size_t)y1 * WW + x0];
        float v11 = base[(size_t)y1 * WW + x1];

        float top = v00 + (v01 - v00) * wx;
        float bot = v10 + (v11 - v10) * wx;
        g_feats[(size_t)n * C_IN + c] = top + (bot - top) * wy;
    } else {
        if (threadIdx.x < KPTS * 3) skp[threadIdx.x] = kp[threadIdx.x];
        __syncthreads();

        int t = (bid - N) * 256 + threadIdx.x;
        int n = t / NNB;
        int a = t % NNB;
        if (n >= N) return;
        int b = batch_of(n, Bn);
        int j = pknn[(size_t)n * NNB + a] + g_cum[b];

        float cx = pxyz[(size_t)n * 3 + 0];
        float cy = pxyz[(size_t)n * 3 + 1];
        float cz = pxyz[(size_t)n * 3 + 2];
        float rx = pxyz[(size_t)j * 3 + 0] - cx;
        float ry = pxyz[(size_t)j * 3 + 1] - cy;
        float rz = pxyz[(size_t)j * 3 + 2] - cz;

#pragma unroll
        for (int k = 0; k < KPTS; k++) {
            float dx = rx - skp[k * 3 + 0];
            float dy = ry - skp[k * 3 + 1];
            float dz = rz - skp[k * 3 + 2];
            float dist = sqrtf(dx * dx + dy * dy + dz * dz);
            g_allw[((size_t)n * NNB + a) * KPTS + k] = fmaxf(1.0f - dist * (1.0f / KP_EXT), 0.0f);
        }
    }
}

// ---------------- launch 3: weighted -> fp16 (float2, 128 thr/point) ----------------
__global__ void __launch_bounds__(128)
weighted_kernel(const int* __restrict__ pknn, int N, int Bn) {
    int n = blockIdx.x;
    int c2 = threadIdx.x;          // 0..127
    if (n >= N) return;

    __shared__ float sw[NNB * KPTS];
    __shared__ int sidx[NNB];
    if (c2 < NNB) {
        int b = batch_of(n, Bn);
        sidx[c2] = pknn[(size_t)n * NNB + c2] + g_cum[b];
    }
    for (int i = c2; i < NNB * KPTS; i += 128)
        sw[i] = g_allw[(size_t)n * NNB * KPTS + i];
    __syncthreads();

    float2 nx[NNB];
#pragma unroll
    for (int a = 0; a < NNB; a++)
        nx[a] = *(const float2*)(g_feats + (size_t)sidx[a] * C_IN + 2 * c2);

    __half2* Ah2 = (__half2*)g_Ah;
    size_t rowbase = ((size_t)n * KD) >> 1;

#pragma unroll
    for (int k = 0; k < KPTS; k++) {
        float acc0 = 0.0f, acc1 = 0.0f;
#pragma unroll
        for (int a = 0; a < NNB; a++) {
            float w = sw[a * KPTS + k];
            acc0 = fmaf(w, nx[a].x, acc0);
            acc1 = fmaf(w, nx[a].y, acc1);
        }
        Ah2[rowbase + (size_t)k * 128 + c2] =
            __halves2half2(__float2half_rn(acc0), __float2half_rn(acc1));
    }
}

// ---------------- launch 4: HMMA fp16 single-pass GEMM, 2 CTAs/SM ----------------
// C[m, d] = sum_kc A[m,kc] * B[d,kc]   (A, B both fp16; fp32 accumulate)
// CTA: 128(M) x 64(N), 256 threads = 8 warps = 4(M) x 2(N), warp tile 32 x 32
// 2-stage double buffer (24 KB/stage) -> 2 CTAs/SM; R10-proven 2-sync mainloop.
#define GM 128
#define GN 64
#define KCHUNK 64
#define NCHUNKS (KD / KCHUNK)           // 60
#define OFF_AH 0                        // 128 rows x 128B = 16 KB
#define OFF_BH 16384                    // 64 rows x 128B = 8 KB
#define STAGE_BYTES 24576               // 24 KB
#define NSTAGE 2
#define GEMM_SMEM (NSTAGE * STAGE_BYTES + 1024)
#define GEMM_THREADS 256

extern __shared__ char gemm_smem[];

__device__ __forceinline__ void issue_chunk(uint32_t stage_u32, int mBase, int nBase,
                                            int k0, int M, int tid) {
    int r_lo = tid >> 3;        // 0..31
    int i    = tid & 7;         // 16B granule within 128B row
    const __half* __restrict__ Ah = g_Ah;
    const __half* __restrict__ Bh = g_Bh;
#pragma unroll
    for (int p = 0; p < 6; p++) {
        uint32_t dst;
        const __half* src;
        if (p < 4) {                       // Ah rows 0..127
            int row = p * 32 + r_lo;
            uint32_t off = (uint32_t)(row * 128 + i * 16);
            uint32_t sw = off ^ ((off >> 3) & 0x70);
            int gr = min(mBase + row, M - 1);
            dst = stage_u32 + OFF_AH + sw;
            src = Ah + (size_t)gr * KD + k0 + i * 8;
        } else {                           // Bh rows 0..63
            int row = (p - 4) * 32 + r_lo;
            uint32_t off = (uint32_t)(row * 128 + i * 16);
            uint32_t sw = off ^ ((off >> 3) & 0x70);
            dst = stage_u32 + OFF_BH + sw;
            src = Bh + (size_t)(nBase + row) * KD + k0 + i * 8;
        }
        CP_ASYNC16(dst, src);
    }
}

__global__ void __launch_bounds__(GEMM_THREADS, 2) gemm_mma_kernel(float* __restrict__ C, int M) {
    int tid = threadIdx.x;
    int wid = tid >> 5;
    int lane = tid & 31;
    int wm = wid & 3;          // 0..3  (32 rows each)
    int wn = wid >> 2;         // 0..1  (32 cols each)
    int mBase = blockIdx.y * GM;
    int nBase = blockIdx.x * GN;

    uint32_t dyn_u32 = smem_u32(gemm_smem);
    uint32_t base_u32 = (dyn_u32 + 1023u) & ~1023u;

    float acc[2][4][4];
#pragma unroll
    for (int a = 0; a < 2; a++)
#pragma unroll
        for (int b = 0; b < 4; b++)
#pragma unroll
            for (int c = 0; c < 4; c++) acc[a][b][c] = 0.0f;

    int lrow = lane & 15;
    int csel = (lane >> 4) * 16;
    int aRow = wm * 32 + lrow;
    int bRow = wn * 32 + lrow;
    uint32_t xa = (uint32_t)((aRow & 7) << 4);
    uint32_t xb = (uint32_t)((bRow & 7) << 4);

    // prologue
    issue_chunk(base_u32, mBase, nBase, 0, M, tid);
    CP_COMMIT();

    for (int ch = 0; ch < NCHUNKS; ch++) {
        int buf = ch & 1;
        uint32_t stg = base_u32 + buf * STAGE_BYTES;

        if (ch + 1 < NCHUNKS) {
            issue_chunk(base_u32 + (buf ^ 1) * STAGE_BYTES,
                        mBase, nBase, (ch + 1) * KCHUNK, M, tid);
            CP_COMMIT();
            CP_WAIT1();       // chunk ch complete; ch+1 may be in flight
        } else {
            CP_WAIT0();
        }
        __syncthreads();

        uint32_t aBase = stg + (uint32_t)(aRow * 128);
        uint32_t bBase = stg + (uint32_t)(bRow * 128);

#pragma unroll
        for (int ks = 0; ks < 4; ks++) {
            uint32_t colA = ((uint32_t)(ks * 32 + csel)) ^ xa;
            uint32_t colB = ((uint32_t)(ks * 32 + csel)) ^ xb;

            uint32_t bh[2][4];
#pragma unroll
            for (int g = 0; g < 2; g++) {
                uint32_t addr = bBase + (uint32_t)(g * 16 * 128) + colB;
                ldsm4(bh[g], addr + OFF_BH);
            }
#pragma unroll
            for (int mt = 0; mt < 2; mt++) {
                uint32_t addr = aBase + (uint32_t)(mt * 16 * 128) + colA;
                uint32_t ah[4];
                ldsm4(ah, addr + OFF_AH);
#pragma unroll
                for (int nt = 0; nt < 4; nt++) {
                    int g = nt >> 1, h = nt & 1;
                    mma16816(acc[mt][nt], ah, bh[g][h], bh[g][h + 2]);
                }
            }
        }
        __syncthreads();   // buffer free before next overwrite
    }

    // ---- store C tile (m16n8 accumulator mapping) ----
    int rBase = mBase + wm * 32 + (lane >> 2);
    int cBase = nBase + wn * 32 + (lane & 3) * 2;
#pragma unroll
    for (int mt = 0; mt < 2; mt++) {
#pragma unroll
        for (int nt = 0; nt < 4; nt++) {
            int r0 = rBase + mt * 16;
            int cc = cBase + nt * 8;
            if (r0 < M)
                *(float2*)(C + (size_t)r0 * C_OUT + cc) =
                    make_float2(acc[mt][nt][0], acc[mt][nt][1]);
            if (r0 + 8 < M)
                *(float2*)(C + (size_t)(r0 + 8) * C_OUT + cc) =
                    make_float2(acc[mt][nt][2], acc[mt][nt][3]);
        }
    }

    // ---- fused BN partial stats: per-CTA column sum / sumsq over valid rows ----
    __syncthreads();                       // pipeline smem no longer needed
    float* sred = (float*)gemm_smem;       // [4 wm][64 cols] sums, then sqs (512 floats)

#pragma unroll
    for (int nt = 0; nt < 4; nt++) {
        float s0 = 0.f, s1 = 0.f, q0 = 0.f, q1 = 0.f;
#pragma unroll
        for (int mt = 0; mt < 2; mt++) {
            int ra = rBase + mt * 16;
            int rb = ra + 8;
            if (ra < M) {
                float v0 = acc[mt][nt][0], v1 = acc[mt][nt][1];
                s0 += v0; s1 += v1; q0 += v0 * v0; q1 += v1 * v1;
            }
            if (rb < M) {
                float v2 = acc[mt][nt][2], v3 = acc[mt][nt][3];
                s0 += v2; s1 += v3; q0 += v2 * v2; q1 += v3 * v3;
            }
        }
#pragma unroll
        for (int off = 16; off >= 4; off >>= 1) {
            s0 += __shfl_down_sync(0xffffffffu, s0, off);
            s1 += __shfl_down_sync(0xffffffffu, s1, off);
            q0 += __shfl_down_sync(0xffffffffu, q0, off);
            q1 += __shfl_down_sync(0xffffffffu, q1, off);
        }
        if (lane < 4) {
            int colL = wn * 32 + nt * 8 + lane * 2;   // 0..63
            sred[wm * 64 + colL]       = s0;
            sred[wm * 64 + colL + 1]   = s1;
            sred[256 + wm * 64 + colL]     = q0;
            sred[256 + wm * 64 + colL + 1] = q1;
        }
    }
    __syncthreads();

    if (tid < 64) {
        float s = sred[tid] + sred[64 + tid] + sred[128 + tid] + sred[192 + tid];
        g_psum[(size_t)blockIdx.y * C_OUT + blockIdx.x * GN + tid] = s;
    } else if (tid < 128) {
        int t = tid - 64;
        float s = sred[256 + t] + sred[320 + t] + sred[384 + t] + sred[448 + t];
        g_psq[(size_t)blockIdx.y * C_OUT + blockIdx.x * GN + t] = s;
    }
}

// ---------------- launch 5: finalize BN stats ----------------
__global__ void colstats_final(const float* __restrict__ gamma,
                               const float* __restrict__ beta,
                               int N, int nMtiles) {
    int d = threadIdx.x;
    float s = 0.f, ss = 0.f;
    for (int i = 0; i < nMtiles; i++) {
        s += g_psum[(size_t)i * C_OUT + d];
        ss += g_psq[(size_t)i * C_OUT + d];
    }
    float invN = 1.0f / (float)N;
    float mean = s * invN;
    float var = ss * invN - mean * mean;
    float sc = rsqrtf(var + BN_EPS) * gamma[d];
    g_scale[d] = sc;
    g_bias[d] = beta[d] - mean * sc;
}

// ---------------- launch 6: BN + ReLU ----------------
__global__ void bn_relu_kernel(float* __restrict__ out, size_t total) {
    for (size_t i = (size_t)blockIdx.x * blockDim.x + threadIdx.x; i < total;
         i += (size_t)gridDim.x * blockDim.x) {
        int d = (int)(i & (C_OUT - 1));
        float v = fmaf(out[i], g_scale[d], g_bias[d]);
        out[i] = v > 0.0f ? v : 0.0f;
    }
}

// ---------------- launch ----------------
extern "C" void kernel_launch(void* const* d_in, const int* in_sizes, int n_in,
                              void* d_out, int out_size) {
    const float* x     = (const float*)d_in[0];
    const float* px    = (const float*)d_in[1];
    const float* py    = (const float*)d_in[2];
    const float* pxyz  = (const float*)d_in[3];
    const int*   pknn  = (const int*)d_in[4];
    const int*   np    = (const int*)d_in[5];
    const float* kp    = (const float*)d_in[6];
    const float* kpw   = (const float*)d_in[7];
    const float* gamma = (const float*)d_in[8];
    const float* beta  = (const float*)d_in[9];
    float* out = (float*)d_out;

    int N  = in_sizes[1];
    int Bn = in_sizes[5];

    cudaFuncSetAttribute(gemm_mma_kernel,
                         cudaFuncAttributeMaxDynamicSharedMemorySize, GEMM_SMEM);

    // launch 1: prefix sums + B fp16 transpose
    prep_all_kernel<<<(KD * C_OUT + 255) / 256, 256>>>(np, Bn, kpw);

    // launch 2: fused feats + allw
    int allw_blocks = (N * NNB + 255) / 256;
    feats_allw_kernel<<<N + allw_blocks, 256>>>(x, px, py, pxyz, pknn, kp, N, Bn);

    // launch 3: weighted (float2, 128 threads per point)
    weighted_kernel<<<N, 128>>>(pknn, N, Bn);

    // launch 4: GEMM + fused BN partial stats (profiled slot)
    int nMtiles = (N + GM - 1) / GM;
    dim3 ggrid(C_OUT / GN, nMtiles);
    gemm_mma_kernel<<<ggrid, GEMM_THREADS, GEMM_SMEM>>>(out, N);

    // launch 5: finalize stats
    colstats_final<<<1, C_OUT>>>(gamma, beta, N, nMtiles);

    // launch 6: BN + ReLU
    size_t total = (size_t)N * C_OUT;
    bn_relu_kernel<<<2048, 256>>>(out, total);
}

// round 14
// speedup vs baseline: 2.0118x; 1.0061x over previous
#include <cuda_runtime.h>
#include <cuda_fp16.h>
#include <cstdint>
#include <cstddef>

// Problem constants
#define C_IN   256
#define C_OUT  256
#define KPTS   15
#define NNB    16
#define HH     64
#define WW     2048
#define KP_EXT 1.2f
#define BN_EPS 1e-5f
#define MAXB   8
#define MAXN   40000
#define KD     (KPTS * C_IN)        // 3840
#define MAXMT  320                  // max M-tiles (40000/128 = 313)

// ---------------- scratch (device globals) ----------------
__device__ int   g_cum[MAXB + 1];
__device__ float g_feats[(size_t)MAXN * C_IN];
__device__ float g_allw[(size_t)MAXN * NNB * KPTS];
__device__ __half g_Ah[(size_t)MAXN * KD];      // 307 MB (fp16 A)
__device__ __half g_Bh[(size_t)C_OUT * KD];     // 1.9 MB, K-major [d][kc], fp16
__device__ float g_psum[MAXMT * C_OUT];
__device__ float g_psq[MAXMT * C_OUT];
__device__ float g_scale[C_OUT];
__device__ float g_bias[C_OUT];

// ---------------- PTX helpers (base sm_103-legal only) ----------------
__device__ __forceinline__ uint32_t smem_u32(const void* p) {
    uint32_t a;
    asm("{ .reg .u64 t; cvta.to.shared.u64 t, %1; cvt.u32.u64 %0, t; }" : "=r"(a) : "l"(p));
    return a;
}

#define CP_ASYNC16(dst_u32, src_ptr) \
    asm volatile("cp.async.cg.shared.global [%0], [%1], 16;" \
                 :: "r"(dst_u32), "l"(src_ptr) : "memory")
#define CP_COMMIT() asm volatile("cp.async.commit_group;" ::: "memory")
#define CP_WAIT1()  asm volatile("cp.async.wait_group 1;" ::: "memory")
#define CP_WAIT0()  asm volatile("cp.async.wait_group 0;" ::: "memory")

__device__ __forceinline__ void ldsm4(uint32_t* r, uint32_t addr) {
    asm volatile("ldmatrix.sync.aligned.m8n8.x4.shared.b16 {%0,%1,%2,%3}, [%4];"
                 : "=r"(r[0]), "=r"(r[1]), "=r"(r[2]), "=r"(r[3]) : "r"(addr));
}

__device__ __forceinline__ void mma16816(float* c, const uint32_t* a,
                                         uint32_t b0, uint32_t b1) {
    asm volatile(
        "mma.sync.aligned.m16n8k16.row.col.f32.f16.f16.f32 "
        "{%0,%1,%2,%3}, {%4,%5,%6,%7}, {%8,%9}, {%0,%1,%2,%3};"
        : "+f"(c[0]), "+f"(c[1]), "+f"(c[2]), "+f"(c[3])
        : "r"(a[0]), "r"(a[1]), "r"(a[2]), "r"(a[3]), "r"(b0), "r"(b1));
}

__device__ __forceinline__ int batch_of(int n, int Bn) {
    int b = 0;
#pragma unroll
    for (int i = 1; i < MAXB; i++)
        if (i < Bn && n >= g_cum[i]) b = i;
    return b;
}

// ---------------- launch 1: prefix sums ----------------
__global__ void prep_cum_kernel(const int* __restrict__ np, int Bn) {
    if (blockIdx.x == 0 && threadIdx.x == 0) {
        int c = 0;
        for (int b = 0; b < Bn && b < MAXB; b++) { g_cum[b] = c; c += np[b]; }
        for (int b = Bn; b < MAXB; b++) g_cum[b] = c;
        g_cum[MAXB] = c;
    }
}

// ---------------- launch 2: B fp16 transpose ----------------
__global__ void prep_b_kernel(const float* __restrict__ kpw) {
    int i = blockIdx.x * blockDim.x + threadIdx.x;
    if (i >= KD * C_OUT) return;
    int kc = i >> 8;
    int d  = i & 255;
    g_Bh[(size_t)d * KD + kc] = __float2half_rn(kpw[i]);
}

// ---------------- launch 3: fused grid sample + kernel-point weights ----------------
__global__ void feats_allw_kernel(const float* __restrict__ x,
                                  const float* __restrict__ px,
                                  const float* __restrict__ py,
                                  const float* __restrict__ pxyz,
                                  const int* __restrict__ pknn,
                                  const float* __restrict__ kp,
                                  int N, int Bn) {
    __shared__ float skp[KPTS * 3];
    int bid = blockIdx.x;
    if (bid < N) {
        int n = bid;
        int c = threadIdx.x;
        int b = batch_of(n, Bn);

        float ix = fminf(fmaxf((px[n] + 1.0f) * (WW * 0.5f) - 0.5f, 0.0f), (float)(WW - 1));
        float iy = fminf(fmaxf((py[n] + 1.0f) * (HH * 0.5f) - 0.5f, 0.0f), (float)(HH - 1));
        float x0f = floorf(ix), y0f = floorf(iy);
        float wx = ix - x0f, wy = iy - y0f;
        int x0 = (int)x0f, y0 = (int)y0f;
        int x1 = min(x0 + 1, WW - 1);
        int y1 = min(y0 + 1, HH - 1);

        const float* base = x + ((size_t)b * C_IN + c) * (size_t)(HH * WW);
        float v00 = base[(size_t)y0 * WW + x0];
        float v01 = base[(size_t)y0 * WW + x1];
        float v10 = base[(size_t)y1 * WW + x0];
        float v11 = base[(size_t)y1 * WW + x1];

        float top = v00 + (v01 - v00) * wx;
        float bot = v10 + (v11 - v10) * wx;
        g_feats[(size_t)n * C_IN + c] = top + (bot - top) * wy;
    } else {
        if (threadIdx.x < KPTS * 3) skp[threadIdx.x] = kp[threadIdx.x];
        __syncthreads();

        int t = (bid - N) * 256 + threadIdx.x;
        int n = t / NNB;
        int a = t % NNB;
        if (n >= N) return;
        int b = batch_of(n, Bn);
        int j = pknn[(size_t)n * NNB + a] + g_cum[b];

        float cx = pxyz[(size_t)n * 3 + 0];
        float cy = pxyz[(size_t)n * 3 + 1];
        float cz = pxyz[(size_t)n * 3 + 2];
        float rx = pxyz[(size_t)j * 3 + 0] - cx;
        float ry = pxyz[(size_t)j * 3 + 1] - cy;
        float rz = pxyz[(size_t)j * 3 + 2] - cz;

#pragma unroll
        for (int k = 0; k < KPTS; k++) {
            float dx = rx - skp[k * 3 + 0];
            float dy = ry - skp[k * 3 + 1];
            float dz = rz - skp[k * 3 + 2];
            float dist = sqrtf(dx * dx + dy * dy + dz * dz);
            g_allw[((size_t)n * NNB + a) * KPTS + k] = fmaxf(1.0f - dist * (1.0f / KP_EXT), 0.0f);
        }
    }
}

// ---------------- launch 4 (profiled): weighted -> fp16 (float2, 128 thr/point) ----------------
__global__ void __launch_bounds__(128)
weighted_kernel(const int* __restrict__ pknn, int N, int Bn) {
    int n = blockIdx.x;
    int c2 = threadIdx.x;          // 0..127
    if (n >= N) return;

    __shared__ float sw[NNB * KPTS];
    __shared__ int sidx[NNB];
    if (c2 < NNB) {
        int b = batch_of(n, Bn);
        sidx[c2] = pknn[(size_t)n * NNB + c2] + g_cum[b];
    }
    for (int i = c2; i < NNB * KPTS; i += 128)
        sw[i] = g_allw[(size_t)n * NNB * KPTS + i];
    __syncthreads();

    float2 nx[NNB];
#pragma unroll
    for (int a = 0; a < NNB; a++)
        nx[a] = *(const float2*)(g_feats + (size_t)sidx[a] * C_IN + 2 * c2);

    __half2* Ah2 = (__half2*)g_Ah;
    size_t rowbase = ((size_t)n * KD) >> 1;

#pragma unroll
    for (int k = 0; k < KPTS; k++) {
        float acc0 = 0.0f, acc1 = 0.0f;
#pragma unroll
        for (int a = 0; a < NNB; a++) {
            float w = sw[a * KPTS + k];
            acc0 = fmaf(w, nx[a].x, acc0);
            acc1 = fmaf(w, nx[a].y, acc1);
        }
        Ah2[rowbase + (size_t)k * 128 + c2] =
            __halves2half2(__float2half_rn(acc0), __float2half_rn(acc1));
    }
}

// ---------------- launch 5: HMMA fp16 single-pass GEMM, 2 CTAs/SM ----------------
// C[m, d] = sum_kc A[m,kc] * B[d,kc]   (A, B both fp16; fp32 accumulate)
// CTA: 128(M) x 64(N), 256 threads = 8 warps = 4(M) x 2(N), warp tile 32 x 32
// 2-stage double buffer (24 KB/stage); per-thread copy addresses hoisted out of
// the mainloop (dst swizzles constant per stage, src pointers advance by k0).
#define GM 128
#define GN 64
#define KCHUNK 64
#define NCHUNKS (KD / KCHUNK)           // 60
#define OFF_AH 0                        // 128 rows x 128B = 16 KB
#define OFF_BH 16384                    // 64 rows x 128B = 8 KB
#define STAGE_BYTES 24576               // 24 KB
#define NSTAGE 2
#define GEMM_SMEM (NSTAGE * STAGE_BYTES + 1024)
#define GEMM_THREADS 256

extern __shared__ char gemm_smem[];

__global__ void __launch_bounds__(GEMM_THREADS, 2) gemm_mma_kernel(float* __restrict__ C, int M) {
    int tid = threadIdx.x;
    int wid = tid >> 5;
    int lane = tid & 31;
    int wm = wid & 3;          // 0..3  (32 rows each)
    int wn = wid >> 2;         // 0..1  (32 cols each)
    int mBase = blockIdx.y * GM;
    int nBase = blockIdx.x * GN;

    uint32_t dyn_u32 = smem_u32(gemm_smem);
    uint32_t base_u32 = (dyn_u32 + 1023u) & ~1023u;

    float acc[2][4][4];
#pragma unroll
    for (int a = 0; a < 2; a++)
#pragma unroll
        for (int b = 0; b < 4; b++)
#pragma unroll
            for (int c = 0; c < 4; c++) acc[a][b][c] = 0.0f;

    // ---- hoisted per-thread copy addresses ----
    int r_lo = tid >> 3;        // 0..31
    int gi   = tid & 7;         // 16B granule within 128B row
    const __half* srcA[4];
    const __half* srcB[2];
    uint32_t dstA[4], dstB[2];
#pragma unroll
    for (int p = 0; p < 4; p++) {
        int row = p * 32 + r_lo;
        uint32_t off = (uint32_t)(row * 128 + gi * 16);
        dstA[p] = OFF_AH + (off ^ ((off >> 3) & 0x70));
        int gr = min(mBase + row, M - 1);
        srcA[p] = g_Ah + (size_t)gr * KD + gi * 8;
    }
#pragma unroll
    for (int p = 0; p < 2; p++) {
        int row = p * 32 + r_lo;
        uint32_t off = (uint32_t)(row * 128 + gi * 16);
        dstB[p] = OFF_BH + (off ^ ((off >> 3) & 0x70));
        srcB[p] = g_Bh + (size_t)(nBase + row) * KD + gi * 8;
    }

    // ---- hoisted ldsm address components ----
    int lrow = lane & 15;
    int csel = (lane >> 4) * 16;
    int aRow = wm * 32 + lrow;
    int bRow = wn * 32 + lrow;
    uint32_t xa = (uint32_t)((aRow & 7) << 4);
    uint32_t xb = (uint32_t)((bRow & 7) << 4);

    // prologue: chunk 0 -> buf 0
#pragma unroll
    for (int p = 0; p < 4; p++) CP_ASYNC16(base_u32 + dstA[p], srcA[p]);
#pragma unroll
    for (int p = 0; p < 2; p++) CP_ASYNC16(base_u32 + dstB[p], srcB[p]);
    CP_COMMIT();

    for (int ch = 0; ch < NCHUNKS; ch++) {
        int buf = ch & 1;
        uint32_t stg = base_u32 + buf * STAGE_BYTES;

        if (ch + 1 < NCHUNKS) {
            uint32_t nstg = base_u32 + (buf ^ 1) * STAGE_BYTES;
            int k1 = (ch + 1) * KCHUNK;
#pragma unroll
            for (int p = 0; p < 4; p++) CP_ASYNC16(nstg + dstA[p], srcA[p] + k1);
#pragma unroll
            for (int p = 0; p < 2; p++) CP_ASYNC16(nstg + dstB[p], srcB[p] + k1);
            CP_COMMIT();
            CP_WAIT1();       // chunk ch complete; ch+1 may be in flight
        } else {
            CP_WAIT0();
        }
        __syncthreads();

        uint32_t aBase = stg + (uint32_t)(aRow * 128);
        uint32_t bBase = stg + (uint32_t)(bRow * 128);

#pragma unroll
        for (int ks = 0; ks < 4; ks++) {
            uint32_t colA = ((uint32_t)(ks * 32 + csel)) ^ xa;
            uint32_t colB = ((uint32_t)(ks * 32 + csel)) ^ xb;

            uint32_t bh[2][4];
#pragma unroll
            for (int g = 0; g < 2; g++) {
                uint32_t addr = bBase + (uint32_t)(g * 16 * 128) + colB;
                ldsm4(bh[g], addr + OFF_BH);
            }
#pragma unroll
            for (int mt = 0; mt < 2; mt++) {
                uint32_t addr = aBase + (uint32_t)(mt * 16 * 128) + colA;
                uint32_t ah[4];
                ldsm4(ah, addr + OFF_AH);
#pragma unroll
                for (int nt = 0; nt < 4; nt++) {
                    int g = nt >> 1, h = nt & 1;
                    mma16816(acc[mt][nt], ah, bh[g][h], bh[g][h + 2]);
                }
            }
        }
        __syncthreads();   // buffer free before next overwrite
    }

    // ---- store C tile (m16n8 accumulator mapping) ----
    int rBase = mBase + wm * 32 + (lane >> 2);
    int cBase = nBase + wn * 32 + (lane & 3) * 2;
#pragma unroll
    for (int mt = 0; mt < 2; mt++) {
#pragma unroll
        for (int nt = 0; nt < 4; nt++) {
            int r0 = rBase + mt * 16;
            int cc = cBase + nt * 8;
            if (r0 < M)
                *(float2*)(C + (size_t)r0 * C_OUT + cc) =
                    make_float2(acc[mt][nt][0], acc[mt][nt][1]);
            if (r0 + 8 < M)
                *(float2*)(C + (size_t)(r0 + 8) * C_OUT + cc) =
                    make_float2(acc[mt][nt][2], acc[mt][nt][3]);
        }
    }

    // ---- fused BN partial stats: per-CTA column sum / sumsq over valid rows ----
    __syncthreads();                       // pipeline smem no longer needed
    float* sred = (float*)gemm_smem;       // [4 wm][64 cols] sums, then sqs (512 floats)

#pragma unroll
    for (int nt = 0; nt < 4; nt++) {
        float s0 = 0.f, s1 = 0.f, q0 = 0.f, q1 = 0.f;
#pragma unroll
        for (int mt = 0; mt < 2; mt++) {
            int ra = rBase + mt * 16;
            int rb = ra + 8;
            if (ra < M) {
                float v0 = acc[mt][nt][0], v1 = acc[mt][nt][1];
                s0 += v0; s1 += v1; q0 += v0 * v0; q1 += v1 * v1;
            }
            if (rb < M) {
                float v2 = acc[mt][nt][2], v3 = acc[mt][nt][3];
                s0 += v2; s1 += v3; q0 += v2 * v2; q1 += v3 * v3;
            }
        }
#pragma unroll
        for (int off = 16; off >= 4; off >>= 1) {
            s0 += __shfl_down_sync(0xffffffffu, s0, off);
            s1 += __shfl_down_sync(0xffffffffu, s1, off);
            q0 += __shfl_down_sync(0xffffffffu, q0, off);
            q1 += __shfl_down_sync(0xffffffffu, q1, off);
        }
        if (lane < 4) {
            int colL = wn * 32 + nt * 8 + lane * 2;   // 0..63
            sred[wm * 64 + colL]       = s0;
            sred[wm * 64 + colL + 1]   = s1;
            sred[256 + wm * 64 + colL]     = q0;
            sred[256 + wm * 64 + colL + 1] = q1;
        }
    }
    __syncthreads();

    if (tid < 64) {
        float s = sred[tid] + sred[64 + tid] + sred[128 + tid] + sred[192 + tid];
        g_psum[(size_t)blockIdx.y * C_OUT + blockIdx.x * GN + tid] = s;
    } else if (tid < 128) {
        int t = tid - 64;
        float s = sred[256 + t] + sred[320 + t] + sred[384 + t] + sred[448 + t];
        g_psq[(size_t)blockIdx.y * C_OUT + blockIdx.x * GN + t] = s;
    }
}

// ---------------- launch 6: finalize BN stats ----------------
__global__ void colstats_final(const float* __restrict__ gamma,
                               const float* __restrict__ beta,
                               int N, int nMtiles) {
    int d = threadIdx.x;
    float s = 0.f, ss = 0.f;
    for (int i = 0; i < nMtiles; i++) {
        s += g_psum[(size_t)i * C_OUT + d];
        ss += g_psq[(size_t)i * C_OUT + d];
    }
    float invN = 1.0f / (float)N;
    float mean = s * invN;
    float var = ss * invN - mean * mean;
    float sc = rsqrtf(var + BN_EPS) * gamma[d];
    g_scale[d] = sc;
    g_bias[d] = beta[d] - mean * sc;
}

// ---------------- launch 7: BN + ReLU (float4) ----------------
__global__ void bn_relu_kernel(float* __restrict__ out, size_t total4) {
    float4* o4 = (float4*)out;
    for (size_t i = (size_t)blockIdx.x * blockDim.x + threadIdx.x; i < total4;
         i += (size_t)gridDim.x * blockDim.x) {
        int d = (int)((i * 4) & (C_OUT - 1));
        float4 v = o4[i];
        v.x = fmaf(v.x, g_scale[d + 0], g_bias[d + 0]);
        v.y = fmaf(v.y, g_scale[d + 1], g_bias[d + 1]);
        v.z = fmaf(v.z, g_scale[d + 2], g_bias[d + 2]);
        v.w = fmaf(v.w, g_scale[d + 3], g_bias[d + 3]);
        v.x = v.x > 0.f ? v.x : 0.f;
        v.y = v.y > 0.f ? v.y : 0.f;
        v.z = v.z > 0.f ? v.z : 0.f;
        v.w = v.w > 0.f ? v.w : 0.f;
        o4[i] = v;
    }
}

// ---------------- launch ----------------
extern "C" void kernel_launch(void* const* d_in, const int* in_sizes, int n_in,
                              void* d_out, int out_size) {
    const float* x     = (const float*)d_in[0];
    const float* px    = (const float*)d_in[1];
    const float* py    = (const float*)d_in[2];
    const float* pxyz  = (const float*)d_in[3];
    const int*   pknn  = (const int*)d_in[4];
    const int*   np    = (const int*)d_in[5];
    const float* kp    = (const float*)d_in[6];
    const float* kpw   = (const float*)d_in[7];
    const float* gamma = (const float*)d_in[8];
    const float* beta  = (const float*)d_in[9];
    float* out = (float*)d_out;

    int N  = in_sizes[1];
    int Bn = in_sizes[5];

    cudaFuncSetAttribute(gemm_mma_kernel,
                         cudaFuncAttributeMaxDynamicSharedMemorySize, GEMM_SMEM);

    // launch 1: prefix sums
    prep_cum_kernel<<<1, 32>>>(np, Bn);

    // launch 2: B fp16 transpose
    prep_b_kernel<<<(KD * C_OUT + 255) / 256, 256>>>(kpw);

    // launch 3: fused feats + allw
    int allw_blocks = (N * NNB + 255) / 256;
    feats_allw_kernel<<<N + allw_blocks, 256>>>(x, px, py, pxyz, pknn, kp, N, Bn);

    // launch 4: weighted (profiled slot this round)
    weighted_kernel<<<N, 128>>>(pknn, N, Bn);

    // launch 5: GEMM + fused BN partial stats
    int nMtiles = (N + GM - 1) / GM;
    dim3 ggrid(C_OUT / GN, nMtiles);
    gemm_mma_kernel<<<ggrid, GEMM_THREADS, GEMM_SMEM>>>(out, N);

    // launch 6: finalize stats
    colstats_final<<<1, C_OUT>>>(gamma, beta, N, nMtiles);

    // launch 7: BN + ReLU
    size_t total4 = ((size_t)N * C_OUT) / 4;
    bn_relu_kernel<<<1024, 256>>>(out, total4);
}

// round 15
// speedup vs baseline: 2.3291x; 1.1577x over previous
#include <cuda_runtime.h>
#include <cuda_fp16.h>
#include <cstdint>
#include <cstddef>

// Problem constants
#define C_IN   256
#define C_OUT  256
#define KPTS   15
#define NNB    16
#define HH     64
#define WW     2048
#define KP_EXT 1.2f
#define BN_EPS 1e-5f
#define MAXB   8
#define MAXN   40000
#define KD     (KPTS * C_IN)        // 3840
#define MAXMT  320                  // max M-tiles (40000/128 = 313)

// ---------------- scratch (device globals) ----------------
__device__ int   g_cum[MAXB + 1];
__device__ float g_feats[(size_t)MAXN * C_IN];
__device__ float g_allw[(size_t)MAXN * NNB * KPTS];
__device__ __half g_Ah[(size_t)MAXN * KD];      // 307 MB (fp16 A)
__device__ __half g_Bh[(size_t)C_OUT * KD];     // 1.9 MB, K-major [d][kc], fp16
__device__ float g_psum[MAXMT * C_OUT];
__device__ float g_psq[MAXMT * C_OUT];
__device__ float g_scale[C_OUT];
__device__ float g_bias[C_OUT];

// ---------------- PTX helpers (base sm_103-legal only) ----------------
__device__ __forceinline__ uint32_t smem_u32(const void* p) {
    uint32_t a;
    asm("{ .reg .u64 t; cvta.to.shared.u64 t, %1; cvt.u32.u64 %0, t; }" : "=r"(a) : "l"(p));
    return a;
}

#define CP_ASYNC16(dst_u32, src_ptr) \
    asm volatile("cp.async.cg.shared.global [%0], [%1], 16;" \
                 :: "r"(dst_u32), "l"(src_ptr) : "memory")
#define CP_COMMIT() asm volatile("cp.async.commit_group;" ::: "memory")
#define CP_WAIT1()  asm volatile("cp.async.wait_group 1;" ::: "memory")
#define CP_WAIT0()  asm volatile("cp.async.wait_group 0;" ::: "memory")

__device__ __forceinline__ void ldsm4(uint32_t* r, uint32_t addr) {
    asm volatile("ldmatrix.sync.aligned.m8n8.x4.shared.b16 {%0,%1,%2,%3}, [%4];"
                 : "=r"(r[0]), "=r"(r[1]), "=r"(r[2]), "=r"(r[3]) : "r"(addr));
}

__device__ __forceinline__ void mma16816(float* c, const uint32_t* a,
                                         uint32_t b0, uint32_t b1) {
    asm volatile(
        "mma.sync.aligned.m16n8k16.row.col.f32.f16.f16.f32 "
        "{%0,%1,%2,%3}, {%4,%5,%6,%7}, {%8,%9}, {%0,%1,%2,%3};"
        : "+f"(c[0]), "+f"(c[1]), "+f"(c[2]), "+f"(c[3])
        : "r"(a[0]), "r"(a[1]), "r"(a[2]), "r"(a[3]), "r"(b0), "r"(b1));
}

__device__ __forceinline__ int batch_of(int n, int Bn) {
    int b = 0;
#pragma unroll
    for (int i = 1; i < MAXB; i++)
        if (i < Bn && n >= g_cum[i]) b = i;
    return b;
}

// ---------------- launch 1: prefix sums ----------------
__global__ void prep_cum_kernel(const int* __restrict__ np, int Bn) {
    if (blockIdx.x == 0 && threadIdx.x == 0) {
        int c = 0;
        for (int b = 0; b < Bn && b < MAXB; b++) { g_cum[b] = c; c += np[b]; }
        for (int b = Bn; b < MAXB; b++) g_cum[b] = c;
        g_cum[MAXB] = c;
    }
}

// ---------------- launch 2: B fp16 transpose ----------------
__global__ void prep_b_kernel(const float* __restrict__ kpw) {
    int i = blockIdx.x * blockDim.x + threadIdx.x;
    if (i >= KD * C_OUT) return;
    int kc = i >> 8;
    int d  = i & 255;
    g_Bh[(size_t)d * KD + kc] = __float2half_rn(kpw[i]);
}

// ---------------- launch 3: fused grid sample + kernel-point weights ----------------
__global__ void feats_allw_kernel(const float* __restrict__ x,
                                  const float* __restrict__ px,
                                  const float* __restrict__ py,
                                  const float* __restrict__ pxyz,
                                  const int* __restrict__ pknn,
                                  const float* __restrict__ kp,
                                  int N, int Bn) {
    __shared__ float skp[KPTS * 3];
    int bid = blockIdx.x;
    if (bid < N) {
        int n = bid;
        int c = threadIdx.x;
        int b = batch_of(n, Bn);

        float ix = fminf(fmaxf((px[n] + 1.0f) * (WW * 0.5f) - 0.5f, 0.0f), (float)(WW - 1));
        float iy = fminf(fmaxf((py[n] + 1.0f) * (HH * 0.5f) - 0.5f, 0.0f), (float)(HH - 1));
        float x0f = floorf(ix), y0f = floorf(iy);
        float wx = ix - x0f, wy = iy - y0f;
        int x0 = (int)x0f, y0 = (int)y0f;
        int x1 = min(x0 + 1, WW - 1);
        int y1 = min(y0 + 1, HH - 1);

        const float* base = x + ((size_t)b * C_IN + c) * (size_t)(HH * WW);
        float v00 = base[(size_t)y0 * WW + x0];
        float v01 = base[(size_t)y0 * WW + x1];
        float v10 = base[(size_t)y1 * WW + x0];
        float v11 = base[(size_t)y1 * WW + x1];

        float top = v00 + (v01 - v00) * wx;
        float bot = v10 + (v11 - v10) * wx;
        g_feats[(size_t)n * C_IN + c] = top + (bot - top) * wy;
    } else {
        if (threadIdx.x < KPTS * 3) skp[threadIdx.x] = kp[threadIdx.x];
        __syncthreads();

        int t = (bid - N) * 256 + threadIdx.x;
        int n = t / NNB;
        int a = t % NNB;
        if (n >= N) return;
        int b = batch_of(n, Bn);
        int j = pknn[(size_t)n * NNB + a] + g_cum[b];

        float cx = pxyz[(size_t)n * 3 + 0];
        float cy = pxyz[(size_t)n * 3 + 1];
        float cz = pxyz[(size_t)n * 3 + 2];
        float rx = pxyz[(size_t)j * 3 + 0] - cx;
        float ry = pxyz[(size_t)j * 3 + 1] - cy;
        float rz = pxyz[(size_t)j * 3 + 2] - cz;

#pragma unroll
        for (int k = 0; k < KPTS; k++) {
            float dx = rx - skp[k * 3 + 0];
            float dy = ry - skp[k * 3 + 1];
            float dz = rz - skp[k * 3 + 2];
            float dist = sqrtf(dx * dx + dy * dy + dz * dz);
            g_allw[((size_t)n * NNB + a) * KPTS + k] = fmaxf(1.0f - dist * (1.0f / KP_EXT), 0.0f);
        }
    }
}

// ---------------- launch 4 (profiled): weighted -> fp16 ----------------
// accumulator-outer restructure: acc[15][2] persistent (30 regs), neighbor
// gathers streamed in 4 groups of 4 (<=8 transient regs) -> low reg count,
// high occupancy on a latency-bound gather kernel.
__global__ void __launch_bounds__(128)
weighted_kernel(const int* __restrict__ pknn, int N, int Bn) {
    int n = blockIdx.x;
    int c2 = threadIdx.x;          // 0..127 (channel pair)
    if (n >= N) return;

    __shared__ float sw[NNB * KPTS];
    __shared__ int sidx[NNB];
    if (c2 < NNB) {
        int b = batch_of(n, Bn);
        sidx[c2] = pknn[(size_t)n * NNB + c2] + g_cum[b];
    }
    for (int i = c2; i < NNB * KPTS; i += 128)
        sw[i] = g_allw[(size_t)n * NNB * KPTS + i];
    __syncthreads();

    float accA[KPTS], accB[KPTS];
#pragma unroll
    for (int k = 0; k < KPTS; k++) { accA[k] = 0.0f; accB[k] = 0.0f; }

#pragma unroll
    for (int g = 0; g < 4; g++) {
        float2 nx[4];
#pragma unroll
        for (int a4 = 0; a4 < 4; a4++)
            nx[a4] = *(const float2*)(g_feats + (size_t)sidx[g * 4 + a4] * C_IN + 2 * c2);
#pragma unroll
        for (int a4 = 0; a4 < 4; a4++) {
            int a = g * 4 + a4;
            float vx = nx[a4].x, vy = nx[a4].y;
#pragma unroll
            for (int k = 0; k < KPTS; k++) {
                float w = sw[a * KPTS + k];
                accA[k] = fmaf(w, vx, accA[k]);
                accB[k] = fmaf(w, vy, accB[k]);
            }
        }
    }

    __half2* Ah2 = (__half2*)g_Ah;
    size_t rowbase = ((size_t)n * KD) >> 1;
#pragma unroll
    for (int k = 0; k < KPTS; k++) {
        Ah2[rowbase + (size_t)k * 128 + c2] =
            __halves2half2(__float2half_rn(accA[k]), __float2half_rn(accB[k]));
    }
}

// ---------------- launch 5: HMMA fp16 single-pass GEMM, 2 CTAs/SM ----------------
// C[m, d] = sum_kc A[m,kc] * B[d,kc]   (A, B both fp16; fp32 accumulate)
// CTA: 128(M) x 64(N), 256 threads = 8 warps = 4(M) x 2(N), warp tile 32 x 32
#define GM 128
#define GN 64
#define KCHUNK 64
#define NCHUNKS (KD / KCHUNK)           // 60
#define OFF_AH 0                        // 128 rows x 128B = 16 KB
#define OFF_BH 16384                    // 64 rows x 128B = 8 KB
#define STAGE_BYTES 24576               // 24 KB
#define NSTAGE 2
#define GEMM_SMEM (NSTAGE * STAGE_BYTES + 1024)
#define GEMM_THREADS 256

extern __shared__ char gemm_smem[];

__global__ void __launch_bounds__(GEMM_THREADS, 2) gemm_mma_kernel(float* __restrict__ C, int M) {
    int tid = threadIdx.x;
    int wid = tid >> 5;
    int lane = tid & 31;
    int wm = wid & 3;          // 0..3  (32 rows each)
    int wn = wid >> 2;         // 0..1  (32 cols each)
    int mBase = blockIdx.y * GM;
    int nBase = blockIdx.x * GN;

    uint32_t dyn_u32 = smem_u32(gemm_smem);
    uint32_t base_u32 = (dyn_u32 + 1023u) & ~1023u;

    float acc[2][4][4];
#pragma unroll
    for (int a = 0; a < 2; a++)
#pragma unroll
        for (int b = 0; b < 4; b++)
#pragma unroll
            for (int c = 0; c < 4; c++) acc[a][b][c] = 0.0f;

    // ---- hoisted per-thread copy addresses ----
    int r_lo = tid >> 3;        // 0..31
    int gi   = tid & 7;         // 16B granule within 128B row
    const __half* srcA[4];
    const __half* srcB[2];
    uint32_t dstA[4], dstB[2];
#pragma unroll
    for (int p = 0; p < 4; p++) {
        int row = p * 32 + r_lo;
        uint32_t off = (uint32_t)(row * 128 + gi * 16);
        dstA[p] = OFF_AH + (off ^ ((off >> 3) & 0x70));
        int gr = min(mBase + row, M - 1);
        srcA[p] = g_Ah + (size_t)gr * KD + gi * 8;
    }
#pragma unroll
    for (int p = 0; p < 2; p++) {
        int row = p * 32 + r_lo;
        uint32_t off = (uint32_t)(row * 128 + gi * 16);
        dstB[p] = OFF_BH + (off ^ ((off >> 3) & 0x70));
        srcB[p] = g_Bh + (size_t)(nBase + row) * KD + gi * 8;
    }

    // ---- hoisted ldsm address components ----
    int lrow = lane & 15;
    int csel = (lane >> 4) * 16;
    int aRow = wm * 32 + lrow;
    int bRow = wn * 32 + lrow;
    uint32_t xa = (uint32_t)((aRow & 7) << 4);
    uint32_t xb = (uint32_t)((bRow & 7) << 4);

    // prologue: chunk 0 -> buf 0
#pragma unroll
    for (int p = 0; p < 4; p++) CP_ASYNC16(base_u32 + dstA[p], srcA[p]);
#pragma unroll
    for (int p = 0; p < 2; p++) CP_ASYNC16(base_u32 + dstB[p], srcB[p]);
    CP_COMMIT();

    for (int ch = 0; ch < NCHUNKS; ch++) {
        int buf = ch & 1;
        uint32_t stg = base_u32 + buf * STAGE_BYTES;

        if (ch + 1 < NCHUNKS) {
            uint32_t nstg = base_u32 + (buf ^ 1) * STAGE_BYTES;
            int k1 = (ch + 1) * KCHUNK;
#pragma unroll
            for (int p = 0; p < 4; p++) CP_ASYNC16(nstg + dstA[p], srcA[p] + k1);
#pragma unroll
            for (int p = 0; p < 2; p++) CP_ASYNC16(nstg + dstB[p], srcB[p] + k1);
            CP_COMMIT();
            CP_WAIT1();       // chunk ch complete; ch+1 may be in flight
        } else {
            CP_WAIT0();
        }
        __syncthreads();

        uint32_t aBase = stg + (uint32_t)(aRow * 128);
        uint32_t bBase = stg + (uint32_t)(bRow * 128);

#pragma unroll
        for (int ks = 0; ks < 4; ks++) {
            uint32_t colA = ((uint32_t)(ks * 32 + csel)) ^ xa;
            uint32_t colB = ((uint32_t)(ks * 32 + csel)) ^ xb;

            uint32_t bh[2][4];
#pragma unroll
            for (int g = 0; g < 2; g++) {
                uint32_t addr = bBase + (uint32_t)(g * 16 * 128) + colB;
                ldsm4(bh[g], addr + OFF_BH);
            }
#pragma unroll
            for (int mt = 0; mt < 2; mt++) {
                uint32_t addr = aBase + (uint32_t)(mt * 16 * 128) + colA;
                uint32_t ah[4];
                ldsm4(ah, addr + OFF_AH);
#pragma unroll
                for (int nt = 0; nt < 4; nt++) {
                    int g = nt >> 1, h = nt & 1;
                    mma16816(acc[mt][nt], ah, bh[g][h], bh[g][h + 2]);
                }
            }
        }
        __syncthreads();   // buffer free before next overwrite
    }

    // ---- store C tile (m16n8 accumulator mapping) ----
    int rBase = mBase + wm * 32 + (lane >> 2);
    int cBase = nBase + wn * 32 + (lane & 3) * 2;
#pragma unroll
    for (int mt = 0; mt < 2; mt++) {
#pragma unroll
        for (int nt = 0; nt < 4; nt++) {
            int r0 = rBase + mt * 16;
            int cc = cBase + nt * 8;
            if (r0 < M)
                *(float2*)(C + (size_t)r0 * C_OUT + cc) =
                    make_float2(acc[mt][nt][0], acc[mt][nt][1]);
            if (r0 + 8 < M)
                *(float2*)(C + (size_t)(r0 + 8) * C_OUT + cc) =
                    make_float2(acc[mt][nt][2], acc[mt][nt][3]);
        }
    }

    // ---- fused BN partial stats: per-CTA column sum / sumsq over valid rows ----
    __syncthreads();                       // pipeline smem no longer needed
    float* sred = (float*)gemm_smem;       // [4 wm][64 cols] sums, then sqs (512 floats)

#pragma unroll
    for (int nt = 0; nt < 4; nt++) {
        float s0 = 0.f, s1 = 0.f, q0 = 0.f, q1 = 0.f;
#pragma unroll
        for (int mt = 0; mt < 2; mt++) {
            int ra = rBase + mt * 16;
            int rb = ra + 8;
            if (ra < M) {
                float v0 = acc[mt][nt][0], v1 = acc[mt][nt][1];
                s0 += v0; s1 += v1; q0 += v0 * v0; q1 += v1 * v1;
            }
            if (rb < M) {
                float v2 = acc[mt][nt][2], v3 = acc[mt][nt][3];
                s0 += v2; s1 += v3; q0 += v2 * v2; q1 += v3 * v3;
            }
        }
#pragma unroll
        for (int off = 16; off >= 4; off >>= 1) {
            s0 += __shfl_down_sync(0xffffffffu, s0, off);
            s1 += __shfl_down_sync(0xffffffffu, s1, off);
            q0 += __shfl_down_sync(0xffffffffu, q0, off);
            q1 += __shfl_down_sync(0xffffffffu, q1, off);
        }
        if (lane < 4) {
            int colL = wn * 32 + nt * 8 + lane * 2;   // 0..63
            sred[wm * 64 + colL]       = s0;
            sred[wm * 64 + colL + 1]   = s1;
            sred[256 + wm * 64 + colL]     = q0;
            sred[256 + wm * 64 + colL + 1] = q1;
        }
    }
    __syncthreads();

    if (tid < 64) {
        float s = sred[tid] + sred[64 + tid] + sred[128 + tid] + sred[192 + tid];
        g_psum[(size_t)blockIdx.y * C_OUT + blockIdx.x * GN + tid] = s;
    } else if (tid < 128) {
        int t = tid - 64;
        float s = sred[256 + t] + sred[320 + t] + sred[384 + t] + sred[448 + t];
        g_psq[(size_t)blockIdx.y * C_OUT + blockIdx.x * GN + t] = s;
    }
}

// ---------------- launch 6: finalize BN stats ----------------
__global__ void colstats_final(const float* __restrict__ gamma,
                               const float* __restrict__ beta,
                               int N, int nMtiles) {
    int d = threadIdx.x;
    float s = 0.f, ss = 0.f;
    for (int i = 0; i < nMtiles; i++) {
        s += g_psum[(size_t)i * C_OUT + d];
        ss += g_psq[(size_t)i * C_OUT + d];
    }
    float invN = 1.0f / (float)N;
    float mean = s * invN;
    float var = ss * invN - mean * mean;
    float sc = rsqrtf(var + BN_EPS) * gamma[d];
    g_scale[d] = sc;
    g_bias[d] = beta[d] - mean * sc;
}

// ---------------- launch 7: BN + ReLU (float4) ----------------
__global__ void bn_relu_kernel(float* __restrict__ out, size_t total4) {
    float4* o4 = (float4*)out;
    for (size_t i = (size_t)blockIdx.x * blockDim.x + threadIdx.x; i < total4;
         i += (size_t)gridDim.x * blockDim.x) {
        int d = (int)((i * 4) & (C_OUT - 1));
        float4 v = o4[i];
        v.x = fmaf(v.x, g_scale[d + 0], g_bias[d + 0]);
        v.y = fmaf(v.y, g_scale[d + 1], g_bias[d + 1]);
        v.z = fmaf(v.z, g_scale[d + 2], g_bias[d + 2]);
        v.w = fmaf(v.w, g_scale[d + 3], g_bias[d + 3]);
        v.x = v.x > 0.f ? v.x : 0.f;
        v.y = v.y > 0.f ? v.y : 0.f;
        v.z = v.z > 0.f ? v.z : 0.f;
        v.w = v.w > 0.f ? v.w : 0.f;
        o4[i] = v;
    }
}

// ---------------- launch ----------------
extern "C" void kernel_launch(void* const* d_in, const int* in_sizes, int n_in,
                              void* d_out, int out_size) {
    const float* x     = (const float*)d_in[0];
    const float* px    = (const float*)d_in[1];
    const float* py    = (const float*)d_in[2];
    const float* pxyz  = (const float*)d_in[3];
    const int*   pknn  = (const int*)d_in[4];
    const int*   np    = (const int*)d_in[5];
    const float* kp    = (const float*)d_in[6];
    const float* kpw   = (const float*)d_in[7];
    const float* gamma = (const float*)d_in[8];
    const float* beta  = (const float*)d_in[9];
    float* out = (float*)d_out;

    int N  = in_sizes[1];
    int Bn = in_sizes[5];

    cudaFuncSetAttribute(gemm_mma_kernel,
                         cudaFuncAttributeMaxDynamicSharedMemorySize, GEMM_SMEM);

    // launch 1: prefix sums
    prep_cum_kernel<<<1, 32>>>(np, Bn);

    // launch 2: B fp16 transpose
    prep_b_kernel<<<(KD * C_OUT + 255) / 256, 256>>>(kpw);

    // launch 3: fused feats + allw
    int allw_blocks = (N * NNB + 255) / 256;
    feats_allw_kernel<<<N + allw_blocks, 256>>>(x, px, py, pxyz, pknn, kp, N, Bn);

    // launch 4: weighted (profiled slot — direct A/B on the restructure)
    weighted_kernel<<<N, 128>>>(pknn, N, Bn);

    // launch 5: GEMM + fused BN partial stats
    int nMtiles = (N + GM - 1) / GM;
    dim3 ggrid(C_OUT / GN, nMtiles);
    gemm_mma_kernel<<<ggrid, GEMM_THREADS, GEMM_SMEM>>>(out, N);

    // launch 6: finalize stats
    colstats_final<<<1, C_OUT>>>(gamma, beta, N, nMtiles);

    // launch 7: BN + ReLU
    size_t total4 = ((size_t)N * C_OUT) / 4;
    bn_relu_kernel<<<1024, 256>>>(out, total4);
}

// round 16
// speedup vs baseline: 2.3296x; 1.0002x over previous
#include <cuda_runtime.h>
#include <cuda_fp16.h>
#include <cstdint>
#include <cstddef>

// Problem constants
#define C_IN   256
#define C_OUT  256
#define KPTS   15
#define NNB    16
#define HH     64
#define WW     2048
#define KP_EXT 1.2f
#define BN_EPS 1e-5f
#define MAXB   8
#define MAXN   40000
#define KD     (KPTS * C_IN)        // 3840
#define MAXMT  320                  // max M-tiles (40000/128 = 313)

// ---------------- scratch (device globals) ----------------
__device__ int   g_cum[MAXB + 1];
__device__ __half g_feats[(size_t)MAXN * C_IN];  // fp16 feats (20 MB)
__device__ float g_allw[(size_t)MAXN * NNB * KPTS];
__device__ __half g_Ah[(size_t)MAXN * KD];      // 307 MB (fp16 A)
__device__ __half g_Bh[(size_t)C_OUT * KD];     // 1.9 MB, K-major [d][kc], fp16
__device__ float g_psum[MAXMT * C_OUT];
__device__ float g_psq[MAXMT * C_OUT];
__device__ float g_scale[C_OUT];
__device__ float g_bias[C_OUT];

// ---------------- PTX helpers (base sm_103-legal only) ----------------
__device__ __forceinline__ uint32_t smem_u32(const void* p) {
    uint32_t a;
    asm("{ .reg .u64 t; cvta.to.shared.u64 t, %1; cvt.u32.u64 %0, t; }" : "=r"(a) : "l"(p));
    return a;
}

#define CP_ASYNC16(dst_u32, src_ptr) \
    asm volatile("cp.async.cg.shared.global [%0], [%1], 16;" \
                 :: "r"(dst_u32), "l"(src_ptr) : "memory")
#define CP_COMMIT() asm volatile("cp.async.commit_group;" ::: "memory")
#define CP_WAIT1()  asm volatile("cp.async.wait_group 1;" ::: "memory")
#define CP_WAIT0()  asm volatile("cp.async.wait_group 0;" ::: "memory")

__device__ __forceinline__ void ldsm4(uint32_t* r, uint32_t addr) {
    asm volatile("ldmatrix.sync.aligned.m8n8.x4.shared.b16 {%0,%1,%2,%3}, [%4];"
                 : "=r"(r[0]), "=r"(r[1]), "=r"(r[2]), "=r"(r[3]) : "r"(addr));
}

__device__ __forceinline__ void mma16816(float* c, const uint32_t* a,
                                         uint32_t b0, uint32_t b1) {
    asm volatile(
        "mma.sync.aligned.m16n8k16.row.col.f32.f16.f16.f32 "
        "{%0,%1,%2,%3}, {%4,%5,%6,%7}, {%8,%9}, {%0,%1,%2,%3};"
        : "+f"(c[0]), "+f"(c[1]), "+f"(c[2]), "+f"(c[3])
        : "r"(a[0]), "r"(a[1]), "r"(a[2]), "r"(a[3]), "r"(b0), "r"(b1));
}

__device__ __forceinline__ int batch_of(int n, int Bn) {
    int b = 0;
#pragma unroll
    for (int i = 1; i < MAXB; i++)
        if (i < Bn && n >= g_cum[i]) b = i;
    return b;
}

// ---------------- launch 1: prefix sums ----------------
__global__ void prep_cum_kernel(const int* __restrict__ np, int Bn) {
    if (blockIdx.x == 0 && threadIdx.x == 0) {
        int c = 0;
        for (int b = 0; b < Bn && b < MAXB; b++) { g_cum[b] = c; c += np[b]; }
        for (int b = Bn; b < MAXB; b++) g_cum[b] = c;
        g_cum[MAXB] = c;
    }
}

// ---------------- launch 2: B fp16 transpose ----------------
__global__ void prep_b_kernel(const float* __restrict__ kpw) {
    int i = blockIdx.x * blockDim.x + threadIdx.x;
    if (i >= KD * C_OUT) return;
    int kc = i >> 8;
    int d  = i & 255;
    g_Bh[(size_t)d * KD + kc] = __float2half_rn(kpw[i]);
}

// ---------------- launch 3: fused grid sample + kernel-point weights ----------------
__global__ void feats_allw_kernel(const float* __restrict__ x,
                                  const float* __restrict__ px,
                                  const float* __restrict__ py,
                                  const float* __restrict__ pxyz,
                                  const int* __restrict__ pknn,
                                  const float* __restrict__ kp,
                                  int N, int Bn) {
    __shared__ float skp[KPTS * 3];
    int bid = blockIdx.x;
    if (bid < N) {
        int n = bid;
        int c = threadIdx.x;
        int b = batch_of(n, Bn);

        float ix = fminf(fmaxf((px[n] + 1.0f) * (WW * 0.5f) - 0.5f, 0.0f), (float)(WW - 1));
        float iy = fminf(fmaxf((py[n] + 1.0f) * (HH * 0.5f) - 0.5f, 0.0f), (float)(HH - 1));
        float x0f = floorf(ix), y0f = floorf(iy);
        float wx = ix - x0f, wy = iy - y0f;
        int x0 = (int)x0f, y0 = (int)y0f;
        int x1 = min(x0 + 1, WW - 1);
        int y1 = min(y0 + 1, HH - 1);

        const float* base = x + ((size_t)b * C_IN + c) * (size_t)(HH * WW);
        float v00 = base[(size_t)y0 * WW + x0];
        float v01 = base[(size_t)y0 * WW + x1];
        float v10 = base[(size_t)y1 * WW + x0];
        float v11 = base[(size_t)y1 * WW + x1];

        float top = v00 + (v01 - v00) * wx;
        float bot = v10 + (v11 - v10) * wx;
        g_feats[(size_t)n * C_IN + c] = __float2half_rn(top + (bot - top) * wy);
    } else {
        if (threadIdx.x < KPTS * 3) skp[threadIdx.x] = kp[threadIdx.x];
        __syncthreads();

        int t = (bid - N) * 256 + threadIdx.x;
        int n = t / NNB;
        int a = t % NNB;
        if (n >= N) return;
        int b = batch_of(n, Bn);
        int j = pknn[(size_t)n * NNB + a] + g_cum[b];

        float cx = pxyz[(size_t)n * 3 + 0];
        float cy = pxyz[(size_t)n * 3 + 1];
        float cz = pxyz[(size_t)n * 3 + 2];
        float rx = pxyz[(size_t)j * 3 + 0] - cx;
        float ry = pxyz[(size_t)j * 3 + 1] - cy;
        float rz = pxyz[(size_t)j * 3 + 2] - cz;

#pragma unroll
        for (int k = 0; k < KPTS; k++) {
            float dx = rx - skp[k * 3 + 0];
            float dy = ry - skp[k * 3 + 1];
            float dz = rz - skp[k * 3 + 2];
            float dist = sqrtf(dx * dx + dy * dy + dz * dz);
            g_allw[((size_t)n * NNB + a) * KPTS + k] = fmaxf(1.0f - dist * (1.0f / KP_EXT), 0.0f);
        }
    }
}

// ---------------- launch 4 (profiled): weighted -> fp16 ----------------
// accumulator-outer, fp16 feats gathers (half the L1/LDG bytes of R15)
__global__ void __launch_bounds__(128)
weighted_kernel(const int* __restrict__ pknn, int N, int Bn) {
    int n = blockIdx.x;
    int c2 = threadIdx.x;          // 0..127 (channel pair)
    if (n >= N) return;

    __shared__ float sw[NNB * KPTS];
    __shared__ int sidx[NNB];
    if (c2 < NNB) {
        int b = batch_of(n, Bn);
        sidx[c2] = pknn[(size_t)n * NNB + c2] + g_cum[b];
    }
    for (int i = c2; i < NNB * KPTS; i += 128)
        sw[i] = g_allw[(size_t)n * NNB * KPTS + i];
    __syncthreads();

    float accA[KPTS], accB[KPTS];
#pragma unroll
    for (int k = 0; k < KPTS; k++) { accA[k] = 0.0f; accB[k] = 0.0f; }

    const __half2* F2 = (const __half2*)g_feats;
#pragma unroll
    for (int g = 0; g < 4; g++) {
        __half2 nh[4];
#pragma unroll
        for (int a4 = 0; a4 < 4; a4++)
            nh[a4] = F2[((size_t)sidx[g * 4 + a4] * C_IN >> 1) + c2];
#pragma unroll
        for (int a4 = 0; a4 < 4; a4++) {
            int a = g * 4 + a4;
            float2 v = __half22float2(nh[a4]);
#pragma unroll
            for (int k = 0; k < KPTS; k++) {
                float w = sw[a * KPTS + k];
                accA[k] = fmaf(w, v.x, accA[k]);
                accB[k] = fmaf(w, v.y, accB[k]);
            }
        }
    }

    __half2* Ah2 = (__half2*)g_Ah;
    size_t rowbase = ((size_t)n * KD) >> 1;
#pragma unroll
    for (int k = 0; k < KPTS; k++) {
        Ah2[rowbase + (size_t)k * 128 + c2] =
            __halves2half2(__float2half_rn(accA[k]), __float2half_rn(accB[k]));
    }
}

// ---------------- launch 5: HMMA fp16 single-pass GEMM, 2 CTAs/SM ----------------
// C[m, d] = sum_kc A[m,kc] * B[d,kc]   (A, B both fp16; fp32 accumulate)
// CTA: 128(M) x 64(N), 256 threads = 8 warps = 4(M) x 2(N), warp tile 32 x 32
#define GM 128
#define GN 64
#define KCHUNK 64
#define NCHUNKS (KD / KCHUNK)           // 60
#define OFF_AH 0                        // 128 rows x 128B = 16 KB
#define OFF_BH 16384                    // 64 rows x 128B = 8 KB
#define STAGE_BYTES 24576               // 24 KB
#define NSTAGE 2
#define GEMM_SMEM (NSTAGE * STAGE_BYTES + 1024)
#define GEMM_THREADS 256

extern __shared__ char gemm_smem[];

__global__ void __launch_bounds__(GEMM_THREADS, 2) gemm_mma_kernel(float* __restrict__ C, int M) {
    int tid = threadIdx.x;
    int wid = tid >> 5;
    int lane = tid & 31;
    int wm = wid & 3;          // 0..3  (32 rows each)
    int wn = wid >> 2;         // 0..1  (32 cols each)
    int mBase = blockIdx.y * GM;
    int nBase = blockIdx.x * GN;

    uint32_t dyn_u32 = smem_u32(gemm_smem);
    uint32_t base_u32 = (dyn_u32 + 1023u) & ~1023u;

    float acc[2][4][4];
#pragma unroll
    for (int a = 0; a < 2; a++)
#pragma unroll
        for (int b = 0; b < 4; b++)
#pragma unroll
            for (int c = 0; c < 4; c++) acc[a][b][c] = 0.0f;

    // ---- hoisted per-thread copy addresses ----
    int r_lo = tid >> 3;        // 0..31
    int gi   = tid & 7;         // 16B granule within 128B row
    const __half* srcA[4];
    const __half* srcB[2];
    uint32_t dstA[4], dstB[2];
#pragma unroll
    for (int p = 0; p < 4; p++) {
        int row = p * 32 + r_lo;
        uint32_t off = (uint32_t)(row * 128 + gi * 16);
        dstA[p] = OFF_AH + (off ^ ((off >> 3) & 0x70));
        int gr = min(mBase + row, M - 1);
        srcA[p] = g_Ah + (size_t)gr * KD + gi * 8;
    }
#pragma unroll
    for (int p = 0; p < 2; p++) {
        int row = p * 32 + r_lo;
        uint32_t off = (uint32_t)(row * 128 + gi * 16);
        dstB[p] = OFF_BH + (off ^ ((off >> 3) & 0x70));
        srcB[p] = g_Bh + (size_t)(nBase + row) * KD + gi * 8;
    }

    // ---- hoisted ldsm address components ----
    int lrow = lane & 15;
    int csel = (lane >> 4) * 16;
    int aRow = wm * 32 + lrow;
    int bRow = wn * 32 + lrow;
    uint32_t xa = (uint32_t)((aRow & 7) << 4);
    uint32_t xb = (uint32_t)((bRow & 7) << 4);

    // prologue: chunk 0 -> buf 0
#pragma unroll
    for (int p = 0; p < 4; p++) CP_ASYNC16(base_u32 + dstA[p], srcA[p]);
#pragma unroll
    for (int p = 0; p < 2; p++) CP_ASYNC16(base_u32 + dstB[p], srcB[p]);
    CP_COMMIT();

    for (int ch = 0; ch < NCHUNKS; ch++) {
        int buf = ch & 1;
        uint32_t stg = base_u32 + buf * STAGE_BYTES;

        if (ch + 1 < NCHUNKS) {
            uint32_t nstg = base_u32 + (buf ^ 1) * STAGE_BYTES;
            int k1 = (ch + 1) * KCHUNK;
#pragma unroll
            for (int p = 0; p < 4; p++) CP_ASYNC16(nstg + dstA[p], srcA[p] + k1);
#pragma unroll
            for (int p = 0; p < 2; p++) CP_ASYNC16(nstg + dstB[p], srcB[p] + k1);
            CP_COMMIT();
            CP_WAIT1();       // chunk ch complete; ch+1 may be in flight
        } else {
            CP_WAIT0();
        }
        __syncthreads();

        uint32_t aBase = stg + (uint32_t)(aRow * 128);
        uint32_t bBase = stg + (uint32_t)(bRow * 128);

#pragma unroll
        for (int ks = 0; ks < 4; ks++) {
            uint32_t colA = ((uint32_t)(ks * 32 + csel)) ^ xa;
            uint32_t colB = ((uint32_t)(ks * 32 + csel)) ^ xb;

            uint32_t bh[2][4];
#pragma unroll
            for (int g = 0; g < 2; g++) {
                uint32_t addr = bBase + (uint32_t)(g * 16 * 128) + colB;
                ldsm4(bh[g], addr + OFF_BH);
            }
#pragma unroll
            for (int mt = 0; mt < 2; mt++) {
                uint32_t addr = aBase + (uint32_t)(mt * 16 * 128) + colA;
                uint32_t ah[4];
                ldsm4(ah, addr + OFF_AH);
#pragma unroll
                for (int nt = 0; nt < 4; nt++) {
                    int g = nt >> 1, h = nt & 1;
                    mma16816(acc[mt][nt], ah, bh[g][h], bh[g][h + 2]);
                }
            }
        }
        __syncthreads();   // buffer free before next overwrite
    }

    // ---- store C tile (m16n8 accumulator mapping) ----
    int rBase = mBase + wm * 32 + (lane >> 2);
    int cBase = nBase + wn * 32 + (lane & 3) * 2;
#pragma unroll
    for (int mt = 0; mt < 2; mt++) {
#pragma unroll
        for (int nt = 0; nt < 4; nt++) {
            int r0 = rBase + mt * 16;
            int cc = cBase + nt * 8;
            if (r0 < M)
                *(float2*)(C + (size_t)r0 * C_OUT + cc) =
                    make_float2(acc[mt][nt][0], acc[mt][nt][1]);
            if (r0 + 8 < M)
                *(float2*)(C + (size_t)(r0 + 8) * C_OUT + cc) =
                    make_float2(acc[mt][nt][2], acc[mt][nt][3]);
        }
    }

    // ---- fused BN partial stats: per-CTA column sum / sumsq over valid rows ----
    __syncthreads();                       // pipeline smem no longer needed
    float* sred = (float*)gemm_smem;       // [4 wm][64 cols] sums, then sqs (512 floats)

#pragma unroll
    for (int nt = 0; nt < 4; nt++) {
        float s0 = 0.f, s1 = 0.f, q0 = 0.f, q1 = 0.f;
#pragma unroll
        for (int mt = 0; mt < 2; mt++) {
            int ra = rBase + mt * 16;
            int rb = ra + 8;
            if (ra < M) {
                float v0 = acc[mt][nt][0], v1 = acc[mt][nt][1];
                s0 += v0; s1 += v1; q0 += v0 * v0; q1 += v1 * v1;
            }
            if (rb < M) {
                float v2 = acc[mt][nt][2], v3 = acc[mt][nt][3];
                s0 += v2; s1 += v3; q0 += v2 * v2; q1 += v3 * v3;
            }
        }
#pragma unroll
        for (int off = 16; off >= 4; off >>= 1) {
            s0 += __shfl_down_sync(0xffffffffu, s0, off);
            s1 += __shfl_down_sync(0xffffffffu, s1, off);
            q0 += __shfl_down_sync(0xffffffffu, q0, off);
            q1 += __shfl_down_sync(0xffffffffu, q1, off);
        }
        if (lane < 4) {
            int colL = wn * 32 + nt * 8 + lane * 2;   // 0..63
            sred[wm * 64 + colL]       = s0;
            sred[wm * 64 + colL + 1]   = s1;
            sred[256 + wm * 64 + colL]     = q0;
            sred[256 + wm * 64 + colL + 1] = q1;
        }
    }
    __syncthreads();

    if (tid < 64) {
        float s = sred[tid] + sred[64 + tid] + sred[128 + tid] + sred[192 + tid];
        g_psum[(size_t)blockIdx.y * C_OUT + blockIdx.x * GN + tid] = s;
    } else if (tid < 128) {
        int t = tid - 64;
        float s = sred[256 + t] + sred[320 + t] + sred[384 + t] + sred[448 + t];
        g_psq[(size_t)blockIdx.y * C_OUT + blockIdx.x * GN + t] = s;
    }
}

// ---------------- launch 6: finalize BN stats ----------------
__global__ void colstats_final(const float* __restrict__ gamma,
                               const float* __restrict__ beta,
                               int N, int nMtiles) {
    int d = threadIdx.x;
    float s = 0.f, ss = 0.f;
    for (int i = 0; i < nMtiles; i++) {
        s += g_psum[(size_t)i * C_OUT + d];
        ss += g_psq[(size_t)i * C_OUT + d];
    }
    float invN = 1.0f / (float)N;
    float mean = s * invN;
    float var = ss * invN - mean * mean;
    float sc = rsqrtf(var + BN_EPS) * gamma[d];
    g_scale[d] = sc;
    g_bias[d] = beta[d] - mean * sc;
}

// ---------------- launch 7: BN + ReLU (float4) ----------------
__global__ void bn_relu_kernel(float* __restrict__ out, size_t total4) {
    float4* o4 = (float4*)out;
    for (size_t i = (size_t)blockIdx.x * blockDim.x + threadIdx.x; i < total4;
         i += (size_t)gridDim.x * blockDim.x) {
        int d = (int)((i * 4) & (C_OUT - 1));
        float4 v = o4[i];
        v.x = fmaf(v.x, g_scale[d + 0], g_bias[d + 0]);
        v.y = fmaf(v.y, g_scale[d + 1], g_bias[d + 1]);
        v.z = fmaf(v.z, g_scale[d + 2], g_bias[d + 2]);
        v.w = fmaf(v.w, g_scale[d + 3], g_bias[d + 3]);
        v.x = v.x > 0.f ? v.x : 0.f;
        v.y = v.y > 0.f ? v.y : 0.f;
        v.z = v.z > 0.f ? v.z : 0.f;
        v.w = v.w > 0.f ? v.w : 0.f;
        o4[i] = v;
    }
}

// ---------------- launch ----------------
extern "C" void kernel_launch(void* const* d_in, const int* in_sizes, int n_in,
                              void* d_out, int out_size) {
    const float* x     = (const float*)d_in[0];
    const float* px    = (const float*)d_in[1];
    const float* py    = (const float*)d_in[2];
    const float* pxyz  = (const float*)d_in[3];
    const int*   pknn  = (const int*)d_in[4];
    const int*   np    = (const int*)d_in[5];
    const float* kp    = (const float*)d_in[6];
    const float* kpw   = (const float*)d_in[7];
    const float* gamma = (const float*)d_in[8];
    const float* beta  = (const float*)d_in[9];
    float* out = (float*)d_out;

    int N  = in_sizes[1];
    int Bn = in_sizes[5];

    cudaFuncSetAttribute(gemm_mma_kernel,
                         cudaFuncAttributeMaxDynamicSharedMemorySize, GEMM_SMEM);

    // launch 1: prefix sums
    prep_cum_kernel<<<1, 32>>>(np, Bn);

    // launch 2: B fp16 transpose
    prep_b_kernel<<<(KD * C_OUT + 255) / 256, 256>>>(kpw);

    // launch 3: fused feats + allw
    int allw_blocks = (N * NNB + 255) / 256;
    feats_allw_kernel<<<N + allw_blocks, 256>>>(x, px, py, pxyz, pknn, kp, N, Bn);

    // launch 4: weighted (profiled slot — A/B on fp16 feats gathers)
    weighted_kernel<<<N, 128>>>(pknn, N, Bn);

    // launch 5: GEMM + fused BN partial stats
    int nMtiles = (N + GM - 1) / GM;
    dim3 ggrid(C_OUT / GN, nMtiles);
    gemm_mma_kernel<<<ggrid, GEMM_THREADS, GEMM_SMEM>>>(out, N);

    // launch 6: finalize stats
    colstats_final<<<1, C_OUT>>>(gamma, beta, N, nMtiles);

    // launch 7: BN + ReLU
    size_t total4 = ((size_t)N * C_OUT) / 4;
    bn_relu_kernel<<<1024, 256>>>(out, total4);
}

// round 17
// speedup vs baseline: 2.3594x; 1.0128x over previous
#include <cuda_runtime.h>
#include <cuda_fp16.h>
#include <cstdint>
#include <cstddef>

// Problem constants
#define C_IN   256
#define C_OUT  256
#define KPTS   15
#define NNB    16
#define HH     64
#define WW     2048
#define KP_EXT 1.2f
#define BN_EPS 1e-5f
#define MAXB   8
#define MAXN   40000
#define KD     (KPTS * C_IN)        // 3840
#define MAXMT  320                  // max M-tiles (40000/128 = 313)

// ---------------- scratch (device globals) ----------------
__device__ int   g_cum[MAXB + 1];
__device__ float g_feats[(size_t)MAXN * C_IN];   // fp32 feats (41 MB)
__device__ float g_allw[(size_t)MAXN * NNB * KPTS];
__device__ __half g_Ah[(size_t)MAXN * KD];      // 307 MB (fp16 A)
__device__ __half g_Bh[(size_t)C_OUT * KD];     // 1.9 MB, K-major [d][kc], fp16
__device__ float g_psum[MAXMT * C_OUT];
__device__ float g_psq[MAXMT * C_OUT];
__device__ float g_scale[C_OUT];
__device__ float g_bias[C_OUT];

// ---------------- PTX helpers (base sm_103-legal only) ----------------
__device__ __forceinline__ uint32_t smem_u32(const void* p) {
    uint32_t a;
    asm("{ .reg .u64 t; cvta.to.shared.u64 t, %1; cvt.u32.u64 %0, t; }" : "=r"(a) : "l"(p));
    return a;
}

#define CP_ASYNC16(dst_u32, src_ptr) \
    asm volatile("cp.async.cg.shared.global [%0], [%1], 16;" \
                 :: "r"(dst_u32), "l"(src_ptr) : "memory")
#define CP_COMMIT() asm volatile("cp.async.commit_group;" ::: "memory")
#define CP_WAIT1()  asm volatile("cp.async.wait_group 1;" ::: "memory")
#define CP_WAIT0()  asm volatile("cp.async.wait_group 0;" ::: "memory")

__device__ __forceinline__ void ldsm4(uint32_t* r, uint32_t addr) {
    asm volatile("ldmatrix.sync.aligned.m8n8.x4.shared.b16 {%0,%1,%2,%3}, [%4];"
                 : "=r"(r[0]), "=r"(r[1]), "=r"(r[2]), "=r"(r[3]) : "r"(addr));
}

__device__ __forceinline__ void mma16816(float* c, const uint32_t* a,
                                         uint32_t b0, uint32_t b1) {
    asm volatile(
        "mma.sync.aligned.m16n8k16.row.col.f32.f16.f16.f32 "
        "{%0,%1,%2,%3}, {%4,%5,%6,%7}, {%8,%9}, {%0,%1,%2,%3};"
        : "+f"(c[0]), "+f"(c[1]), "+f"(c[2]), "+f"(c[3])
        : "r"(a[0]), "r"(a[1]), "r"(a[2]), "r"(a[3]), "r"(b0), "r"(b1));
}

__device__ __forceinline__ int batch_of(int n, int Bn) {
    int b = 0;
#pragma unroll
    for (int i = 1; i < MAXB; i++)
        if (i < Bn && n >= g_cum[i]) b = i;
    return b;
}

// ---------------- launch 1: prefix sums ----------------
__global__ void prep_cum_kernel(const int* __restrict__ np, int Bn) {
    if (blockIdx.x == 0 && threadIdx.x == 0) {
        int c = 0;
        for (int b = 0; b < Bn && b < MAXB; b++) { g_cum[b] = c; c += np[b]; }
        for (int b = Bn; b < MAXB; b++) g_cum[b] = c;
        g_cum[MAXB] = c;
    }
}

// ---------------- launch 2: B fp16 transpose ----------------
__global__ void prep_b_kernel(const float* __restrict__ kpw) {
    int i = blockIdx.x * blockDim.x + threadIdx.x;
    if (i >= KD * C_OUT) return;
    int kc = i >> 8;
    int d  = i & 255;
    g_Bh[(size_t)d * KD + kc] = __float2half_rn(kpw[i]);
}

// ---------------- launch 3: fused grid sample + kernel-point weights ----------------
__global__ void feats_allw_kernel(const float* __restrict__ x,
                                  const float* __restrict__ px,
                                  const float* __restrict__ py,
                                  const float* __restrict__ pxyz,
                                  const int* __restrict__ pknn,
                                  const float* __restrict__ kp,
                                  int N, int Bn) {
    __shared__ float skp[KPTS * 3];
    int bid = blockIdx.x;
    if (bid < N) {
        int n = bid;
        int c = threadIdx.x;
        int b = batch_of(n, Bn);

        float ix = fminf(fmaxf((px[n] + 1.0f) * (WW * 0.5f) - 0.5f, 0.0f), (float)(WW - 1));
        float iy = fminf(fmaxf((py[n] + 1.0f) * (HH * 0.5f) - 0.5f, 0.0f), (float)(HH - 1));
        float x0f = floorf(ix), y0f = floorf(iy);
        float wx = ix - x0f, wy = iy - y0f;
        int x0 = (int)x0f, y0 = (int)y0f;
        int x1 = min(x0 + 1, WW - 1);
        int y1 = min(y0 + 1, HH - 1);

        const float* base = x + ((size_t)b * C_IN + c) * (size_t)(HH * WW);
        float v00 = base[(size_t)y0 * WW + x0];
        float v01 = base[(size_t)y0 * WW + x1];
        float v10 = base[(size_t)y1 * WW + x0];
        float v11 = base[(size_t)y1 * WW + x1];

        float top = v00 + (v01 - v00) * wx;
        float bot = v10 + (v11 - v10) * wx;
        g_feats[(size_t)n * C_IN + c] = top + (bot - top) * wy;
    } else {
        if (threadIdx.x < KPTS * 3) skp[threadIdx.x] = kp[threadIdx.x];
        __syncthreads();

        int t = (bid - N) * 256 + threadIdx.x;
        int n = t / NNB;
        int a = t % NNB;
        if (n >= N) return;
        int b = batch_of(n, Bn);
        int j = pknn[(size_t)n * NNB + a] + g_cum[b];

        float cx = pxyz[(size_t)n * 3 + 0];
        float cy = pxyz[(size_t)n * 3 + 1];
        float cz = pxyz[(size_t)n * 3 + 2];
        float rx = pxyz[(size_t)j * 3 + 0] - cx;
        float ry = pxyz[(size_t)j * 3 + 1] - cy;
        float rz = pxyz[(size_t)j * 3 + 2] - cz;

#pragma unroll
        for (int k = 0; k < KPTS; k++) {
            float dx = rx - skp[k * 3 + 0];
            float dy = ry - skp[k * 3 + 1];
            float dz = rz - skp[k * 3 + 2];
            float dist = sqrtf(dx * dx + dy * dy + dz * dz);
            g_allw[((size_t)n * NNB + a) * KPTS + k] = fmaxf(1.0f - dist * (1.0f / KP_EXT), 0.0f);
        }
    }
}

// ---------------- launch 4 (profiled): weighted -> fp16 ----------------
// accumulator-outer; weight tile padded to 16 floats/row so the per-neighbor
// weight reads are 4x LDS.128 instead of 15x LDS.32 (kernel is issue-bound).
__global__ void __launch_bounds__(128)
weighted_kernel(const int* __restrict__ pknn, int N, int Bn) {
    int n = blockIdx.x;
    int c2 = threadIdx.x;          // 0..127 (channel pair)
    if (n >= N) return;

    __shared__ __align__(16) float sw[NNB * 16];   // padded rows (k=15 -> 0)
    __shared__ int sidx[NNB];
    if (c2 < NNB) {
        int b = batch_of(n, Bn);
        sidx[c2] = pknn[(size_t)n * NNB + c2] + g_cum[b];
    }
#pragma unroll
    for (int i = c2; i < NNB * 16; i += 128) {
        int a = i >> 4, k = i & 15;
        sw[i] = (k < KPTS) ? g_allw[(size_t)n * NNB * KPTS + a * KPTS + k] : 0.0f;
    }
    __syncthreads();

    float accA[16], accB[16];
#pragma unroll
    for (int k = 0; k < 16; k++) { accA[k] = 0.0f; accB[k] = 0.0f; }

#pragma unroll
    for (int g = 0; g < 4; g++) {
        float2 nx[4];
#pragma unroll
        for (int a4 = 0; a4 < 4; a4++)
            nx[a4] = *(const float2*)(g_feats + (size_t)sidx[g * 4 + a4] * C_IN + 2 * c2);
#pragma unroll
        for (int a4 = 0; a4 < 4; a4++) {
            int a = g * 4 + a4;
            float vx = nx[a4].x, vy = nx[a4].y;
            const float4* w4p = (const float4*)&sw[a * 16];
#pragma unroll
            for (int q = 0; q < 4; q++) {
                float4 w = w4p[q];
                accA[q * 4 + 0] = fmaf(w.x, vx, accA[q * 4 + 0]);
                accB[q * 4 + 0] = fmaf(w.x, vy, accB[q * 4 + 0]);
                accA[q * 4 + 1] = fmaf(w.y, vx, accA[q * 4 + 1]);
                accB[q * 4 + 1] = fmaf(w.y, vy, accB[q * 4 + 1]);
                accA[q * 4 + 2] = fmaf(w.z, vx, accA[q * 4 + 2]);
                accB[q * 4 + 2] = fmaf(w.z, vy, accB[q * 4 + 2]);
                accA[q * 4 + 3] = fmaf(w.w, vx, accA[q * 4 + 3]);
                accB[q * 4 + 3] = fmaf(w.w, vy, accB[q * 4 + 3]);
            }
        }
    }

    __half2* Ah2 = (__half2*)g_Ah;
    size_t rowbase = ((size_t)n * KD) >> 1;
#pragma unroll
    for (int k = 0; k < KPTS; k++) {
        Ah2[rowbase + (size_t)k * 128 + c2] =
            __halves2half2(__float2half_rn(accA[k]), __float2half_rn(accB[k]));
    }
}

// ---------------- launch 5: HMMA fp16 single-pass GEMM, 2 CTAs/SM ----------------
// C[m, d] = sum_kc A[m,kc] * B[d,kc]   (A, B both fp16; fp32 accumulate)
// CTA: 128(M) x 64(N), 256 threads = 8 warps = 4(M) x 2(N), warp tile 32 x 32
#define GM 128
#define GN 64
#define KCHUNK 64
#define NCHUNKS (KD / KCHUNK)           // 60
#define OFF_AH 0                        // 128 rows x 128B = 16 KB
#define OFF_BH 16384                    // 64 rows x 128B = 8 KB
#define STAGE_BYTES 24576               // 24 KB
#define NSTAGE 2
#define GEMM_SMEM (NSTAGE * STAGE_BYTES + 1024)
#define GEMM_THREADS 256

extern __shared__ char gemm_smem[];

__global__ void __launch_bounds__(GEMM_THREADS, 2) gemm_mma_kernel(float* __restrict__ C, int M) {
    int tid = threadIdx.x;
    int wid = tid >> 5;
    int lane = tid & 31;
    int wm = wid & 3;          // 0..3  (32 rows each)
    int wn = wid >> 2;         // 0..1  (32 cols each)
    int mBase = blockIdx.y * GM;
    int nBase = blockIdx.x * GN;

    uint32_t dyn_u32 = smem_u32(gemm_smem);
    uint32_t base_u32 = (dyn_u32 + 1023u) & ~1023u;

    float acc[2][4][4];
#pragma unroll
    for (int a = 0; a < 2; a++)
#pragma unroll
        for (int b = 0; b < 4; b++)
#pragma unroll
            for (int c = 0; c < 4; c++) acc[a][b][c] = 0.0f;

    // ---- hoisted per-thread copy addresses ----
    int r_lo = tid >> 3;        // 0..31
    int gi   = tid & 7;         // 16B granule within 128B row
    const __half* srcA[4];
    const __half* srcB[2];
    uint32_t dstA[4], dstB[2];
#pragma unroll
    for (int p = 0; p < 4; p++) {
        int row = p * 32 + r_lo;
        uint32_t off = (uint32_t)(row * 128 + gi * 16);
        dstA[p] = OFF_AH + (off ^ ((off >> 3) & 0x70));
        int gr = min(mBase + row, M - 1);
        srcA[p] = g_Ah + (size_t)gr * KD + gi * 8;
    }
#pragma unroll
    for (int p = 0; p < 2; p++) {
        int row = p * 32 + r_lo;
        uint32_t off = (uint32_t)(row * 128 + gi * 16);
        dstB[p] = OFF_BH + (off ^ ((off >> 3) & 0x70));
        srcB[p] = g_Bh + (size_t)(nBase + row) * KD + gi * 8;
    }

    // ---- hoisted ldsm address components ----
    int lrow = lane & 15;
    int csel = (lane >> 4) * 16;
    int aRow = wm * 32 + lrow;
    int bRow = wn * 32 + lrow;
    uint32_t xa = (uint32_t)((aRow & 7) << 4);
    uint32_t xb = (uint32_t)((bRow & 7) << 4);

    // prologue: chunk 0 -> buf 0
#pragma unroll
    for (int p = 0; p < 4; p++) CP_ASYNC16(base_u32 + dstA[p], srcA[p]);
#pragma unroll
    for (int p = 0; p < 2; p++) CP_ASYNC16(base_u32 + dstB[p], srcB[p]);
    CP_COMMIT();

    for (int ch = 0; ch < NCHUNKS; ch++) {
        int buf = ch & 1;
        uint32_t stg = base_u32 + buf * STAGE_BYTES;

        if (ch + 1 < NCHUNKS) {
            uint32_t nstg = base_u32 + (buf ^ 1) * STAGE_BYTES;
            int k1 = (ch + 1) * KCHUNK;
#pragma unroll
            for (int p = 0; p < 4; p++) CP_ASYNC16(nstg + dstA[p], srcA[p] + k1);
#pragma unroll
            for (int p = 0; p < 2; p++) CP_ASYNC16(nstg + dstB[p], srcB[p] + k1);
            CP_COMMIT();
            CP_WAIT1();       // chunk ch complete; ch+1 may be in flight
        } else {
            CP_WAIT0();
        }
        __syncthreads();

        uint32_t aBase = stg + (uint32_t)(aRow * 128);
        uint32_t bBase = stg + (uint32_t)(bRow * 128);

#pragma unroll
        for (int ks = 0; ks < 4; ks++) {
            uint32_t colA = ((uint32_t)(ks * 32 + csel)) ^ xa;
            uint32_t colB = ((uint32_t)(ks * 32 + csel)) ^ xb;

            uint32_t bh[2][4];
#pragma unroll
            for (int g = 0; g < 2; g++) {
                uint32_t addr = bBase + (uint32_t)(g * 16 * 128) + colB;
                ldsm4(bh[g], addr + OFF_BH);
            }
#pragma unroll
            for (int mt = 0; mt < 2; mt++) {
                uint32_t addr = aBase + (uint32_t)(mt * 16 * 128) + colA;
                uint32_t ah[4];
                ldsm4(ah, addr + OFF_AH);
#pragma unroll
                for (int nt = 0; nt < 4; nt++) {
                    int g = nt >> 1, h = nt & 1;
                    mma16816(acc[mt][nt], ah, bh[g][h], bh[g][h + 2]);
                }
            }
        }
        __syncthreads();   // buffer free before next overwrite
    }

    // ---- store C tile (m16n8 accumulator mapping) ----
    int rBase = mBase + wm * 32 + (lane >> 2);
    int cBase = nBase + wn * 32 + (lane & 3) * 2;
#pragma unroll
    for (int mt = 0; mt < 2; mt++) {
#pragma unroll
        for (int nt = 0; nt < 4; nt++) {
            int r0 = rBase + mt * 16;
            int cc = cBase + nt * 8;
            if (r0 < M)
                *(float2*)(C + (size_t)r0 * C_OUT + cc) =
                    make_float2(acc[mt][nt][0], acc[mt][nt][1]);
            if (r0 + 8 < M)
                *(float2*)(C + (size_t)(r0 + 8) * C_OUT + cc) =
                    make_float2(acc[mt][nt][2], acc[mt][nt][3]);
        }
    }

    // ---- fused BN partial stats: per-CTA column sum / sumsq over valid rows ----
    __syncthreads();                       // pipeline smem no longer needed
    float* sred = (float*)gemm_smem;       // [4 wm][64 cols] sums, then sqs (512 floats)

#pragma unroll
    for (int nt = 0; nt < 4; nt++) {
        float s0 = 0.f, s1 = 0.f, q0 = 0.f, q1 = 0.f;
#pragma unroll
        for (int mt = 0; mt < 2; mt++) {
            int ra = rBase + mt * 16;
            int rb = ra + 8;
            if (ra < M) {
                float v0 = acc[mt][nt][0], v1 = acc[mt][nt][1];
                s0 += v0; s1 += v1; q0 += v0 * v0; q1 += v1 * v1;
            }
            if (rb < M) {
                float v2 = acc[mt][nt][2], v3 = acc[mt][nt][3];
                s0 += v2; s1 += v3; q0 += v2 * v2; q1 += v3 * v3;
            }
        }
#pragma unroll
        for (int off = 16; off >= 4; off >>= 1) {
            s0 += __shfl_down_sync(0xffffffffu, s0, off);
            s1 += __shfl_down_sync(0xffffffffu, s1, off);
            q0 += __shfl_down_sync(0xffffffffu, q0, off);
            q1 += __shfl_down_sync(0xffffffffu, q1, off);
        }
        if (lane < 4) {
            int colL = wn * 32 + nt * 8 + lane * 2;   // 0..63
            sred[wm * 64 + colL]       = s0;
            sred[wm * 64 + colL + 1]   = s1;
            sred[256 + wm * 64 + colL]     = q0;
            sred[256 + wm * 64 + colL + 1] = q1;
        }
    }
    __syncthreads();

    if (tid < 64) {
        float s = sred[tid] + sred[64 + tid] + sred[128 + tid] + sred[192 + tid];
        g_psum[(size_t)blockIdx.y * C_OUT + blockIdx.x * GN + tid] = s;
    } else if (tid < 128) {
        int t = tid - 64;
        float s = sred[256 + t] + sred[320 + t] + sred[384 + t] + sred[448 + t];
        g_psq[(size_t)blockIdx.y * C_OUT + blockIdx.x * GN + t] = s;
    }
}

// ---------------- launch 6: finalize BN stats ----------------
__global__ void colstats_final(const float* __restrict__ gamma,
                               const float* __restrict__ beta,
                               int N, int nMtiles) {
    int d = threadIdx.x;
    float s = 0.f, ss = 0.f;
    for (int i = 0; i < nMtiles; i++) {
        s += g_psum[(size_t)i * C_OUT + d];
        ss += g_psq[(size_t)i * C_OUT + d];
    }
    float invN = 1.0f / (float)N;
    float mean = s * invN;
    float var = ss * invN - mean * mean;
    float sc = rsqrtf(var + BN_EPS) * gamma[d];
    g_scale[d] = sc;
    g_bias[d] = beta[d] - mean * sc;
}

// ---------------- launch 7: BN + ReLU (float4) ----------------
__global__ void bn_relu_kernel(float* __restrict__ out, size_t total4) {
    float4* o4 = (float4*)out;
    for (size_t i = (size_t)blockIdx.x * blockDim.x + threadIdx.x; i < total4;
         i += (size_t)gridDim.x * blockDim.x) {
        int d = (int)((i * 4) & (C_OUT - 1));
        float4 v = o4[i];
        v.x = fmaf(v.x, g_scale[d + 0], g_bias[d + 0]);
        v.y = fmaf(v.y, g_scale[d + 1], g_bias[d + 1]);
        v.z = fmaf(v.z, g_scale[d + 2], g_bias[d + 2]);
        v.w = fmaf(v.w, g_scale[d + 3], g_bias[d + 3]);
        v.x = v.x > 0.f ? v.x : 0.f;
        v.y = v.y > 0.f ? v.y : 0.f;
        v.z = v.z > 0.f ? v.z : 0.f;
        v.w = v.w > 0.f ? v.w : 0.f;
        o4[i] = v;
    }
}

// ---------------- launch ----------------
extern "C" void kernel_launch(void* const* d_in, const int* in_sizes, int n_in,
                              void* d_out, int out_size) {
    const float* x     = (const float*)d_in[0];
    const float* px    = (const float*)d_in[1];
    const float* py    = (const float*)d_in[2];
    const float* pxyz  = (const float*)d_in[3];
    const int*   pknn  = (const int*)d_in[4];
    const int*   np    = (const int*)d_in[5];
    const float* kp    = (const float*)d_in[6];
    const float* kpw   = (const float*)d_in[7];
    const float* gamma = (const float*)d_in[8];
    const float* beta  = (const float*)d_in[9];
    float* out = (float*)d_out;

    int N  = in_sizes[1];
    int Bn = in_sizes[5];

    cudaFuncSetAttribute(gemm_mma_kernel,
                         cudaFuncAttributeMaxDynamicSharedMemorySize, GEMM_SMEM);

    // launch 1: prefix sums
    prep_cum_kernel<<<1, 32>>>(np, Bn);

    // launch 2: B fp16 transpose
    prep_b_kernel<<<(KD * C_OUT + 255) / 256, 256>>>(kpw);

    // launch 3: fused feats + allw
    int allw_blocks = (N * NNB + 255) / 256;
    feats_allw_kernel<<<N + allw_blocks, 256>>>(x, px, py, pxyz, pknn, kp, N, Bn);

    // launch 4: weighted (profiled slot — A/B on float4 weight loads)
    weighted_kernel<<<N, 128>>>(pknn, N, Bn);

    // launch 5: GEMM + fused BN partial stats
    int nMtiles = (N + GM - 1) / GM;
    dim3 ggrid(C_OUT / GN, nMtiles);
    gemm_mma_kernel<<<ggrid, GEMM_THREADS, GEMM_SMEM>>>(out, N);

    // launch 6: finalize stats
    colstats_final<<<1, C_OUT>>>(gamma, beta, N, nMtiles);

    // launch 7: BN + ReLU
    size_t total4 = ((size_t)N * C_OUT) / 4;
    bn_relu_kernel<<<1024, 256>>>(out, total4);
}